// round 9
// baseline (speedup 1.0000x reference)
#include <cuda_runtime.h>
#include <cuda_bf16.h>
#include <math.h>
#include <stdint.h>

// ---------------- problem constants ----------------
namespace {
constexpr int B_  = 8;
constexpr int P_  = 16;
constexpr int HOR = 10;
constexpr int NO_ = 128;
constexpr int NR_ = 8;
constexpr int D_  = 768;
constexpr int NH_ = 12;
constexpr int HD_ = 64;
constexpr int F_  = 3072;
constexpr int L_  = 12;
constexpr int TPS = NO_ + NR_;          // 136
constexpr int T_  = P_ + HOR * TPS;     // 1376
constexpr int M_  = B_ * T_;            // 11008
constexpr float LN_EPS = 1e-6f;
constexpr float ATT_SCALE = 0.125f;     // 1/sqrt(64)

// int8 GEMM tiling: 256 threads, 2x4 warp grid (64x32 warp tile), BK=64 int8, 2-stage cp.async
constexpr int BM = 128;
constexpr int BN = 128;
constexpr int BK = 64;                   // int8 elements -> 64B rows (same bytes as bf16 BK=32)
constexpr int RSB = 80;                  // SMEM row stride bytes, conflict-free ldmatrix
constexpr int TILE_B = 128 * RSB;        // 10240 bytes per operand tile
constexpr int STAGE_B = 4 * TILE_B;      // Aq1,Aq2,Bq1,Bq2 = 40960
constexpr int SMEM_GEMM = 2 * STAGE_B;   // 81920

// attention smem layout (bf16 units unless noted)
constexpr int ARS   = 72;                // 144B row stride, conflict-free
constexpr int AT_QH = 0;
constexpr int AT_QL = 1 * 64 * ARS;
constexpr int AT_KH = 2 * 64 * ARS;
constexpr int AT_KL = 3 * 64 * ARS;
constexpr int AT_VH = 4 * 64 * ARS;
constexpr int AT_VL = 5 * 64 * ARS;
constexpr int AT_CODE_B = 6 * 64 * ARS * 2;
constexpr int ATTN_SMEM = AT_CODE_B + 64 * 4;   // 55552 bytes
}

// ---------------- scratch (device globals: no cudaMalloc allowed) ----------------
__device__ float g_x  [(size_t)M_ * D_];
__device__ float g_att[(size_t)M_ * D_];
__device__ float g_ffn[(size_t)M_ * F_];
// quantized activations
__device__ int8_t g_yq1[(size_t)M_ * D_];
__device__ int8_t g_yq2[(size_t)M_ * D_];
__device__ float  g_ysc[M_];
__device__ int8_t g_aq1[(size_t)M_ * D_];
__device__ int8_t g_aq2[(size_t)M_ * D_];
__device__ float  g_asc[M_];
__device__ int8_t g_fq1[(size_t)M_ * F_];
__device__ int8_t g_fq2[(size_t)M_ * F_];
__device__ float  g_fsc[M_];
// qkv (split bf16, consumed by attention)
__device__ __nv_bfloat16 g_qkv_hi[(size_t)M_ * 3 * D_];
__device__ __nv_bfloat16 g_qkv_lo[(size_t)M_ * 3 * D_];
// quantized transposed weights [N,K] + per-N scales
__device__ int8_t g_wqkv_q1[(size_t)L_ * 3 * D_ * D_];
__device__ int8_t g_wqkv_q2[(size_t)L_ * 3 * D_ * D_];
__device__ float  g_wqkv_sc[(size_t)L_ * 3 * D_];
__device__ int8_t g_wo_q1[(size_t)L_ * D_ * D_];
__device__ int8_t g_wo_q2[(size_t)L_ * D_ * D_];
__device__ float  g_wo_sc[(size_t)L_ * D_];
__device__ int8_t g_w1_q1[(size_t)L_ * F_ * D_];
__device__ int8_t g_w1_q2[(size_t)L_ * F_ * D_];
__device__ float  g_w1_sc[(size_t)L_ * F_];
__device__ int8_t g_w2_q1[(size_t)L_ * D_ * F_];
__device__ int8_t g_w2_q2[(size_t)L_ * D_ * F_];
__device__ float  g_w2_sc[(size_t)L_ * D_];

// ---------------- mma / async helpers ----------------
__device__ __forceinline__ unsigned smem_u32(const void* p) {
    return (unsigned)__cvta_generic_to_shared(p);
}
__device__ __forceinline__ void ldsm_x4(unsigned* r, unsigned addr) {
    asm volatile("ldmatrix.sync.aligned.m8n8.x4.shared.b16 {%0,%1,%2,%3}, [%4];"
                 : "=r"(r[0]), "=r"(r[1]), "=r"(r[2]), "=r"(r[3]) : "r"(addr));
}
__device__ __forceinline__ void ldsm_x4t(unsigned* r, unsigned addr) {
    asm volatile("ldmatrix.sync.aligned.m8n8.x4.trans.shared.b16 {%0,%1,%2,%3}, [%4];"
                 : "=r"(r[0]), "=r"(r[1]), "=r"(r[2]), "=r"(r[3]) : "r"(addr));
}
__device__ __forceinline__ void mma_bf16(float* c, const unsigned* a, const unsigned* b) {
    asm volatile(
        "mma.sync.aligned.m16n8k16.row.col.f32.bf16.bf16.f32 "
        "{%0,%1,%2,%3}, {%4,%5,%6,%7}, {%8,%9}, {%0,%1,%2,%3};"
        : "+f"(c[0]), "+f"(c[1]), "+f"(c[2]), "+f"(c[3])
        : "r"(a[0]), "r"(a[1]), "r"(a[2]), "r"(a[3]), "r"(b[0]), "r"(b[1]));
}
__device__ __forceinline__ void mma_s8(int* c, const unsigned* a, const unsigned* b) {
    asm volatile(
        "mma.sync.aligned.m16n8k32.row.col.s32.s8.s8.s32 "
        "{%0,%1,%2,%3}, {%4,%5,%6,%7}, {%8,%9}, {%0,%1,%2,%3};"
        : "+r"(c[0]), "+r"(c[1]), "+r"(c[2]), "+r"(c[3])
        : "r"(a[0]), "r"(a[1]), "r"(a[2]), "r"(a[3]), "r"(b[0]), "r"(b[1]));
}
__device__ __forceinline__ void cp16(unsigned saddr, const void* g) {
    asm volatile("cp.async.cg.shared.global [%0], [%1], 16;" :: "r"(saddr), "l"(g));
}
__device__ __forceinline__ void cp_commit() {
    asm volatile("cp.async.commit_group;" ::: "memory");
}
template <int N>
__device__ __forceinline__ void cp_wait() {
    asm volatile("cp.async.wait_group %0;" :: "n"(N) : "memory");
}
__device__ __forceinline__ unsigned pack_bf2(__nv_bfloat16 a, __nv_bfloat16 b) {
    __nv_bfloat162 t(a, b);
    return *(unsigned*)&t;
}
__device__ __forceinline__ void split2(float v, __nv_bfloat16& h, __nv_bfloat16& l) {
    h = __float2bfloat16(v);
    l = __float2bfloat16(v - __bfloat162float(h));
}
// two-level int8 quantization: x ~= s*(q1 + q2/128)
__device__ __forceinline__ void quant2(float x, float inv_s, int8_t& q1, int8_t& q2) {
    float t = x * inv_s;
    float r1 = rintf(t);
    r1 = fminf(fmaxf(r1, -127.0f), 127.0f);
    float r2 = rintf((t - r1) * 128.0f);
    q1 = (int8_t)(int)r1;
    q2 = (int8_t)(int)r2;
}

// ---------------- misc helpers ----------------
__device__ __forceinline__ float gelu_tanh(float x) {
    float x3 = x * x * x;
    return 0.5f * x * (1.0f + tanhf(0.7978845608028654f * (x + 0.044715f * x3)));
}
__device__ __forceinline__ int tok_group(int i) {
    if (i < P_) return 0;
    return (((i - P_) % TPS) < NO_) ? 1 : 2;
}
__device__ __forceinline__ int tok_ts(int i) {
    return (i < P_) ? -1 : (i - P_) / TPS;
}
__device__ __forceinline__ bool allow_code(int gq, int tq, int kc) {
    int gk = kc & 3;
    int tk = kc >> 2;
    if (gk == 0) return true;
    if (gq == 0) return false;
    if (tk > tq) return false;
    return (gk == 1) || (gq == 2);
}

// ---------------- assemble ----------------
__global__ void assemble_kernel(const float* __restrict__ prefix,
                                const float* __restrict__ obs,
                                const float* __restrict__ rdo) {
    for (int idx = blockIdx.x * blockDim.x + threadIdx.x;
         idx < M_ * D_; idx += gridDim.x * blockDim.x) {
        int d = idx % D_;
        int bt = idx / D_;
        int t = bt % T_;
        int b = bt / T_;
        float v;
        if (t < P_) {
            v = prefix[((size_t)b * P_ + t) * D_ + d];
        } else {
            int tt = t - P_;
            int ho = tt / TPS;
            int r  = tt % TPS;
            if (r < NO_)
                v = obs[(((size_t)b * HOR + ho) * NO_ + r) * D_ + d];
            else
                v = rdo[(((size_t)b * HOR + ho) * NR_ + (r - NO_)) * D_ + d];
        }
        g_x[idx] = v;
    }
}

// ---------------- weight quantization: absmax per output column ----------------
// src [K,N] (per layer). scales[l*N + n] = absmax(col n)/127
__global__ void wabsmax_kernel(const float* __restrict__ src, float* __restrict__ scales,
                               int K, int N) {
    int n = blockIdx.x * blockDim.x + threadIdx.x;
    int l = blockIdx.y;
    if (n >= N) return;
    const float* s = src + (size_t)l * K * N;
    float m = 0.0f;
    for (int k = 0; k < K; k++) m = fmaxf(m, fabsf(s[(size_t)k * N + n]));
    scales[(size_t)l * N + n] = fmaxf(m, 1e-8f) / 127.0f;
}

// transpose + quantize: src[K,N] -> q1T/q2T [N,K] int8, using scales[n]
__global__ void wquant_kernel(const float* __restrict__ src,
                              int8_t* __restrict__ q1T, int8_t* __restrict__ q2T,
                              const float* __restrict__ scales, int K, int N) {
    __shared__ float t[32][33];
    const int l = blockIdx.y;
    const int cols = N / 32;
    const int cb = (blockIdx.x % cols) * 32, rb = (blockIdx.x / cols) * 32;
    const int tx = threadIdx.x, ty = threadIdx.y;
    const float* s = src + (size_t)l * K * N;
    int8_t* o1 = q1T + (size_t)l * K * N;
    int8_t* o2 = q2T + (size_t)l * K * N;
    const float* sc = scales + (size_t)l * N;
    #pragma unroll
    for (int i = 0; i < 32; i += 8)
        t[ty + i][tx] = s[(size_t)(rb + ty + i) * N + cb + tx];
    __syncthreads();
    #pragma unroll
    for (int i = 0; i < 32; i += 8) {
        int n = cb + ty + i;
        float inv_s = 1.0f / sc[n];
        int8_t q1, q2;
        quant2(t[tx][ty + i], inv_s, q1, q2);
        size_t o = (size_t)n * K + rb + tx;
        o1[o] = q1;
        o2[o] = q2;
    }
}

// ---------------- reductions ----------------
__device__ __forceinline__ float block_reduce_sum(float v, float* red) {
    int lane = threadIdx.x & 31;
    int wid  = threadIdx.x >> 5;
    #pragma unroll
    for (int o = 16; o; o >>= 1) v += __shfl_down_sync(0xffffffffu, v, o);
    if (lane == 0) red[wid] = v;
    __syncthreads();
    if (threadIdx.x < 32) {
        float t = (threadIdx.x < 8) ? red[threadIdx.x] : 0.0f;
        #pragma unroll
        for (int o = 4; o; o >>= 1) t += __shfl_down_sync(0xffffffffu, t, o);
        if (threadIdx.x == 0) red[32] = t;
    }
    __syncthreads();
    return red[32];
}
__device__ __forceinline__ float block_reduce_max(float v, float* red) {
    int lane = threadIdx.x & 31;
    int wid  = threadIdx.x >> 5;
    #pragma unroll
    for (int o = 16; o; o >>= 1) v = fmaxf(v, __shfl_down_sync(0xffffffffu, v, o));
    if (lane == 0) red[wid] = v;
    __syncthreads();
    if (threadIdx.x < 32) {
        float t = (threadIdx.x < 8) ? red[threadIdx.x] : 0.0f;
        #pragma unroll
        for (int o = 4; o; o >>= 1) t = fmaxf(t, __shfl_down_sync(0xffffffffu, t, o));
        if (threadIdx.x == 0) red[32] = t;
    }
    __syncthreads();
    return red[32];
}

// ---------------- layernorm (fp32 out, final) ----------------
__global__ void ln_kernel(const float* __restrict__ x,
                          const float* __restrict__ s,
                          const float* __restrict__ b,
                          float* __restrict__ y) {
    __shared__ float red[33];
    int row = blockIdx.x;
    const float* xp = x + (size_t)row * D_;
    float v0 = xp[threadIdx.x];
    float v1 = xp[threadIdx.x + 256];
    float v2 = xp[threadIdx.x + 512];
    float mu = block_reduce_sum(v0 + v1 + v2, red) * (1.0f / D_);
    float d0 = v0 - mu, d1 = v1 - mu, d2 = v2 - mu;
    float var = block_reduce_sum(d0 * d0 + d1 * d1 + d2 * d2, red) * (1.0f / D_);
    float inv = rsqrtf(var + LN_EPS);
    float* yp = y + (size_t)row * D_;
    yp[threadIdx.x      ] = d0 * inv * s[threadIdx.x      ] + b[threadIdx.x      ];
    yp[threadIdx.x + 256] = d1 * inv * s[threadIdx.x + 256] + b[threadIdx.x + 256];
    yp[threadIdx.x + 512] = d2 * inv * s[threadIdx.x + 512] + b[threadIdx.x + 512];
}

// ---------------- layernorm + row quantization ----------------
__global__ void ln_quant_kernel(const float* __restrict__ x,
                                const float* __restrict__ s,
                                const float* __restrict__ b,
                                int8_t* __restrict__ q1, int8_t* __restrict__ q2,
                                float* __restrict__ scl) {
    __shared__ float red[33];
    int row = blockIdx.x;
    const float* xp = x + (size_t)row * D_;
    float v0 = xp[threadIdx.x];
    float v1 = xp[threadIdx.x + 256];
    float v2 = xp[threadIdx.x + 512];
    float mu = block_reduce_sum(v0 + v1 + v2, red) * (1.0f / D_);
    float d0 = v0 - mu, d1 = v1 - mu, d2 = v2 - mu;
    float var = block_reduce_sum(d0 * d0 + d1 * d1 + d2 * d2, red) * (1.0f / D_);
    float inv = rsqrtf(var + LN_EPS);
    float y0 = d0 * inv * s[threadIdx.x      ] + b[threadIdx.x      ];
    float y1 = d1 * inv * s[threadIdx.x + 256] + b[threadIdx.x + 256];
    float y2 = d2 * inv * s[threadIdx.x + 512] + b[threadIdx.x + 512];
    float mx = block_reduce_max(fmaxf(fabsf(y0), fmaxf(fabsf(y1), fabsf(y2))), red);
    float sc = fmaxf(mx, 1e-8f) / 127.0f;
    float inv_s = 1.0f / sc;
    if (threadIdx.x == 0) scl[row] = sc;
    size_t base = (size_t)row * D_;
    int8_t a, c;
    quant2(y0, inv_s, a, c); q1[base + threadIdx.x      ] = a; q2[base + threadIdx.x      ] = c;
    quant2(y1, inv_s, a, c); q1[base + threadIdx.x + 256] = a; q2[base + threadIdx.x + 256] = c;
    quant2(y2, inv_s, a, c); q1[base + threadIdx.x + 512] = a; q2[base + threadIdx.x + 512] = c;
}

// ---------------- generic fp32-row -> int8 pair quantization ----------------
// one block per row; C = 768 or 3072 (multiple of 256)
__global__ void quant_rows_kernel(const float* __restrict__ src,
                                  int8_t* __restrict__ q1, int8_t* __restrict__ q2,
                                  float* __restrict__ scl, int C) {
    __shared__ float red[33];
    int row = blockIdx.x;
    const float* xp = src + (size_t)row * C;
    float mx = 0.0f;
    for (int c = threadIdx.x; c < C; c += 256) mx = fmaxf(mx, fabsf(xp[c]));
    mx = block_reduce_max(mx, red);
    float sc = fmaxf(mx, 1e-8f) / 127.0f;
    float inv_s = 1.0f / sc;
    if (threadIdx.x == 0) scl[row] = sc;
    size_t base = (size_t)row * C;
    for (int c = threadIdx.x; c < C; c += 256) {
        int8_t a, b;
        quant2(xp[c], inv_s, a, b);
        q1[base + c] = a;
        q2[base + c] = b;
    }
}

// ---------------- int8 two-level warp-mma GEMM ----------------
// C[M,N] = As[m]*Ws[n] * (Aq1@Wq1^T + (Aq1@Wq2^T + Aq2@Wq1^T)/128) + bias
// EPI 0: -> split bf16 (qkv) ; EPI 1: gelu -> fp32 ; EPI 2: +R -> fp32
template <int EPI>
__global__ __launch_bounds__(256, 1) void gemm_i8(
    const int8_t* __restrict__ Aq1, const int8_t* __restrict__ Aq2,
    const float* __restrict__ As,
    const int8_t* __restrict__ Wq1, const int8_t* __restrict__ Wq2,
    const float* __restrict__ Ws,
    const float* __restrict__ bias, const float* __restrict__ R,
    float* __restrict__ C,
    __nv_bfloat16* __restrict__ Chi, __nv_bfloat16* __restrict__ Clo,
    int Ndim, int Kdim) {
    extern __shared__ char smem[];
    const unsigned sbase = smem_u32(smem);
    const int tid = threadIdx.x;
    const int lane = tid & 31;
    const int wid = tid >> 5;
    const int warp_m = wid & 1;          // 2 warp rows (64 M each)
    const int warp_n = wid >> 1;         // 4 warp cols (32 N each)
    const int bm = blockIdx.y * BM;
    const int bn = blockIdx.x * BN;
    const int NK = Kdim / BK;            // BK=64 int8

    // cp.async mapping: rows of 64B = 4 chunks of 16B; thread -> (row tid>>2 / +64, chunk tid&3)
    const int r_ = tid >> 2, cc_ = tid & 3;
    const int r2_ = r_ + 64;
    const unsigned so1 = (unsigned)(r_ * RSB + cc_ * 16);
    const unsigned so2 = (unsigned)(r2_ * RSB + cc_ * 16);

    auto issue_stage = [&](int st) {
        const unsigned sb = sbase + (unsigned)((st & 1) * STAGE_B);
        const int k0 = st * BK;
        size_t a1 = (size_t)(bm + r_)  * Kdim + k0 + 16 * cc_;
        size_t a2 = (size_t)(bm + r2_) * Kdim + k0 + 16 * cc_;
        size_t b1 = (size_t)(bn + r_)  * Kdim + k0 + 16 * cc_;
        size_t b2 = (size_t)(bn + r2_) * Kdim + k0 + 16 * cc_;
        cp16(sb + so1,              Aq1 + a1);
        cp16(sb + so2,              Aq1 + a2);
        cp16(sb + TILE_B + so1,     Aq2 + a1);
        cp16(sb + TILE_B + so2,     Aq2 + a2);
        cp16(sb + 2 * TILE_B + so1, Wq1 + b1);
        cp16(sb + 2 * TILE_B + so2, Wq1 + b2);
        cp16(sb + 3 * TILE_B + so1, Wq2 + b1);
        cp16(sb + 3 * TILE_B + so2, Wq2 + b2);
        cp_commit();
    };

    const unsigned a_base = (unsigned)((warp_m * 64 + (lane & 15)) * RSB + (lane >> 4) * 16);
    const unsigned b_row = (unsigned)(warp_n * 32 + (lane & 7) + ((lane >> 4) << 3));
    const unsigned b_base = (unsigned)(b_row * RSB + (((lane >> 3) & 1) * 16));

    int acc1[4][4][4], acc2[4][4][4];
    #pragma unroll
    for (int mt = 0; mt < 4; mt++)
        #pragma unroll
        for (int nt = 0; nt < 4; nt++)
            #pragma unroll
            for (int r = 0; r < 4; r++) { acc1[mt][nt][r] = 0; acc2[mt][nt][r] = 0; }

    issue_stage(0);

    for (int i = 0; i < NK; i++) {
        cp_wait<0>();
        __syncthreads();
        if (i + 1 < NK) issue_stage(i + 1);

        const unsigned tA1 = sbase + (unsigned)((i & 1) * STAGE_B);
        const unsigned tA2 = tA1 + TILE_B;
        const unsigned tB1 = tA2 + TILE_B;
        const unsigned tB2 = tB1 + TILE_B;

        #pragma unroll
        for (int ks = 0; ks < 2; ks++) {   // each ks covers 32 int8 of K
            unsigned fb1[2][4], fb2[2][4];
            #pragma unroll
            for (int pr = 0; pr < 2; pr++) {
                unsigned bo = b_base + (unsigned)(pr * 16 * RSB + ks * 32);
                ldsm_x4(fb1[pr], tB1 + bo);
                ldsm_x4(fb2[pr], tB2 + bo);
            }
            #pragma unroll
            for (int mt = 0; mt < 4; mt++) {
                unsigned fa1[4], fa2[4];
                unsigned ao = a_base + (unsigned)(mt * 16 * RSB + ks * 32);
                ldsm_x4(fa1, tA1 + ao);
                ldsm_x4(fa2, tA2 + ao);
                #pragma unroll
                for (int nt = 0; nt < 4; nt++) {
                    const unsigned* b1p = &fb1[nt >> 1][(nt & 1) * 2];
                    const unsigned* b2p = &fb2[nt >> 1][(nt & 1) * 2];
                    mma_s8(acc1[mt][nt], fa1, b1p);
                    mma_s8(acc2[mt][nt], fa1, b2p);
                    mma_s8(acc2[mt][nt], fa2, b1p);
                }
            }
        }
    }

    // ---- epilogue ----
    const int g = lane >> 2, tg = lane & 3;
    #pragma unroll
    for (int mt = 0; mt < 4; mt++) {
        int row0 = bm + warp_m * 64 + mt * 16 + g;
        float sa0 = As[row0];
        float sa1 = As[row0 + 8];
        #pragma unroll
        for (int nt = 0; nt < 4; nt++) {
            int col = bn + warp_n * 32 + nt * 8 + tg * 2;
            float2 bv = *(const float2*)(bias + col);
            float2 sw = *(const float2*)(Ws + col);
            float c0 = sa0 * sw.x * ((float)acc1[mt][nt][0] + (float)acc2[mt][nt][0] * 0.0078125f) + bv.x;
            float c1 = sa0 * sw.y * ((float)acc1[mt][nt][1] + (float)acc2[mt][nt][1] * 0.0078125f) + bv.y;
            float c2 = sa1 * sw.x * ((float)acc1[mt][nt][2] + (float)acc2[mt][nt][2] * 0.0078125f) + bv.x;
            float c3 = sa1 * sw.y * ((float)acc1[mt][nt][3] + (float)acc2[mt][nt][3] * 0.0078125f) + bv.y;
            size_t o0 = (size_t)row0 * Ndim + col;
            size_t o1 = o0 + (size_t)8 * Ndim;
            if (EPI == 0) {
                __nv_bfloat16 h0, l0v, h1, l1v, h2, l2v, h3, l3v;
                split2(c0, h0, l0v); split2(c1, h1, l1v);
                split2(c2, h2, l2v); split2(c3, h3, l3v);
                *(unsigned*)(Chi + o0) = pack_bf2(h0, h1);
                *(unsigned*)(Clo + o0) = pack_bf2(l0v, l1v);
                *(unsigned*)(Chi + o1) = pack_bf2(h2, h3);
                *(unsigned*)(Clo + o1) = pack_bf2(l2v, l3v);
            } else if (EPI == 1) {
                *(float2*)(C + o0) = make_float2(gelu_tanh(c0), gelu_tanh(c1));
                *(float2*)(C + o1) = make_float2(gelu_tanh(c2), gelu_tanh(c3));
            } else {
                float2 r0 = *(const float2*)(R + o0);
                float2 r1 = *(const float2*)(R + o1);
                *(float2*)(C + o0) = make_float2(c0 + r0.x, c1 + r0.y);
                *(float2*)(C + o1) = make_float2(c2 + r1.x, c3 + r1.y);
            }
        }
    }
}

// ---------------- tensor-core flash attention (split bf16, fp32 out) ----------------
__global__ __launch_bounds__(128) void attn_mma(
    const __nv_bfloat16* __restrict__ qh_, const __nv_bfloat16* __restrict__ ql_,
    float* __restrict__ out_) {
    extern __shared__ char smem[];
    __nv_bfloat16* sb = (__nv_bfloat16*)smem;
    int* kcode = (int*)(smem + AT_CODE_B);
    const unsigned sbase = smem_u32(smem);
    const int h = blockIdx.y, b = blockIdx.z;
    const int q0 = blockIdx.x * 64;
    const int tid = threadIdx.x;
    const int lane = tid & 31;
    const int warp = tid >> 5;
    const int tg2 = (lane & 3) * 2;

    for (int idx = tid; idx < 64 * 8; idx += 128) {
        int r = idx >> 3, c = idx & 7;
        int gr = min(q0 + r, T_ - 1);
        size_t src = ((size_t)(b * T_ + gr)) * (3 * D_) + h * HD_ + c * 8;
        *(uint4*)&sb[AT_QH + r * ARS + c * 8] = *(const uint4*)(qh_ + src);
        *(uint4*)&sb[AT_QL + r * ARS + c * 8] = *(const uint4*)(ql_ + src);
    }
    __syncthreads();

    unsigned qfh[4][4], qfl[4][4];
    {
        unsigned rowoff = (unsigned)((warp * 16 + (lane & 15)) * (ARS * 2)) + (lane >> 4) * 16;
        #pragma unroll
        for (int ks = 0; ks < 4; ks++) {
            ldsm_x4(qfh[ks], sbase + AT_QH * 2 + rowoff + ks * 32);
            ldsm_x4(qfl[ks], sbase + AT_QL * 2 + rowoff + ks * 32);
        }
    }

    const int r0 = q0 + warp * 16 + (lane >> 2);
    const int r1 = r0 + 8;
    const int rc0 = min(r0, T_ - 1), rc1 = min(r1, T_ - 1);
    const int gq0 = tok_group(rc0), tq0 = tok_ts(rc0);
    const int gq1 = tok_group(rc1), tq1 = tok_ts(rc1);

    float m0 = -1e30f, m1 = -1e30f, l0 = 0.0f, l1 = 0.0f;
    float o[8][4];
    #pragma unroll
    for (int nt = 0; nt < 8; nt++)
        #pragma unroll
        for (int r = 0; r < 4; r++) o[nt][r] = 0.0f;

    const int rlast = min(q0 + 63, T_ - 1);
    const int kmax = P_ + (tok_ts(rlast) + 1) * TPS;

    const unsigned kb = (unsigned)(((lane & 7) + ((lane >> 4) << 3)) * (ARS * 2)) +
                        ((lane >> 3) & 1) * 16;

    for (int k0 = 0; k0 < kmax; k0 += 64) {
        __syncthreads();
        for (int idx = tid; idx < 64 * 8; idx += 128) {
            int r = idx >> 3, c = idx & 7;
            int kr = k0 + r;
            uint4 z = make_uint4(0, 0, 0, 0);
            uint4 kvh = z, kvl = z, vvh = z, vvl = z;
            if (kr < T_) {
                size_t src = ((size_t)(b * T_ + kr)) * (3 * D_) + D_ + h * HD_ + c * 8;
                kvh = *(const uint4*)(qh_ + src);
                kvl = *(const uint4*)(ql_ + src);
                vvh = *(const uint4*)(qh_ + src + D_);
                vvl = *(const uint4*)(ql_ + src + D_);
            }
            *(uint4*)&sb[AT_KH + r * ARS + c * 8] = kvh;
            *(uint4*)&sb[AT_KL + r * ARS + c * 8] = kvl;
            *(uint4*)&sb[AT_VH + r * ARS + c * 8] = vvh;
            *(uint4*)&sb[AT_VL + r * ARS + c * 8] = vvl;
        }
        if (tid < 64) {
            int kg = k0 + tid;
            kcode[tid] = (kg < kmax && kg < T_)
                       ? ((tok_ts(kg) << 2) | tok_group(kg))
                       : ((0x3FFF << 2) | 3);
        }
        __syncthreads();

        float s[8][4];
        #pragma unroll
        for (int nt = 0; nt < 8; nt++)
            #pragma unroll
            for (int r = 0; r < 4; r++) s[nt][r] = 0.0f;

        #pragma unroll
        for (int kg = 0; kg < 4; kg++) {
            #pragma unroll
            for (int ks = 0; ks < 4; ks++) {
                unsigned kh[4], kl[4];
                unsigned addr = sbase + kb + (unsigned)(kg * 16 * (ARS * 2)) + ks * 32;
                ldsm_x4(kh, addr + AT_KH * 2);
                ldsm_x4(kl, addr + AT_KL * 2);
                #pragma unroll
                for (int half = 0; half < 2; half++) {
                    int nt = kg * 2 + half;
                    mma_bf16(s[nt], qfh[ks], &kh[half * 2]);
                    mma_bf16(s[nt], qfh[ks], &kl[half * 2]);
                    mma_bf16(s[nt], qfl[ks], &kh[half * 2]);
                }
            }
        }

        #pragma unroll
        for (int nt = 0; nt < 8; nt++) {
            int kc0 = kcode[nt * 8 + tg2];
            int kc1 = kcode[nt * 8 + tg2 + 1];
            s[nt][0] = allow_code(gq0, tq0, kc0) ? s[nt][0] * ATT_SCALE : -1e30f;
            s[nt][1] = allow_code(gq0, tq0, kc1) ? s[nt][1] * ATT_SCALE : -1e30f;
            s[nt][2] = allow_code(gq1, tq1, kc0) ? s[nt][2] * ATT_SCALE : -1e30f;
            s[nt][3] = allow_code(gq1, tq1, kc1) ? s[nt][3] * ATT_SCALE : -1e30f;
        }

        float mx0 = -1e30f, mx1 = -1e30f;
        #pragma unroll
        for (int nt = 0; nt < 8; nt++) {
            mx0 = fmaxf(mx0, fmaxf(s[nt][0], s[nt][1]));
            mx1 = fmaxf(mx1, fmaxf(s[nt][2], s[nt][3]));
        }
        mx0 = fmaxf(mx0, __shfl_xor_sync(0xffffffffu, mx0, 1));
        mx0 = fmaxf(mx0, __shfl_xor_sync(0xffffffffu, mx0, 2));
        mx1 = fmaxf(mx1, __shfl_xor_sync(0xffffffffu, mx1, 1));
        mx1 = fmaxf(mx1, __shfl_xor_sync(0xffffffffu, mx1, 2));
        float mn0 = fmaxf(m0, mx0), mn1 = fmaxf(m1, mx1);
        float corr0 = __expf(m0 - mn0), corr1 = __expf(m1 - mn1);
        m0 = mn0; m1 = mn1;
        l0 *= corr0; l1 *= corr1;
        #pragma unroll
        for (int nt = 0; nt < 8; nt++) {
            o[nt][0] *= corr0; o[nt][1] *= corr0;
            o[nt][2] *= corr1; o[nt][3] *= corr1;
        }

        #pragma unroll
        for (int kv = 0; kv < 4; kv++) {
            unsigned ph[4], pl[4];
            #pragma unroll
            for (int half = 0; half < 2; half++) {
                int nt = kv * 2 + half;
                float p0 = __expf(s[nt][0] - m0);
                float p1 = __expf(s[nt][1] - m0);
                float p2 = __expf(s[nt][2] - m1);
                float p3 = __expf(s[nt][3] - m1);
                l0 += p0 + p1;
                l1 += p2 + p3;
                __nv_bfloat16 h0, lo0, h1, lo1, h2, lo2, h3, lo3;
                split2(p0, h0, lo0); split2(p1, h1, lo1);
                split2(p2, h2, lo2); split2(p3, h3, lo3);
                ph[half * 2 + 0] = pack_bf2(h0, h1);
                ph[half * 2 + 1] = pack_bf2(h2, h3);
                pl[half * 2 + 0] = pack_bf2(lo0, lo1);
                pl[half * 2 + 1] = pack_bf2(lo2, lo3);
            }
            #pragma unroll
            for (int dg = 0; dg < 4; dg++) {
                unsigned vh[4], vl[4];
                unsigned addr = sbase + kb + (unsigned)(kv * 16 * (ARS * 2)) + dg * 32;
                ldsm_x4t(vh, addr + AT_VH * 2);
                ldsm_x4t(vl, addr + AT_VL * 2);
                #pragma unroll
                for (int half = 0; half < 2; half++) {
                    int nt = dg * 2 + half;
                    unsigned bhp[2] = {vh[half], vh[2 + half]};
                    unsigned blp[2] = {vl[half], vl[2 + half]};
                    mma_bf16(o[nt], ph, bhp);
                    mma_bf16(o[nt], ph, blp);
                    mma_bf16(o[nt], pl, bhp);
                }
            }
        }
    }

    l0 += __shfl_xor_sync(0xffffffffu, l0, 1);
    l0 += __shfl_xor_sync(0xffffffffu, l0, 2);
    l1 += __shfl_xor_sync(0xffffffffu, l1, 1);
    l1 += __shfl_xor_sync(0xffffffffu, l1, 2);
    float li0 = 1.0f / l0, li1 = 1.0f / l1;

    #pragma unroll
    for (int nt = 0; nt < 8; nt++) {
        int d = h * HD_ + nt * 8 + tg2;
        if (r0 < T_) {
            size_t off = ((size_t)(b * T_ + r0)) * D_ + d;
            *(float2*)(out_ + off) = make_float2(o[nt][0] * li0, o[nt][1] * li0);
        }
        if (r1 < T_) {
            size_t off = ((size_t)(b * T_ + r1)) * D_ + d;
            *(float2*)(out_ + off) = make_float2(o[nt][2] * li1, o[nt][3] * li1);
        }
    }
}

// ---------------- host orchestration ----------------
extern "C" void kernel_launch(void* const* d_in, const int* in_sizes, int n_in,
                              void* d_out, int out_size) {
    (void)in_sizes; (void)n_in; (void)out_size;

    const float* prefix = (const float*)d_in[0];
    const float* obs    = (const float*)d_in[2];
    const float* rdo    = (const float*)d_in[4];
    const float* ln1_s  = (const float*)d_in[6];
    const float* ln1_b  = (const float*)d_in[7];
    const float* wqkv   = (const float*)d_in[8];
    const float* bqkv   = (const float*)d_in[9];
    const float* wo     = (const float*)d_in[10];
    const float* bo     = (const float*)d_in[11];
    const float* ln2_s  = (const float*)d_in[12];
    const float* ln2_b  = (const float*)d_in[13];
    const float* w1     = (const float*)d_in[14];
    const float* b1     = (const float*)d_in[15];
    const float* w2     = (const float*)d_in[16];
    const float* b2     = (const float*)d_in[17];
    const float* lnf_s  = (const float*)d_in[18];
    const float* lnf_b  = (const float*)d_in[19];
    float* out = (float*)d_out;

    float *x, *att, *ffn;
    int8_t *yq1, *yq2, *aq1, *aq2, *fq1, *fq2;
    float *ysc, *asc, *fsc;
    __nv_bfloat16 *qkvhi, *qkvlo;
    int8_t *wq_qkv1, *wq_qkv2, *wq_o1, *wq_o2, *wq_11, *wq_12, *wq_21, *wq_22;
    float *ws_qkv, *ws_o, *ws_1, *ws_2;
    cudaGetSymbolAddress((void**)&x,     g_x);
    cudaGetSymbolAddress((void**)&att,   g_att);
    cudaGetSymbolAddress((void**)&ffn,   g_ffn);
    cudaGetSymbolAddress((void**)&yq1,   g_yq1);
    cudaGetSymbolAddress((void**)&yq2,   g_yq2);
    cudaGetSymbolAddress((void**)&ysc,   g_ysc);
    cudaGetSymbolAddress((void**)&aq1,   g_aq1);
    cudaGetSymbolAddress((void**)&aq2,   g_aq2);
    cudaGetSymbolAddress((void**)&asc,   g_asc);
    cudaGetSymbolAddress((void**)&fq1,   g_fq1);
    cudaGetSymbolAddress((void**)&fq2,   g_fq2);
    cudaGetSymbolAddress((void**)&fsc,   g_fsc);
    cudaGetSymbolAddress((void**)&qkvhi, g_qkv_hi);
    cudaGetSymbolAddress((void**)&qkvlo, g_qkv_lo);
    cudaGetSymbolAddress((void**)&wq_qkv1, g_wqkv_q1);
    cudaGetSymbolAddress((void**)&wq_qkv2, g_wqkv_q2);
    cudaGetSymbolAddress((void**)&ws_qkv,  g_wqkv_sc);
    cudaGetSymbolAddress((void**)&wq_o1,   g_wo_q1);
    cudaGetSymbolAddress((void**)&wq_o2,   g_wo_q2);
    cudaGetSymbolAddress((void**)&ws_o,    g_wo_sc);
    cudaGetSymbolAddress((void**)&wq_11,   g_w1_q1);
    cudaGetSymbolAddress((void**)&wq_12,   g_w1_q2);
    cudaGetSymbolAddress((void**)&ws_1,    g_w1_sc);
    cudaGetSymbolAddress((void**)&wq_21,   g_w2_q1);
    cudaGetSymbolAddress((void**)&wq_22,   g_w2_q2);
    cudaGetSymbolAddress((void**)&ws_2,    g_w2_sc);

    cudaFuncSetAttribute(gemm_i8<0>, cudaFuncAttributeMaxDynamicSharedMemorySize, SMEM_GEMM);
    cudaFuncSetAttribute(gemm_i8<1>, cudaFuncAttributeMaxDynamicSharedMemorySize, SMEM_GEMM);
    cudaFuncSetAttribute(gemm_i8<2>, cudaFuncAttributeMaxDynamicSharedMemorySize, SMEM_GEMM);
    cudaFuncSetAttribute(attn_mma, cudaFuncAttributeMaxDynamicSharedMemorySize, ATTN_SMEM);

    assemble_kernel<<<2048, 256>>>(prefix, obs, rdo);

    // ---- weight quantization (setup) ----
    const dim3 tb(32, 8);
    wabsmax_kernel<<<dim3((3 * D_ + 255) / 256, L_), 256>>>(wqkv, ws_qkv, D_, 3 * D_);
    wabsmax_kernel<<<dim3((D_ + 255) / 256, L_), 256>>>(wo, ws_o, D_, D_);
    wabsmax_kernel<<<dim3((F_ + 255) / 256, L_), 256>>>(w1, ws_1, D_, F_);
    wabsmax_kernel<<<dim3((D_ + 255) / 256, L_), 256>>>(w2, ws_2, F_, D_);
    wquant_kernel<<<dim3((3 * D_ / 32) * (D_ / 32), L_), tb>>>(wqkv, wq_qkv1, wq_qkv2, ws_qkv, D_, 3 * D_);
    wquant_kernel<<<dim3((D_ / 32) * (D_ / 32), L_), tb>>>(wo, wq_o1, wq_o2, ws_o, D_, D_);
    wquant_kernel<<<dim3((F_ / 32) * (D_ / 32), L_), tb>>>(w1, wq_11, wq_12, ws_1, D_, F_);
    wquant_kernel<<<dim3((D_ / 32) * (F_ / 32), L_), tb>>>(w2, wq_21, wq_22, ws_2, F_, D_);

    const dim3 g_qkv_grid(3 * D_ / BN, M_ / BM);   // (18, 86)
    const dim3 g_wo_grid (D_ / BN,     M_ / BM);   // (6, 86)
    const dim3 g_w1_grid (F_ / BN,     M_ / BM);   // (24, 86)
    const dim3 g_attn((T_ + 63) / 64, NH_, B_);    // (22, 12, 8)

    for (int l = 0; l < L_; l++) {
        ln_quant_kernel<<<M_, 256>>>(x, ln1_s + (size_t)l * D_, ln1_b + (size_t)l * D_,
                                     yq1, yq2, ysc);
        gemm_i8<0><<<g_qkv_grid, 256, SMEM_GEMM>>>(
            yq1, yq2, ysc,
            wq_qkv1 + (size_t)l * 3 * D_ * D_, wq_qkv2 + (size_t)l * 3 * D_ * D_,
            ws_qkv + (size_t)l * 3 * D_,
            bqkv + (size_t)l * 3 * D_, nullptr, nullptr, qkvhi, qkvlo, 3 * D_, D_);
        attn_mma<<<g_attn, 128, ATTN_SMEM>>>(qkvhi, qkvlo, att);
        quant_rows_kernel<<<M_, 256>>>(att, aq1, aq2, asc, D_);
        gemm_i8<2><<<g_wo_grid, 256, SMEM_GEMM>>>(
            aq1, aq2, asc,
            wq_o1 + (size_t)l * D_ * D_, wq_o2 + (size_t)l * D_ * D_,
            ws_o + (size_t)l * D_,
            bo + (size_t)l * D_, x, x, nullptr, nullptr, D_, D_);
        ln_quant_kernel<<<M_, 256>>>(x, ln2_s + (size_t)l * D_, ln2_b + (size_t)l * D_,
                                     yq1, yq2, ysc);
        gemm_i8<1><<<g_w1_grid, 256, SMEM_GEMM>>>(
            yq1, yq2, ysc,
            wq_11 + (size_t)l * F_ * D_, wq_12 + (size_t)l * F_ * D_,
            ws_1 + (size_t)l * F_,
            b1 + (size_t)l * F_, nullptr, ffn, nullptr, nullptr, F_, D_);
        quant_rows_kernel<<<M_, 256>>>(ffn, fq1, fq2, fsc, F_);
        gemm_i8<2><<<g_wo_grid, 256, SMEM_GEMM>>>(
            fq1, fq2, fsc,
            wq_21 + (size_t)l * D_ * F_, wq_22 + (size_t)l * D_ * F_,
            ws_2 + (size_t)l * D_,
            b2 + (size_t)l * D_, x, x, nullptr, nullptr, D_, F_);
    }

    ln_kernel<<<M_, 256>>>(x, lnf_s, lnf_b, out);
}

// round 10
// speedup vs baseline: 1.0188x; 1.0188x over previous
#include <cuda_runtime.h>
#include <cuda_bf16.h>
#include <math.h>
#include <stdint.h>

// ---------------- problem constants ----------------
namespace {
constexpr int B_  = 8;
constexpr int P_  = 16;
constexpr int HOR = 10;
constexpr int NO_ = 128;
constexpr int NR_ = 8;
constexpr int D_  = 768;
constexpr int NH_ = 12;
constexpr int HD_ = 64;
constexpr int F_  = 3072;
constexpr int L_  = 12;
constexpr int TPS = NO_ + NR_;          // 136
constexpr int T_  = P_ + HOR * TPS;     // 1376
constexpr int M_  = B_ * T_;            // 11008
constexpr float LN_EPS = 1e-6f;
constexpr float ATT_SCALE = 0.125f;     // 1/sqrt(64)

// int8 GEMM tiling: 512 threads, 4x4 warp grid (32x32 warp tile), BK=64 int8, 2-stage cp.async
constexpr int BM = 128;
constexpr int BN = 128;
constexpr int BK = 64;                   // int8 elements (64B rows)
constexpr int RSB = 80;                  // SMEM row stride bytes, conflict-free ldmatrix
constexpr int TILE_B = 128 * RSB;        // 10240 bytes per operand tile
constexpr int STAGE_B = 4 * TILE_B;      // Aq1,Aq2,Bq1,Bq2 = 40960
constexpr int SMEM_GEMM = 2 * STAGE_B;   // 81920

// attention smem layout (bf16 units unless noted)
constexpr int ARS   = 72;                // 144B row stride, conflict-free
constexpr int AT_QH = 0;
constexpr int AT_QL = 1 * 64 * ARS;
constexpr int AT_KH = 2 * 64 * ARS;
constexpr int AT_KL = 3 * 64 * ARS;
constexpr int AT_VH = 4 * 64 * ARS;
constexpr int AT_VL = 5 * 64 * ARS;
constexpr int AT_CODE_B = 6 * 64 * ARS * 2;
constexpr int ATTN_SMEM = AT_CODE_B + 64 * 4;   // 55552 bytes
}

// ---------------- scratch (device globals: no cudaMalloc allowed) ----------------
__device__ float g_x  [(size_t)M_ * D_];
__device__ float g_att[(size_t)M_ * D_];
__device__ float g_ffn[(size_t)M_ * F_];
__device__ int8_t g_yq1[(size_t)M_ * D_];
__device__ int8_t g_yq2[(size_t)M_ * D_];
__device__ float  g_ysc[M_];
__device__ int8_t g_aq1[(size_t)M_ * D_];
__device__ int8_t g_aq2[(size_t)M_ * D_];
__device__ float  g_asc[M_];
__device__ int8_t g_fq1[(size_t)M_ * F_];
__device__ int8_t g_fq2[(size_t)M_ * F_];
__device__ float  g_fsc[M_];
__device__ __nv_bfloat16 g_qkv_hi[(size_t)M_ * 3 * D_];
__device__ __nv_bfloat16 g_qkv_lo[(size_t)M_ * 3 * D_];
__device__ int8_t g_wqkv_q1[(size_t)L_ * 3 * D_ * D_];
__device__ int8_t g_wqkv_q2[(size_t)L_ * 3 * D_ * D_];
__device__ float  g_wqkv_sc[(size_t)L_ * 3 * D_];
__device__ int8_t g_wo_q1[(size_t)L_ * D_ * D_];
__device__ int8_t g_wo_q2[(size_t)L_ * D_ * D_];
__device__ float  g_wo_sc[(size_t)L_ * D_];
__device__ int8_t g_w1_q1[(size_t)L_ * F_ * D_];
__device__ int8_t g_w1_q2[(size_t)L_ * F_ * D_];
__device__ float  g_w1_sc[(size_t)L_ * F_];
__device__ int8_t g_w2_q1[(size_t)L_ * D_ * F_];
__device__ int8_t g_w2_q2[(size_t)L_ * D_ * F_];
__device__ float  g_w2_sc[(size_t)L_ * D_];

// ---------------- mma / async helpers ----------------
__device__ __forceinline__ unsigned smem_u32(const void* p) {
    return (unsigned)__cvta_generic_to_shared(p);
}
__device__ __forceinline__ void ldsm_x4(unsigned* r, unsigned addr) {
    asm volatile("ldmatrix.sync.aligned.m8n8.x4.shared.b16 {%0,%1,%2,%3}, [%4];"
                 : "=r"(r[0]), "=r"(r[1]), "=r"(r[2]), "=r"(r[3]) : "r"(addr));
}
__device__ __forceinline__ void ldsm_x4t(unsigned* r, unsigned addr) {
    asm volatile("ldmatrix.sync.aligned.m8n8.x4.trans.shared.b16 {%0,%1,%2,%3}, [%4];"
                 : "=r"(r[0]), "=r"(r[1]), "=r"(r[2]), "=r"(r[3]) : "r"(addr));
}
__device__ __forceinline__ void mma_bf16(float* c, const unsigned* a, const unsigned* b) {
    asm volatile(
        "mma.sync.aligned.m16n8k16.row.col.f32.bf16.bf16.f32 "
        "{%0,%1,%2,%3}, {%4,%5,%6,%7}, {%8,%9}, {%0,%1,%2,%3};"
        : "+f"(c[0]), "+f"(c[1]), "+f"(c[2]), "+f"(c[3])
        : "r"(a[0]), "r"(a[1]), "r"(a[2]), "r"(a[3]), "r"(b[0]), "r"(b[1]));
}
__device__ __forceinline__ void mma_s8(int* c, const unsigned* a, const unsigned* b) {
    asm volatile(
        "mma.sync.aligned.m16n8k32.row.col.s32.s8.s8.s32 "
        "{%0,%1,%2,%3}, {%4,%5,%6,%7}, {%8,%9}, {%0,%1,%2,%3};"
        : "+r"(c[0]), "+r"(c[1]), "+r"(c[2]), "+r"(c[3])
        : "r"(a[0]), "r"(a[1]), "r"(a[2]), "r"(a[3]), "r"(b[0]), "r"(b[1]));
}
__device__ __forceinline__ void cp16(unsigned saddr, const void* g) {
    asm volatile("cp.async.cg.shared.global [%0], [%1], 16;" :: "r"(saddr), "l"(g));
}
__device__ __forceinline__ void cp_commit() {
    asm volatile("cp.async.commit_group;" ::: "memory");
}
template <int N>
__device__ __forceinline__ void cp_wait() {
    asm volatile("cp.async.wait_group %0;" :: "n"(N) : "memory");
}
__device__ __forceinline__ unsigned pack_bf2(__nv_bfloat16 a, __nv_bfloat16 b) {
    __nv_bfloat162 t(a, b);
    return *(unsigned*)&t;
}
__device__ __forceinline__ void split2(float v, __nv_bfloat16& h, __nv_bfloat16& l) {
    h = __float2bfloat16(v);
    l = __float2bfloat16(v - __bfloat162float(h));
}
__device__ __forceinline__ void quant2(float x, float inv_s, int8_t& q1, int8_t& q2) {
    float t = x * inv_s;
    float r1 = rintf(t);
    r1 = fminf(fmaxf(r1, -127.0f), 127.0f);
    float r2 = rintf((t - r1) * 128.0f);
    q1 = (int8_t)(int)r1;
    q2 = (int8_t)(int)r2;
}

// ---------------- misc helpers ----------------
__device__ __forceinline__ float gelu_tanh(float x) {
    float x3 = x * x * x;
    return 0.5f * x * (1.0f + tanhf(0.7978845608028654f * (x + 0.044715f * x3)));
}
__device__ __forceinline__ int tok_group(int i) {
    if (i < P_) return 0;
    return (((i - P_) % TPS) < NO_) ? 1 : 2;
}
__device__ __forceinline__ int tok_ts(int i) {
    return (i < P_) ? -1 : (i - P_) / TPS;
}
__device__ __forceinline__ bool allow_code(int gq, int tq, int kc) {
    int gk = kc & 3;
    int tk = kc >> 2;
    if (gk == 0) return true;
    if (gq == 0) return false;
    if (tk > tq) return false;
    return (gk == 1) || (gq == 2);
}

// ---------------- assemble ----------------
__global__ void assemble_kernel(const float* __restrict__ prefix,
                                const float* __restrict__ obs,
                                const float* __restrict__ rdo) {
    for (int idx = blockIdx.x * blockDim.x + threadIdx.x;
         idx < M_ * D_; idx += gridDim.x * blockDim.x) {
        int d = idx % D_;
        int bt = idx / D_;
        int t = bt % T_;
        int b = bt / T_;
        float v;
        if (t < P_) {
            v = prefix[((size_t)b * P_ + t) * D_ + d];
        } else {
            int tt = t - P_;
            int ho = tt / TPS;
            int r  = tt % TPS;
            if (r < NO_)
                v = obs[(((size_t)b * HOR + ho) * NO_ + r) * D_ + d];
            else
                v = rdo[(((size_t)b * HOR + ho) * NR_ + (r - NO_)) * D_ + d];
        }
        g_x[idx] = v;
    }
}

// ---------------- weight quantization ----------------
__global__ void wabsmax_kernel(const float* __restrict__ src, float* __restrict__ scales,
                               int K, int N) {
    int n = blockIdx.x * blockDim.x + threadIdx.x;
    int l = blockIdx.y;
    if (n >= N) return;
    const float* s = src + (size_t)l * K * N;
    float m = 0.0f;
    for (int k = 0; k < K; k++) m = fmaxf(m, fabsf(s[(size_t)k * N + n]));
    scales[(size_t)l * N + n] = fmaxf(m, 1e-8f) / 127.0f;
}

__global__ void wquant_kernel(const float* __restrict__ src,
                              int8_t* __restrict__ q1T, int8_t* __restrict__ q2T,
                              const float* __restrict__ scales, int K, int N) {
    __shared__ float t[32][33];
    const int l = blockIdx.y;
    const int cols = N / 32;
    const int cb = (blockIdx.x % cols) * 32, rb = (blockIdx.x / cols) * 32;
    const int tx = threadIdx.x, ty = threadIdx.y;
    const float* s = src + (size_t)l * K * N;
    int8_t* o1 = q1T + (size_t)l * K * N;
    int8_t* o2 = q2T + (size_t)l * K * N;
    const float* sc = scales + (size_t)l * N;
    #pragma unroll
    for (int i = 0; i < 32; i += 8)
        t[ty + i][tx] = s[(size_t)(rb + ty + i) * N + cb + tx];
    __syncthreads();
    #pragma unroll
    for (int i = 0; i < 32; i += 8) {
        int n = cb + ty + i;
        float inv_s = 1.0f / sc[n];
        int8_t q1, q2;
        quant2(t[tx][ty + i], inv_s, q1, q2);
        size_t o = (size_t)n * K + rb + tx;
        o1[o] = q1;
        o2[o] = q2;
    }
}

// ---------------- reductions ----------------
__device__ __forceinline__ float block_reduce_sum(float v, float* red) {
    int lane = threadIdx.x & 31;
    int wid  = threadIdx.x >> 5;
    #pragma unroll
    for (int o = 16; o; o >>= 1) v += __shfl_down_sync(0xffffffffu, v, o);
    if (lane == 0) red[wid] = v;
    __syncthreads();
    if (threadIdx.x < 32) {
        float t = (threadIdx.x < 8) ? red[threadIdx.x] : 0.0f;
        #pragma unroll
        for (int o = 4; o; o >>= 1) t += __shfl_down_sync(0xffffffffu, t, o);
        if (threadIdx.x == 0) red[32] = t;
    }
    __syncthreads();
    return red[32];
}
__device__ __forceinline__ float block_reduce_max(float v, float* red) {
    int lane = threadIdx.x & 31;
    int wid  = threadIdx.x >> 5;
    #pragma unroll
    for (int o = 16; o; o >>= 1) v = fmaxf(v, __shfl_down_sync(0xffffffffu, v, o));
    if (lane == 0) red[wid] = v;
    __syncthreads();
    if (threadIdx.x < 32) {
        float t = (threadIdx.x < 8) ? red[threadIdx.x] : 0.0f;
        #pragma unroll
        for (int o = 4; o; o >>= 1) t = fmaxf(t, __shfl_down_sync(0xffffffffu, t, o));
        if (threadIdx.x == 0) red[32] = t;
    }
    __syncthreads();
    return red[32];
}

// ---------------- layernorm (fp32 out, final) ----------------
__global__ void ln_kernel(const float* __restrict__ x,
                          const float* __restrict__ s,
                          const float* __restrict__ b,
                          float* __restrict__ y) {
    __shared__ float red[33];
    int row = blockIdx.x;
    const float* xp = x + (size_t)row * D_;
    float v0 = xp[threadIdx.x];
    float v1 = xp[threadIdx.x + 256];
    float v2 = xp[threadIdx.x + 512];
    float mu = block_reduce_sum(v0 + v1 + v2, red) * (1.0f / D_);
    float d0 = v0 - mu, d1 = v1 - mu, d2 = v2 - mu;
    float var = block_reduce_sum(d0 * d0 + d1 * d1 + d2 * d2, red) * (1.0f / D_);
    float inv = rsqrtf(var + LN_EPS);
    float* yp = y + (size_t)row * D_;
    yp[threadIdx.x      ] = d0 * inv * s[threadIdx.x      ] + b[threadIdx.x      ];
    yp[threadIdx.x + 256] = d1 * inv * s[threadIdx.x + 256] + b[threadIdx.x + 256];
    yp[threadIdx.x + 512] = d2 * inv * s[threadIdx.x + 512] + b[threadIdx.x + 512];
}

// ---------------- layernorm + row quantization ----------------
__global__ void ln_quant_kernel(const float* __restrict__ x,
                                const float* __restrict__ s,
                                const float* __restrict__ b,
                                int8_t* __restrict__ q1, int8_t* __restrict__ q2,
                                float* __restrict__ scl) {
    __shared__ float red[33];
    int row = blockIdx.x;
    const float* xp = x + (size_t)row * D_;
    float v0 = xp[threadIdx.x];
    float v1 = xp[threadIdx.x + 256];
    float v2 = xp[threadIdx.x + 512];
    float mu = block_reduce_sum(v0 + v1 + v2, red) * (1.0f / D_);
    float d0 = v0 - mu, d1 = v1 - mu, d2 = v2 - mu;
    float var = block_reduce_sum(d0 * d0 + d1 * d1 + d2 * d2, red) * (1.0f / D_);
    float inv = rsqrtf(var + LN_EPS);
    float y0 = d0 * inv * s[threadIdx.x      ] + b[threadIdx.x      ];
    float y1 = d1 * inv * s[threadIdx.x + 256] + b[threadIdx.x + 256];
    float y2 = d2 * inv * s[threadIdx.x + 512] + b[threadIdx.x + 512];
    float mx = block_reduce_max(fmaxf(fabsf(y0), fmaxf(fabsf(y1), fabsf(y2))), red);
    float sc = fmaxf(mx, 1e-8f) / 127.0f;
    float inv_s = 1.0f / sc;
    if (threadIdx.x == 0) scl[row] = sc;
    size_t base = (size_t)row * D_;
    int8_t a, c;
    quant2(y0, inv_s, a, c); q1[base + threadIdx.x      ] = a; q2[base + threadIdx.x      ] = c;
    quant2(y1, inv_s, a, c); q1[base + threadIdx.x + 256] = a; q2[base + threadIdx.x + 256] = c;
    quant2(y2, inv_s, a, c); q1[base + threadIdx.x + 512] = a; q2[base + threadIdx.x + 512] = c;
}

// ---------------- generic fp32-row -> int8 pair quantization ----------------
__global__ void quant_rows_kernel(const float* __restrict__ src,
                                  int8_t* __restrict__ q1, int8_t* __restrict__ q2,
                                  float* __restrict__ scl, int C) {
    __shared__ float red[33];
    int row = blockIdx.x;
    const float* xp = src + (size_t)row * C;
    float mx = 0.0f;
    for (int c = threadIdx.x; c < C; c += 256) mx = fmaxf(mx, fabsf(xp[c]));
    mx = block_reduce_max(mx, red);
    float sc = fmaxf(mx, 1e-8f) / 127.0f;
    float inv_s = 1.0f / sc;
    if (threadIdx.x == 0) scl[row] = sc;
    size_t base = (size_t)row * C;
    for (int c = threadIdx.x; c < C; c += 256) {
        int8_t a, b;
        quant2(xp[c], inv_s, a, b);
        q1[base + c] = a;
        q2[base + c] = b;
    }
}

// ---------------- int8 two-level warp-mma GEMM (512 thr, 4x4 warps, 32x32 warp tile) ----------------
// C[M,N] = As[m]*Ws[n] * (Aq1@Wq1^T + (Aq1@Wq2^T + Aq2@Wq1^T)/128) + bias
// EPI 0: -> split bf16 (qkv) ; EPI 1: gelu -> fp32 ; EPI 2: +R -> fp32
template <int EPI>
__global__ __launch_bounds__(512, 1) void gemm_i8(
    const int8_t* __restrict__ Aq1, const int8_t* __restrict__ Aq2,
    const float* __restrict__ As,
    const int8_t* __restrict__ Wq1, const int8_t* __restrict__ Wq2,
    const float* __restrict__ Ws,
    const float* __restrict__ bias, const float* __restrict__ R,
    float* __restrict__ C,
    __nv_bfloat16* __restrict__ Chi, __nv_bfloat16* __restrict__ Clo,
    int Ndim, int Kdim) {
    extern __shared__ char smem[];
    const unsigned sbase = smem_u32(smem);
    const int tid = threadIdx.x;
    const int lane = tid & 31;
    const int wid = tid >> 5;
    const int warp_m = wid & 3;          // 4 warp rows (32 M each)
    const int warp_n = wid >> 2;         // 4 warp cols (32 N each)
    const int bm = blockIdx.y * BM;
    const int bn = blockIdx.x * BN;
    const int NK = Kdim / BK;            // BK=64 int8

    // cp.async: 1 chunk of 16B per thread per tile (128 rows x 4 chunks = 512)
    const int r_ = tid >> 2, cc_ = tid & 3;
    const unsigned so = (unsigned)(r_ * RSB + cc_ * 16);

    auto issue_stage = [&](int st) {
        const unsigned sb = sbase + (unsigned)((st & 1) * STAGE_B);
        const int k0 = st * BK;
        size_t ao = (size_t)(bm + r_) * Kdim + k0 + 16 * cc_;
        size_t bo = (size_t)(bn + r_) * Kdim + k0 + 16 * cc_;
        cp16(sb + so,              Aq1 + ao);
        cp16(sb + TILE_B + so,     Aq2 + ao);
        cp16(sb + 2 * TILE_B + so, Wq1 + bo);
        cp16(sb + 3 * TILE_B + so, Wq2 + bo);
        cp_commit();
    };

    const unsigned a_base = (unsigned)((warp_m * 32 + (lane & 15)) * RSB + (lane >> 4) * 16);
    const unsigned b_row = (unsigned)(warp_n * 32 + (lane & 7) + ((lane >> 4) << 3));
    const unsigned b_base = (unsigned)(b_row * RSB + (((lane >> 3) & 1) * 16));

    int acc1[2][4][4], acc2[2][4][4];
    #pragma unroll
    for (int mt = 0; mt < 2; mt++)
        #pragma unroll
        for (int nt = 0; nt < 4; nt++)
            #pragma unroll
            for (int r = 0; r < 4; r++) { acc1[mt][nt][r] = 0; acc2[mt][nt][r] = 0; }

    issue_stage(0);

    for (int i = 0; i < NK; i++) {
        cp_wait<0>();
        __syncthreads();
        if (i + 1 < NK) issue_stage(i + 1);

        const unsigned tA1 = sbase + (unsigned)((i & 1) * STAGE_B);
        const unsigned tA2 = tA1 + TILE_B;
        const unsigned tB1 = tA2 + TILE_B;
        const unsigned tB2 = tB1 + TILE_B;

        #pragma unroll
        for (int ks = 0; ks < 2; ks++) {   // each ks covers 32 int8 of K
            unsigned fb1[2][4], fb2[2][4];
            #pragma unroll
            for (int pr = 0; pr < 2; pr++) {
                unsigned bo = b_base + (unsigned)(pr * 16 * RSB + ks * 32);
                ldsm_x4(fb1[pr], tB1 + bo);
                ldsm_x4(fb2[pr], tB2 + bo);
            }
            #pragma unroll
            for (int mt = 0; mt < 2; mt++) {
                unsigned fa1[4], fa2[4];
                unsigned ao = a_base + (unsigned)(mt * 16 * RSB + ks * 32);
                ldsm_x4(fa1, tA1 + ao);
                ldsm_x4(fa2, tA2 + ao);
                #pragma unroll
                for (int nt = 0; nt < 4; nt++) {
                    const unsigned* b1p = &fb1[nt >> 1][(nt & 1) * 2];
                    const unsigned* b2p = &fb2[nt >> 1][(nt & 1) * 2];
                    mma_s8(acc1[mt][nt], fa1, b1p);
                    mma_s8(acc2[mt][nt], fa1, b2p);
                    mma_s8(acc2[mt][nt], fa2, b1p);
                }
            }
        }
    }

    // ---- epilogue ----
    const int g = lane >> 2, tg = lane & 3;
    #pragma unroll
    for (int mt = 0; mt < 2; mt++) {
        int row0 = bm + warp_m * 32 + mt * 16 + g;
        float sa0 = As[row0];
        float sa1 = As[row0 + 8];
        #pragma unroll
        for (int nt = 0; nt < 4; nt++) {
            int col = bn + warp_n * 32 + nt * 8 + tg * 2;
            float2 bv = *(const float2*)(bias + col);
            float2 sw = *(const float2*)(Ws + col);
            float c0 = sa0 * sw.x * ((float)acc1[mt][nt][0] + (float)acc2[mt][nt][0] * 0.0078125f) + bv.x;
            float c1 = sa0 * sw.y * ((float)acc1[mt][nt][1] + (float)acc2[mt][nt][1] * 0.0078125f) + bv.y;
            float c2 = sa1 * sw.x * ((float)acc1[mt][nt][2] + (float)acc2[mt][nt][2] * 0.0078125f) + bv.x;
            float c3 = sa1 * sw.y * ((float)acc1[mt][nt][3] + (float)acc2[mt][nt][3] * 0.0078125f) + bv.y;
            size_t o0 = (size_t)row0 * Ndim + col;
            size_t o1 = o0 + (size_t)8 * Ndim;
            if (EPI == 0) {
                __nv_bfloat16 h0, l0v, h1, l1v, h2, l2v, h3, l3v;
                split2(c0, h0, l0v); split2(c1, h1, l1v);
                split2(c2, h2, l2v); split2(c3, h3, l3v);
                *(unsigned*)(Chi + o0) = pack_bf2(h0, h1);
                *(unsigned*)(Clo + o0) = pack_bf2(l0v, l1v);
                *(unsigned*)(Chi + o1) = pack_bf2(h2, h3);
                *(unsigned*)(Clo + o1) = pack_bf2(l2v, l3v);
            } else if (EPI == 1) {
                *(float2*)(C + o0) = make_float2(gelu_tanh(c0), gelu_tanh(c1));
                *(float2*)(C + o1) = make_float2(gelu_tanh(c2), gelu_tanh(c3));
            } else {
                float2 r0 = *(const float2*)(R + o0);
                float2 r1 = *(const float2*)(R + o1);
                *(float2*)(C + o0) = make_float2(c0 + r0.x, c1 + r0.y);
                *(float2*)(C + o1) = make_float2(c2 + r1.x, c3 + r1.y);
            }
        }
    }
}

// ---------------- tensor-core flash attention (split bf16, fp32 out) ----------------
__global__ __launch_bounds__(128) void attn_mma(
    const __nv_bfloat16* __restrict__ qh_, const __nv_bfloat16* __restrict__ ql_,
    float* __restrict__ out_) {
    extern __shared__ char smem[];
    __nv_bfloat16* sb = (__nv_bfloat16*)smem;
    int* kcode = (int*)(smem + AT_CODE_B);
    const unsigned sbase = smem_u32(smem);
    const int h = blockIdx.y, b = blockIdx.z;
    const int q0 = blockIdx.x * 64;
    const int tid = threadIdx.x;
    const int lane = tid & 31;
    const int warp = tid >> 5;
    const int tg2 = (lane & 3) * 2;

    for (int idx = tid; idx < 64 * 8; idx += 128) {
        int r = idx >> 3, c = idx & 7;
        int gr = min(q0 + r, T_ - 1);
        size_t src = ((size_t)(b * T_ + gr)) * (3 * D_) + h * HD_ + c * 8;
        *(uint4*)&sb[AT_QH + r * ARS + c * 8] = *(const uint4*)(qh_ + src);
        *(uint4*)&sb[AT_QL + r * ARS + c * 8] = *(const uint4*)(ql_ + src);
    }
    __syncthreads();

    unsigned qfh[4][4], qfl[4][4];
    {
        unsigned rowoff = (unsigned)((warp * 16 + (lane & 15)) * (ARS * 2)) + (lane >> 4) * 16;
        #pragma unroll
        for (int ks = 0; ks < 4; ks++) {
            ldsm_x4(qfh[ks], sbase + AT_QH * 2 + rowoff + ks * 32);
            ldsm_x4(qfl[ks], sbase + AT_QL * 2 + rowoff + ks * 32);
        }
    }

    const int r0 = q0 + warp * 16 + (lane >> 2);
    const int r1 = r0 + 8;
    const int rc0 = min(r0, T_ - 1), rc1 = min(r1, T_ - 1);
    const int gq0 = tok_group(rc0), tq0 = tok_ts(rc0);
    const int gq1 = tok_group(rc1), tq1 = tok_ts(rc1);

    float m0 = -1e30f, m1 = -1e30f, l0 = 0.0f, l1 = 0.0f;
    float o[8][4];
    #pragma unroll
    for (int nt = 0; nt < 8; nt++)
        #pragma unroll
        for (int r = 0; r < 4; r++) o[nt][r] = 0.0f;

    const int rlast = min(q0 + 63, T_ - 1);
    const int kmax = P_ + (tok_ts(rlast) + 1) * TPS;

    const unsigned kb = (unsigned)(((lane & 7) + ((lane >> 4) << 3)) * (ARS * 2)) +
                        ((lane >> 3) & 1) * 16;

    for (int k0 = 0; k0 < kmax; k0 += 64) {
        __syncthreads();
        for (int idx = tid; idx < 64 * 8; idx += 128) {
            int r = idx >> 3, c = idx & 7;
            int kr = k0 + r;
            uint4 z = make_uint4(0, 0, 0, 0);
            uint4 kvh = z, kvl = z, vvh = z, vvl = z;
            if (kr < T_) {
                size_t src = ((size_t)(b * T_ + kr)) * (3 * D_) + D_ + h * HD_ + c * 8;
                kvh = *(const uint4*)(qh_ + src);
                kvl = *(const uint4*)(ql_ + src);
                vvh = *(const uint4*)(qh_ + src + D_);
                vvl = *(const uint4*)(ql_ + src + D_);
            }
            *(uint4*)&sb[AT_KH + r * ARS + c * 8] = kvh;
            *(uint4*)&sb[AT_KL + r * ARS + c * 8] = kvl;
            *(uint4*)&sb[AT_VH + r * ARS + c * 8] = vvh;
            *(uint4*)&sb[AT_VL + r * ARS + c * 8] = vvl;
        }
        if (tid < 64) {
            int kg = k0 + tid;
            kcode[tid] = (kg < kmax && kg < T_)
                       ? ((tok_ts(kg) << 2) | tok_group(kg))
                       : ((0x3FFF << 2) | 3);
        }
        __syncthreads();

        float s[8][4];
        #pragma unroll
        for (int nt = 0; nt < 8; nt++)
            #pragma unroll
            for (int r = 0; r < 4; r++) s[nt][r] = 0.0f;

        #pragma unroll
        for (int kg = 0; kg < 4; kg++) {
            #pragma unroll
            for (int ks = 0; ks < 4; ks++) {
                unsigned kh[4], kl[4];
                unsigned addr = sbase + kb + (unsigned)(kg * 16 * (ARS * 2)) + ks * 32;
                ldsm_x4(kh, addr + AT_KH * 2);
                ldsm_x4(kl, addr + AT_KL * 2);
                #pragma unroll
                for (int half = 0; half < 2; half++) {
                    int nt = kg * 2 + half;
                    mma_bf16(s[nt], qfh[ks], &kh[half * 2]);
                    mma_bf16(s[nt], qfh[ks], &kl[half * 2]);
                    mma_bf16(s[nt], qfl[ks], &kh[half * 2]);
                }
            }
        }

        #pragma unroll
        for (int nt = 0; nt < 8; nt++) {
            int kc0 = kcode[nt * 8 + tg2];
            int kc1 = kcode[nt * 8 + tg2 + 1];
            s[nt][0] = allow_code(gq0, tq0, kc0) ? s[nt][0] * ATT_SCALE : -1e30f;
            s[nt][1] = allow_code(gq0, tq0, kc1) ? s[nt][1] * ATT_SCALE : -1e30f;
            s[nt][2] = allow_code(gq1, tq1, kc0) ? s[nt][2] * ATT_SCALE : -1e30f;
            s[nt][3] = allow_code(gq1, tq1, kc1) ? s[nt][3] * ATT_SCALE : -1e30f;
        }

        float mx0 = -1e30f, mx1 = -1e30f;
        #pragma unroll
        for (int nt = 0; nt < 8; nt++) {
            mx0 = fmaxf(mx0, fmaxf(s[nt][0], s[nt][1]));
            mx1 = fmaxf(mx1, fmaxf(s[nt][2], s[nt][3]));
        }
        mx0 = fmaxf(mx0, __shfl_xor_sync(0xffffffffu, mx0, 1));
        mx0 = fmaxf(mx0, __shfl_xor_sync(0xffffffffu, mx0, 2));
        mx1 = fmaxf(mx1, __shfl_xor_sync(0xffffffffu, mx1, 1));
        mx1 = fmaxf(mx1, __shfl_xor_sync(0xffffffffu, mx1, 2));
        float mn0 = fmaxf(m0, mx0), mn1 = fmaxf(m1, mx1);
        float corr0 = __expf(m0 - mn0), corr1 = __expf(m1 - mn1);
        m0 = mn0; m1 = mn1;
        l0 *= corr0; l1 *= corr1;
        #pragma unroll
        for (int nt = 0; nt < 8; nt++) {
            o[nt][0] *= corr0; o[nt][1] *= corr0;
            o[nt][2] *= corr1; o[nt][3] *= corr1;
        }

        #pragma unroll
        for (int kv = 0; kv < 4; kv++) {
            unsigned ph[4], pl[4];
            #pragma unroll
            for (int half = 0; half < 2; half++) {
                int nt = kv * 2 + half;
                float p0 = __expf(s[nt][0] - m0);
                float p1 = __expf(s[nt][1] - m0);
                float p2 = __expf(s[nt][2] - m1);
                float p3 = __expf(s[nt][3] - m1);
                l0 += p0 + p1;
                l1 += p2 + p3;
                __nv_bfloat16 h0, lo0, h1, lo1, h2, lo2, h3, lo3;
                split2(p0, h0, lo0); split2(p1, h1, lo1);
                split2(p2, h2, lo2); split2(p3, h3, lo3);
                ph[half * 2 + 0] = pack_bf2(h0, h1);
                ph[half * 2 + 1] = pack_bf2(h2, h3);
                pl[half * 2 + 0] = pack_bf2(lo0, lo1);
                pl[half * 2 + 1] = pack_bf2(lo2, lo3);
            }
            #pragma unroll
            for (int dg = 0; dg < 4; dg++) {
                unsigned vh[4], vl[4];
                unsigned addr = sbase + kb + (unsigned)(kv * 16 * (ARS * 2)) + dg * 32;
                ldsm_x4t(vh, addr + AT_VH * 2);
                ldsm_x4t(vl, addr + AT_VL * 2);
                #pragma unroll
                for (int half = 0; half < 2; half++) {
                    int nt = dg * 2 + half;
                    unsigned bhp[2] = {vh[half], vh[2 + half]};
                    unsigned blp[2] = {vl[half], vl[2 + half]};
                    mma_bf16(o[nt], ph, bhp);
                    mma_bf16(o[nt], ph, blp);
                    mma_bf16(o[nt], pl, bhp);
                }
            }
        }
    }

    l0 += __shfl_xor_sync(0xffffffffu, l0, 1);
    l0 += __shfl_xor_sync(0xffffffffu, l0, 2);
    l1 += __shfl_xor_sync(0xffffffffu, l1, 1);
    l1 += __shfl_xor_sync(0xffffffffu, l1, 2);
    float li0 = 1.0f / l0, li1 = 1.0f / l1;

    #pragma unroll
    for (int nt = 0; nt < 8; nt++) {
        int d = h * HD_ + nt * 8 + tg2;
        if (r0 < T_) {
            size_t off = ((size_t)(b * T_ + r0)) * D_ + d;
            *(float2*)(out_ + off) = make_float2(o[nt][0] * li0, o[nt][1] * li0);
        }
        if (r1 < T_) {
            size_t off = ((size_t)(b * T_ + r1)) * D_ + d;
            *(float2*)(out_ + off) = make_float2(o[nt][2] * li1, o[nt][3] * li1);
        }
    }
}

// ---------------- host orchestration ----------------
extern "C" void kernel_launch(void* const* d_in, const int* in_sizes, int n_in,
                              void* d_out, int out_size) {
    (void)in_sizes; (void)n_in; (void)out_size;

    const float* prefix = (const float*)d_in[0];
    const float* obs    = (const float*)d_in[2];
    const float* rdo    = (const float*)d_in[4];
    const float* ln1_s  = (const float*)d_in[6];
    const float* ln1_b  = (const float*)d_in[7];
    const float* wqkv   = (const float*)d_in[8];
    const float* bqkv   = (const float*)d_in[9];
    const float* wo     = (const float*)d_in[10];
    const float* bo     = (const float*)d_in[11];
    const float* ln2_s  = (const float*)d_in[12];
    const float* ln2_b  = (const float*)d_in[13];
    const float* w1     = (const float*)d_in[14];
    const float* b1     = (const float*)d_in[15];
    const float* w2     = (const float*)d_in[16];
    const float* b2     = (const float*)d_in[17];
    const float* lnf_s  = (const float*)d_in[18];
    const float* lnf_b  = (const float*)d_in[19];
    float* out = (float*)d_out;

    float *x, *att, *ffn;
    int8_t *yq1, *yq2, *aq1, *aq2, *fq1, *fq2;
    float *ysc, *asc, *fsc;
    __nv_bfloat16 *qkvhi, *qkvlo;
    int8_t *wq_qkv1, *wq_qkv2, *wq_o1, *wq_o2, *wq_11, *wq_12, *wq_21, *wq_22;
    float *ws_qkv, *ws_o, *ws_1, *ws_2;
    cudaGetSymbolAddress((void**)&x,     g_x);
    cudaGetSymbolAddress((void**)&att,   g_att);
    cudaGetSymbolAddress((void**)&ffn,   g_ffn);
    cudaGetSymbolAddress((void**)&yq1,   g_yq1);
    cudaGetSymbolAddress((void**)&yq2,   g_yq2);
    cudaGetSymbolAddress((void**)&ysc,   g_ysc);
    cudaGetSymbolAddress((void**)&aq1,   g_aq1);
    cudaGetSymbolAddress((void**)&aq2,   g_aq2);
    cudaGetSymbolAddress((void**)&asc,   g_asc);
    cudaGetSymbolAddress((void**)&fq1,   g_fq1);
    cudaGetSymbolAddress((void**)&fq2,   g_fq2);
    cudaGetSymbolAddress((void**)&fsc,   g_fsc);
    cudaGetSymbolAddress((void**)&qkvhi, g_qkv_hi);
    cudaGetSymbolAddress((void**)&qkvlo, g_qkv_lo);
    cudaGetSymbolAddress((void**)&wq_qkv1, g_wqkv_q1);
    cudaGetSymbolAddress((void**)&wq_qkv2, g_wqkv_q2);
    cudaGetSymbolAddress((void**)&ws_qkv,  g_wqkv_sc);
    cudaGetSymbolAddress((void**)&wq_o1,   g_wo_q1);
    cudaGetSymbolAddress((void**)&wq_o2,   g_wo_q2);
    cudaGetSymbolAddress((void**)&ws_o,    g_wo_sc);
    cudaGetSymbolAddress((void**)&wq_11,   g_w1_q1);
    cudaGetSymbolAddress((void**)&wq_12,   g_w1_q2);
    cudaGetSymbolAddress((void**)&ws_1,    g_w1_sc);
    cudaGetSymbolAddress((void**)&wq_21,   g_w2_q1);
    cudaGetSymbolAddress((void**)&wq_22,   g_w2_q2);
    cudaGetSymbolAddress((void**)&ws_2,    g_w2_sc);

    cudaFuncSetAttribute(gemm_i8<0>, cudaFuncAttributeMaxDynamicSharedMemorySize, SMEM_GEMM);
    cudaFuncSetAttribute(gemm_i8<1>, cudaFuncAttributeMaxDynamicSharedMemorySize, SMEM_GEMM);
    cudaFuncSetAttribute(gemm_i8<2>, cudaFuncAttributeMaxDynamicSharedMemorySize, SMEM_GEMM);
    cudaFuncSetAttribute(attn_mma, cudaFuncAttributeMaxDynamicSharedMemorySize, ATTN_SMEM);

    assemble_kernel<<<2048, 256>>>(prefix, obs, rdo);

    // ---- weight quantization (setup) ----
    const dim3 tb(32, 8);
    wabsmax_kernel<<<dim3((3 * D_ + 255) / 256, L_), 256>>>(wqkv, ws_qkv, D_, 3 * D_);
    wabsmax_kernel<<<dim3((D_ + 255) / 256, L_), 256>>>(wo, ws_o, D_, D_);
    wabsmax_kernel<<<dim3((F_ + 255) / 256, L_), 256>>>(w1, ws_1, D_, F_);
    wabsmax_kernel<<<dim3((D_ + 255) / 256, L_), 256>>>(w2, ws_2, F_, D_);
    wquant_kernel<<<dim3((3 * D_ / 32) * (D_ / 32), L_), tb>>>(wqkv, wq_qkv1, wq_qkv2, ws_qkv, D_, 3 * D_);
    wquant_kernel<<<dim3((D_ / 32) * (D_ / 32), L_), tb>>>(wo, wq_o1, wq_o2, ws_o, D_, D_);
    wquant_kernel<<<dim3((F_ / 32) * (D_ / 32), L_), tb>>>(w1, wq_11, wq_12, ws_1, D_, F_);
    wquant_kernel<<<dim3((D_ / 32) * (F_ / 32), L_), tb>>>(w2, wq_21, wq_22, ws_2, F_, D_);

    const dim3 g_qkv_grid(3 * D_ / BN, M_ / BM);   // (18, 86)
    const dim3 g_wo_grid (D_ / BN,     M_ / BM);   // (6, 86)
    const dim3 g_w1_grid (F_ / BN,     M_ / BM);   // (24, 86)
    const dim3 g_attn((T_ + 63) / 64, NH_, B_);    // (22, 12, 8)

    for (int l = 0; l < L_; l++) {
        ln_quant_kernel<<<M_, 256>>>(x, ln1_s + (size_t)l * D_, ln1_b + (size_t)l * D_,
                                     yq1, yq2, ysc);
        gemm_i8<0><<<g_qkv_grid, 512, SMEM_GEMM>>>(
            yq1, yq2, ysc,
            wq_qkv1 + (size_t)l * 3 * D_ * D_, wq_qkv2 + (size_t)l * 3 * D_ * D_,
            ws_qkv + (size_t)l * 3 * D_,
            bqkv + (size_t)l * 3 * D_, nullptr, nullptr, qkvhi, qkvlo, 3 * D_, D_);
        attn_mma<<<g_attn, 128, ATTN_SMEM>>>(qkvhi, qkvlo, att);
        quant_rows_kernel<<<M_, 256>>>(att, aq1, aq2, asc, D_);
        gemm_i8<2><<<g_wo_grid, 512, SMEM_GEMM>>>(
            aq1, aq2, asc,
            wq_o1 + (size_t)l * D_ * D_, wq_o2 + (size_t)l * D_ * D_,
            ws_o + (size_t)l * D_,
            bo + (size_t)l * D_, x, x, nullptr, nullptr, D_, D_);
        ln_quant_kernel<<<M_, 256>>>(x, ln2_s + (size_t)l * D_, ln2_b + (size_t)l * D_,
                                     yq1, yq2, ysc);
        gemm_i8<1><<<g_w1_grid, 512, SMEM_GEMM>>>(
            yq1, yq2, ysc,
            wq_11 + (size_t)l * F_ * D_, wq_12 + (size_t)l * F_ * D_,
            ws_1 + (size_t)l * F_,
            b1 + (size_t)l * F_, nullptr, ffn, nullptr, nullptr, F_, D_);
        quant_rows_kernel<<<M_, 256>>>(ffn, fq1, fq2, fsc, F_);
        gemm_i8<2><<<g_wo_grid, 512, SMEM_GEMM>>>(
            fq1, fq2, fsc,
            wq_21 + (size_t)l * D_ * F_, wq_22 + (size_t)l * D_ * F_,
            ws_2 + (size_t)l * D_,
            b2 + (size_t)l * D_, x, x, nullptr, nullptr, D_, F_);
    }

    ln_kernel<<<M_, 256>>>(x, lnf_s, lnf_b, out);
}

// round 11
// speedup vs baseline: 2.0184x; 1.9812x over previous
#include <cuda_runtime.h>
#include <cuda_bf16.h>
#include <cuda_fp16.h>
#include <math.h>
#include <stdint.h>

// ---------------- problem constants ----------------
namespace {
constexpr int B_  = 8;
constexpr int P_  = 16;
constexpr int HOR = 10;
constexpr int NO_ = 128;
constexpr int NR_ = 8;
constexpr int D_  = 768;
constexpr int NH_ = 12;
constexpr int HD_ = 64;
constexpr int F_  = 3072;
constexpr int L_  = 12;
constexpr int TPS = NO_ + NR_;          // 136
constexpr int T_  = P_ + HOR * TPS;     // 1376
constexpr int M_  = B_ * T_;            // 11008
constexpr float LN_EPS = 1e-6f;
constexpr float ATT_SCALE = 0.125f;     // 1/sqrt(64)

// GEMM tiling (fp16 split, f16-acc corrections): 256 thr, 2x4 warps, BK=32, 2-stage
constexpr int BM = 128;
constexpr int BN = 128;
constexpr int BK = 32;
constexpr int RS = 40;                   // SMEM row stride in fp16 (80B), conflict-free ldmatrix
constexpr int TILE_B = 128 * RS * 2;     // 10240 bytes per operand tile
constexpr int STAGE_B = 4 * TILE_B;      // Ah,Al,Bh,Bl = 40960
constexpr int SMEM_GEMM = 2 * STAGE_B;   // 81920

// attention smem layout (bf16 units unless noted)
constexpr int ARS   = 72;                // 144B row stride, conflict-free
constexpr int AT_QH = 0;
constexpr int AT_QL = 1 * 64 * ARS;
constexpr int AT_KH = 2 * 64 * ARS;
constexpr int AT_KL = 3 * 64 * ARS;
constexpr int AT_VH = 4 * 64 * ARS;
constexpr int AT_VL = 5 * 64 * ARS;
constexpr int AT_CODE_B = 6 * 64 * ARS * 2;
constexpr int ATTN_SMEM = AT_CODE_B + 64 * 4;   // 55552 bytes
}

// ---------------- scratch (device globals: no cudaMalloc allowed) ----------------
__device__ float g_x[(size_t)M_ * D_];
// fp16-split activations
__device__ __half g_y_hi  [(size_t)M_ * D_];
__device__ __half g_y_lo  [(size_t)M_ * D_];
__device__ __half g_att_hi[(size_t)M_ * D_];
__device__ __half g_att_lo[(size_t)M_ * D_];
__device__ __half g_ffn_hi[(size_t)M_ * F_];
__device__ __half g_ffn_lo[(size_t)M_ * F_];
// qkv stays bf16 split (consumed by attention)
__device__ __nv_bfloat16 g_qkv_hi[(size_t)M_ * 3 * D_];
__device__ __nv_bfloat16 g_qkv_lo[(size_t)M_ * 3 * D_];
// fp16-split transposed weights [N, K]
__device__ __half g_wqkvT_hi[(size_t)L_ * 3 * D_ * D_];
__device__ __half g_wqkvT_lo[(size_t)L_ * 3 * D_ * D_];
__device__ __half g_woT_hi  [(size_t)L_ * D_ * D_];
__device__ __half g_woT_lo  [(size_t)L_ * D_ * D_];
__device__ __half g_w1T_hi  [(size_t)L_ * F_ * D_];
__device__ __half g_w1T_lo  [(size_t)L_ * F_ * D_];
__device__ __half g_w2T_hi  [(size_t)L_ * D_ * F_];
__device__ __half g_w2T_lo  [(size_t)L_ * D_ * F_];

// ---------------- mma / async helpers ----------------
__device__ __forceinline__ unsigned smem_u32(const void* p) {
    return (unsigned)__cvta_generic_to_shared(p);
}
__device__ __forceinline__ void ldsm_x4(unsigned* r, unsigned addr) {
    asm volatile("ldmatrix.sync.aligned.m8n8.x4.shared.b16 {%0,%1,%2,%3}, [%4];"
                 : "=r"(r[0]), "=r"(r[1]), "=r"(r[2]), "=r"(r[3]) : "r"(addr));
}
__device__ __forceinline__ void ldsm_x4t(unsigned* r, unsigned addr) {
    asm volatile("ldmatrix.sync.aligned.m8n8.x4.trans.shared.b16 {%0,%1,%2,%3}, [%4];"
                 : "=r"(r[0]), "=r"(r[1]), "=r"(r[2]), "=r"(r[3]) : "r"(addr));
}
__device__ __forceinline__ void mma_bf16(float* c, const unsigned* a, const unsigned* b) {
    asm volatile(
        "mma.sync.aligned.m16n8k16.row.col.f32.bf16.bf16.f32 "
        "{%0,%1,%2,%3}, {%4,%5,%6,%7}, {%8,%9}, {%0,%1,%2,%3};"
        : "+f"(c[0]), "+f"(c[1]), "+f"(c[2]), "+f"(c[3])
        : "r"(a[0]), "r"(a[1]), "r"(a[2]), "r"(a[3]), "r"(b[0]), "r"(b[1]));
}
// fp16 inputs, f32 accumulators
__device__ __forceinline__ void mma_f16f32(float* c, const unsigned* a, const unsigned* b) {
    asm volatile(
        "mma.sync.aligned.m16n8k16.row.col.f32.f16.f16.f32 "
        "{%0,%1,%2,%3}, {%4,%5,%6,%7}, {%8,%9}, {%0,%1,%2,%3};"
        : "+f"(c[0]), "+f"(c[1]), "+f"(c[2]), "+f"(c[3])
        : "r"(a[0]), "r"(a[1]), "r"(a[2]), "r"(a[3]), "r"(b[0]), "r"(b[1]));
}
// fp16 inputs, f16 accumulators (2 packed regs) — the double-rate hypothesis path
__device__ __forceinline__ void mma_f16f16(unsigned* c, const unsigned* a, const unsigned* b) {
    asm volatile(
        "mma.sync.aligned.m16n8k16.row.col.f16.f16.f16.f16 "
        "{%0,%1}, {%2,%3,%4,%5}, {%6,%7}, {%0,%1};"
        : "+r"(c[0]), "+r"(c[1])
        : "r"(a[0]), "r"(a[1]), "r"(a[2]), "r"(a[3]), "r"(b[0]), "r"(b[1]));
}
__device__ __forceinline__ void cp16(unsigned saddr, const void* g) {
    asm volatile("cp.async.cg.shared.global [%0], [%1], 16;" :: "r"(saddr), "l"(g));
}
__device__ __forceinline__ void cp_commit() {
    asm volatile("cp.async.commit_group;" ::: "memory");
}
template <int N>
__device__ __forceinline__ void cp_wait() {
    asm volatile("cp.async.wait_group %0;" :: "n"(N) : "memory");
}
__device__ __forceinline__ unsigned pack_bf2(__nv_bfloat16 a, __nv_bfloat16 b) {
    __nv_bfloat162 t(a, b);
    return *(unsigned*)&t;
}
__device__ __forceinline__ unsigned pack_h2(__half a, __half b) {
    __half2 t(a, b);
    return *(unsigned*)&t;
}
__device__ __forceinline__ void split2(float v, __nv_bfloat16& h, __nv_bfloat16& l) {
    h = __float2bfloat16(v);
    l = __float2bfloat16(v - __bfloat162float(h));
}
__device__ __forceinline__ void split2h(float v, __half& h, __half& l) {
    h = __float2half(v);
    l = __float2half(v - __half2float(h));
}

// ---------------- misc helpers ----------------
__device__ __forceinline__ float gelu_tanh(float x) {
    float x3 = x * x * x;
    return 0.5f * x * (1.0f + tanhf(0.7978845608028654f * (x + 0.044715f * x3)));
}
__device__ __forceinline__ int tok_group(int i) {
    if (i < P_) return 0;
    return (((i - P_) % TPS) < NO_) ? 1 : 2;
}
__device__ __forceinline__ int tok_ts(int i) {
    return (i < P_) ? -1 : (i - P_) / TPS;
}
__device__ __forceinline__ bool allow_code(int gq, int tq, int kc) {
    int gk = kc & 3;
    int tk = kc >> 2;
    if (gk == 0) return true;
    if (gq == 0) return false;
    if (tk > tq) return false;
    return (gk == 1) || (gq == 2);
}

// ---------------- assemble ----------------
__global__ void assemble_kernel(const float* __restrict__ prefix,
                                const float* __restrict__ obs,
                                const float* __restrict__ rdo) {
    for (int idx = blockIdx.x * blockDim.x + threadIdx.x;
         idx < M_ * D_; idx += gridDim.x * blockDim.x) {
        int d = idx % D_;
        int bt = idx / D_;
        int t = bt % T_;
        int b = bt / T_;
        float v;
        if (t < P_) {
            v = prefix[((size_t)b * P_ + t) * D_ + d];
        } else {
            int tt = t - P_;
            int ho = tt / TPS;
            int r  = tt % TPS;
            if (r < NO_)
                v = obs[(((size_t)b * HOR + ho) * NO_ + r) * D_ + d];
            else
                v = rdo[(((size_t)b * HOR + ho) * NR_ + (r - NO_)) * D_ + d];
        }
        g_x[idx] = v;
    }
}

// ---------------- fused weight transpose + fp16 split ----------------
__global__ void wsplit_all_kernel(const float* __restrict__ wqkv, const float* __restrict__ wo,
                                  const float* __restrict__ w1, const float* __restrict__ w2,
                                  __half* __restrict__ qh, __half* __restrict__ ql,
                                  __half* __restrict__ oh, __half* __restrict__ ol,
                                  __half* __restrict__ h1, __half* __restrict__ l1,
                                  __half* __restrict__ h2, __half* __restrict__ l2) {
    __shared__ float t[32][33];
    const int l = blockIdx.y;
    int bx = blockIdx.x;
    const float* src;
    __half *hiT, *loT;
    int R, C;
    if (bx < 1728) {
        src = wqkv + (size_t)l * D_ * 3 * D_;
        hiT = qh + (size_t)l * 3 * D_ * D_;  loT = ql + (size_t)l * 3 * D_ * D_;
        R = D_; C = 3 * D_;
    } else if (bx < 2304) {
        bx -= 1728;
        src = wo + (size_t)l * D_ * D_;
        hiT = oh + (size_t)l * D_ * D_;  loT = ol + (size_t)l * D_ * D_;
        R = D_; C = D_;
    } else if (bx < 4608) {
        bx -= 2304;
        src = w1 + (size_t)l * D_ * F_;
        hiT = h1 + (size_t)l * F_ * D_;  loT = l1 + (size_t)l * F_ * D_;
        R = D_; C = F_;
    } else {
        bx -= 4608;
        src = w2 + (size_t)l * F_ * D_;
        hiT = h2 + (size_t)l * D_ * F_;  loT = l2 + (size_t)l * D_ * F_;
        R = F_; C = D_;
    }
    const int cols = C / 32;
    const int cb = (bx % cols) * 32, rb = (bx / cols) * 32;
    const int tx = threadIdx.x, ty = threadIdx.y;
    #pragma unroll
    for (int i = 0; i < 32; i += 8)
        t[ty + i][tx] = src[(size_t)(rb + ty + i) * C + cb + tx];
    __syncthreads();
    #pragma unroll
    for (int i = 0; i < 32; i += 8) {
        float v = t[tx][ty + i];
        __half h, lo;
        split2h(v, h, lo);
        size_t o = (size_t)(cb + ty + i) * R + rb + tx;
        hiT[o] = h;
        loT[o] = lo;
    }
}

// ---------------- layernorm ----------------
__device__ __forceinline__ float block_reduce_sum(float v, float* red) {
    int lane = threadIdx.x & 31;
    int wid  = threadIdx.x >> 5;
    #pragma unroll
    for (int o = 16; o; o >>= 1) v += __shfl_down_sync(0xffffffffu, v, o);
    if (lane == 0) red[wid] = v;
    __syncthreads();
    if (threadIdx.x < 32) {
        float t = (threadIdx.x < 8) ? red[threadIdx.x] : 0.0f;
        #pragma unroll
        for (int o = 4; o; o >>= 1) t += __shfl_down_sync(0xffffffffu, t, o);
        if (threadIdx.x == 0) red[32] = t;
    }
    __syncthreads();
    return red[32];
}

__global__ void ln_kernel(const float* __restrict__ x,
                          const float* __restrict__ s,
                          const float* __restrict__ b,
                          float* __restrict__ y) {
    __shared__ float red[33];
    int row = blockIdx.x;
    const float* xp = x + (size_t)row * D_;
    float v0 = xp[threadIdx.x];
    float v1 = xp[threadIdx.x + 256];
    float v2 = xp[threadIdx.x + 512];
    float mu = block_reduce_sum(v0 + v1 + v2, red) * (1.0f / D_);
    float d0 = v0 - mu, d1 = v1 - mu, d2 = v2 - mu;
    float var = block_reduce_sum(d0 * d0 + d1 * d1 + d2 * d2, red) * (1.0f / D_);
    float inv = rsqrtf(var + LN_EPS);
    float* yp = y + (size_t)row * D_;
    yp[threadIdx.x      ] = d0 * inv * s[threadIdx.x      ] + b[threadIdx.x      ];
    yp[threadIdx.x + 256] = d1 * inv * s[threadIdx.x + 256] + b[threadIdx.x + 256];
    yp[threadIdx.x + 512] = d2 * inv * s[threadIdx.x + 512] + b[threadIdx.x + 512];
}

__global__ void ln_split_kernel(const float* __restrict__ x,
                                const float* __restrict__ s,
                                const float* __restrict__ b,
                                __half* __restrict__ yhi,
                                __half* __restrict__ ylo) {
    __shared__ float red[33];
    int row = blockIdx.x;
    const float* xp = x + (size_t)row * D_;
    float v0 = xp[threadIdx.x];
    float v1 = xp[threadIdx.x + 256];
    float v2 = xp[threadIdx.x + 512];
    float mu = block_reduce_sum(v0 + v1 + v2, red) * (1.0f / D_);
    float d0 = v0 - mu, d1 = v1 - mu, d2 = v2 - mu;
    float var = block_reduce_sum(d0 * d0 + d1 * d1 + d2 * d2, red) * (1.0f / D_);
    float inv = rsqrtf(var + LN_EPS);
    size_t base = (size_t)row * D_;
    #pragma unroll
    for (int i = 0; i < 3; i++) {
        int c = threadIdx.x + i * 256;
        float dv = (i == 0 ? d0 : (i == 1 ? d1 : d2));
        float v = dv * inv * s[c] + b[c];
        __half h, l;
        split2h(v, h, l);
        yhi[base + c] = h;
        ylo[base + c] = l;
    }
}

// ---------------- fp16-split warp-mma GEMM (f16-acc corrections) ----------------
// C[M,N] = (Ah+Al)[M,K] @ (Wh+Wl)[N,K]^T + bias
//   hh term -> f32 acc ; hl + lh terms -> shared f16 acc (double-rate hypothesis)
// EPI 0: write split bf16 (qkv) ; EPI 1: gelu -> split fp16 ; EPI 2: +R -> fp32
template <int EPI>
__global__ __launch_bounds__(256, 1) void wmma_gemm(
    const __half* __restrict__ Ahi, const __half* __restrict__ Alo,
    const __half* __restrict__ Whi, const __half* __restrict__ Wlo,
    const float* __restrict__ bias, const float* __restrict__ R,
    float* __restrict__ C,
    __nv_bfloat16* __restrict__ Cbh, __nv_bfloat16* __restrict__ Cbl,
    __half* __restrict__ Chh, __half* __restrict__ Chl,
    int Ndim, int Kdim) {
    extern __shared__ char smem[];
    const unsigned sbase = smem_u32(smem);
    const int tid = threadIdx.x;
    const int lane = tid & 31;
    const int wid = tid >> 5;
    const int warp_m = wid & 1;          // 2 warp rows (64 M each)
    const int warp_n = wid >> 1;         // 4 warp cols (32 N each)
    const int bm = blockIdx.y * BM;
    const int bn = blockIdx.x * BN;
    const int NK = Kdim / BK;

    // cp.async mapping: 2 chunks per tile (128 rows x 32 fp16)
    const int r_ = tid >> 2, cc_ = tid & 3;
    const int r2_ = r_ + 64;
    const unsigned so1 = (unsigned)(r_ * (RS * 2) + cc_ * 16);
    const unsigned so2 = (unsigned)(r2_ * (RS * 2) + cc_ * 16);

    auto issue_stage = [&](int st) {
        const unsigned sb = sbase + (unsigned)((st & 1) * STAGE_B);
        const int k0 = st * BK;
        size_t a1 = (size_t)(bm + r_)  * Kdim + k0 + 8 * cc_;
        size_t a2 = (size_t)(bm + r2_) * Kdim + k0 + 8 * cc_;
        size_t b1 = (size_t)(bn + r_)  * Kdim + k0 + 8 * cc_;
        size_t b2 = (size_t)(bn + r2_) * Kdim + k0 + 8 * cc_;
        cp16(sb + so1,              Ahi + a1);
        cp16(sb + so2,              Ahi + a2);
        cp16(sb + TILE_B + so1,     Alo + a1);
        cp16(sb + TILE_B + so2,     Alo + a2);
        cp16(sb + 2 * TILE_B + so1, Whi + b1);
        cp16(sb + 2 * TILE_B + so2, Whi + b2);
        cp16(sb + 3 * TILE_B + so1, Wlo + b1);
        cp16(sb + 3 * TILE_B + so2, Wlo + b2);
        cp_commit();
    };

    const unsigned a_base = (unsigned)((warp_m * 64 + (lane & 15)) * (RS * 2) + (lane >> 4) * 16);
    const unsigned b_row = (unsigned)(warp_n * 32 + (lane & 7) + ((lane >> 4) << 3));
    const unsigned b_base = (unsigned)(b_row * (RS * 2) + (((lane >> 3) & 1) * 16));

    float acc[4][4][4];        // hi*hi, f32 acc
    unsigned accc[4][4][2];    // corrections, f16 acc (packed pairs)
    #pragma unroll
    for (int mt = 0; mt < 4; mt++)
        #pragma unroll
        for (int nt = 0; nt < 4; nt++) {
            #pragma unroll
            for (int r = 0; r < 4; r++) acc[mt][nt][r] = 0.0f;
            accc[mt][nt][0] = 0u;
            accc[mt][nt][1] = 0u;
        }

    issue_stage(0);

    for (int i = 0; i < NK; i++) {
        cp_wait<0>();
        __syncthreads();
        if (i + 1 < NK) issue_stage(i + 1);

        const unsigned tAhi = sbase + (unsigned)((i & 1) * STAGE_B);
        const unsigned tAlo = tAhi + TILE_B;
        const unsigned tBhi = tAlo + TILE_B;
        const unsigned tBlo = tBhi + TILE_B;

        #pragma unroll
        for (int ks = 0; ks < 2; ks++) {
            unsigned fbh[2][4], fbl[2][4];
            #pragma unroll
            for (int pr = 0; pr < 2; pr++) {
                unsigned bo = b_base + (unsigned)(pr * 16 * (RS * 2) + ks * 32);
                ldsm_x4(fbh[pr], tBhi + bo);
                ldsm_x4(fbl[pr], tBlo + bo);
            }
            #pragma unroll
            for (int mt = 0; mt < 4; mt++) {
                unsigned fah[4], fal[4];
                unsigned ao = a_base + (unsigned)(mt * 16 * (RS * 2) + ks * 32);
                ldsm_x4(fah, tAhi + ao);
                ldsm_x4(fal, tAlo + ao);
                #pragma unroll
                for (int nt = 0; nt < 4; nt++) {
                    const unsigned* bH = &fbh[nt >> 1][(nt & 1) * 2];
                    const unsigned* bL = &fbl[nt >> 1][(nt & 1) * 2];
                    mma_f16f32(acc[mt][nt], fah, bH);
                    mma_f16f16(accc[mt][nt], fah, bL);
                    mma_f16f16(accc[mt][nt], fal, bH);
                }
            }
        }
        __syncthreads();
    }

    // ---- epilogue ----
    const int g = lane >> 2, tg = lane & 3;
    #pragma unroll
    for (int mt = 0; mt < 4; mt++) {
        #pragma unroll
        for (int nt = 0; nt < 4; nt++) {
            int row0 = bm + warp_m * 64 + mt * 16 + g;
            int col  = bn + warp_n * 32 + nt * 8 + tg * 2;
            float2 bv = *(const float2*)(bias + col);
            __half2 cp0 = *(__half2*)&accc[mt][nt][0];   // corrections row g
            __half2 cp1 = *(__half2*)&accc[mt][nt][1];   // corrections row g+8
            float c0 = acc[mt][nt][0] + __half2float(cp0.x) + bv.x;
            float c1 = acc[mt][nt][1] + __half2float(cp0.y) + bv.y;
            float c2 = acc[mt][nt][2] + __half2float(cp1.x) + bv.x;
            float c3 = acc[mt][nt][3] + __half2float(cp1.y) + bv.y;
            size_t o0 = (size_t)row0 * Ndim + col;
            size_t o1 = o0 + (size_t)8 * Ndim;
            if (EPI == 2) {
                float2 r0 = *(const float2*)(R + o0);
                float2 r1 = *(const float2*)(R + o1);
                *(float2*)(C + o0) = make_float2(c0 + r0.x, c1 + r0.y);
                *(float2*)(C + o1) = make_float2(c2 + r1.x, c3 + r1.y);
            } else if (EPI == 0) {
                __nv_bfloat16 h0, l0v, h1, l1v, h2, l2v, h3, l3v;
                split2(c0, h0, l0v); split2(c1, h1, l1v);
                split2(c2, h2, l2v); split2(c3, h3, l3v);
                *(unsigned*)(Cbh + o0) = pack_bf2(h0, h1);
                *(unsigned*)(Cbl + o0) = pack_bf2(l0v, l1v);
                *(unsigned*)(Cbh + o1) = pack_bf2(h2, h3);
                *(unsigned*)(Cbl + o1) = pack_bf2(l2v, l3v);
            } else {
                c0 = gelu_tanh(c0); c1 = gelu_tanh(c1);
                c2 = gelu_tanh(c2); c3 = gelu_tanh(c3);
                __half h0, l0v, h1, l1v, h2, l2v, h3, l3v;
                split2h(c0, h0, l0v); split2h(c1, h1, l1v);
                split2h(c2, h2, l2v); split2h(c3, h3, l3v);
                *(unsigned*)(Chh + o0) = pack_h2(h0, h1);
                *(unsigned*)(Chl + o0) = pack_h2(l0v, l1v);
                *(unsigned*)(Chh + o1) = pack_h2(h2, h3);
                *(unsigned*)(Chl + o1) = pack_h2(l2v, l3v);
            }
        }
    }
}

// ---------------- tensor-core flash attention (bf16 split internal, fp16-split out) ----------------
__global__ __launch_bounds__(128) void attn_mma(
    const __nv_bfloat16* __restrict__ qh_, const __nv_bfloat16* __restrict__ ql_,
    __half* __restrict__ oh_, __half* __restrict__ ol_) {
    extern __shared__ char smem[];
    __nv_bfloat16* sb = (__nv_bfloat16*)smem;
    int* kcode = (int*)(smem + AT_CODE_B);
    const unsigned sbase = smem_u32(smem);
    const int h = blockIdx.y, b = blockIdx.z;
    const int q0 = blockIdx.x * 64;
    const int tid = threadIdx.x;
    const int lane = tid & 31;
    const int warp = tid >> 5;
    const int tg2 = (lane & 3) * 2;

    for (int idx = tid; idx < 64 * 8; idx += 128) {
        int r = idx >> 3, c = idx & 7;
        int gr = min(q0 + r, T_ - 1);
        size_t src = ((size_t)(b * T_ + gr)) * (3 * D_) + h * HD_ + c * 8;
        *(uint4*)&sb[AT_QH + r * ARS + c * 8] = *(const uint4*)(qh_ + src);
        *(uint4*)&sb[AT_QL + r * ARS + c * 8] = *(const uint4*)(ql_ + src);
    }
    __syncthreads();

    unsigned qfh[4][4], qfl[4][4];
    {
        unsigned rowoff = (unsigned)((warp * 16 + (lane & 15)) * (ARS * 2)) + (lane >> 4) * 16;
        #pragma unroll
        for (int ks = 0; ks < 4; ks++) {
            ldsm_x4(qfh[ks], sbase + AT_QH * 2 + rowoff + ks * 32);
            ldsm_x4(qfl[ks], sbase + AT_QL * 2 + rowoff + ks * 32);
        }
    }

    const int r0 = q0 + warp * 16 + (lane >> 2);
    const int r1 = r0 + 8;
    const int rc0 = min(r0, T_ - 1), rc1 = min(r1, T_ - 1);
    const int gq0 = tok_group(rc0), tq0 = tok_ts(rc0);
    const int gq1 = tok_group(rc1), tq1 = tok_ts(rc1);

    float m0 = -1e30f, m1 = -1e30f, l0 = 0.0f, l1 = 0.0f;
    float o[8][4];
    #pragma unroll
    for (int nt = 0; nt < 8; nt++)
        #pragma unroll
        for (int r = 0; r < 4; r++) o[nt][r] = 0.0f;

    const int rlast = min(q0 + 63, T_ - 1);
    const int kmax = P_ + (tok_ts(rlast) + 1) * TPS;

    const unsigned kb = (unsigned)(((lane & 7) + ((lane >> 4) << 3)) * (ARS * 2)) +
                        ((lane >> 3) & 1) * 16;

    for (int k0 = 0; k0 < kmax; k0 += 64) {
        __syncthreads();
        for (int idx = tid; idx < 64 * 8; idx += 128) {
            int r = idx >> 3, c = idx & 7;
            int kr = k0 + r;
            uint4 z = make_uint4(0, 0, 0, 0);
            uint4 kvh = z, kvl = z, vvh = z, vvl = z;
            if (kr < T_) {
                size_t src = ((size_t)(b * T_ + kr)) * (3 * D_) + D_ + h * HD_ + c * 8;
                kvh = *(const uint4*)(qh_ + src);
                kvl = *(const uint4*)(ql_ + src);
                vvh = *(const uint4*)(qh_ + src + D_);
                vvl = *(const uint4*)(ql_ + src + D_);
            }
            *(uint4*)&sb[AT_KH + r * ARS + c * 8] = kvh;
            *(uint4*)&sb[AT_KL + r * ARS + c * 8] = kvl;
            *(uint4*)&sb[AT_VH + r * ARS + c * 8] = vvh;
            *(uint4*)&sb[AT_VL + r * ARS + c * 8] = vvl;
        }
        if (tid < 64) {
            int kg = k0 + tid;
            kcode[tid] = (kg < kmax && kg < T_)
                       ? ((tok_ts(kg) << 2) | tok_group(kg))
                       : ((0x3FFF << 2) | 3);
        }
        __syncthreads();

        float s[8][4];
        #pragma unroll
        for (int nt = 0; nt < 8; nt++)
            #pragma unroll
            for (int r = 0; r < 4; r++) s[nt][r] = 0.0f;

        #pragma unroll
        for (int kg = 0; kg < 4; kg++) {
            #pragma unroll
            for (int ks = 0; ks < 4; ks++) {
                unsigned kh[4], kl[4];
                unsigned addr = sbase + kb + (unsigned)(kg * 16 * (ARS * 2)) + ks * 32;
                ldsm_x4(kh, addr + AT_KH * 2);
                ldsm_x4(kl, addr + AT_KL * 2);
                #pragma unroll
                for (int half = 0; half < 2; half++) {
                    int nt = kg * 2 + half;
                    mma_bf16(s[nt], qfh[ks], &kh[half * 2]);
                    mma_bf16(s[nt], qfh[ks], &kl[half * 2]);
                    mma_bf16(s[nt], qfl[ks], &kh[half * 2]);
                }
            }
        }

        #pragma unroll
        for (int nt = 0; nt < 8; nt++) {
            int kc0 = kcode[nt * 8 + tg2];
            int kc1 = kcode[nt * 8 + tg2 + 1];
            s[nt][0] = allow_code(gq0, tq0, kc0) ? s[nt][0] * ATT_SCALE : -1e30f;
            s[nt][1] = allow_code(gq0, tq0, kc1) ? s[nt][1] * ATT_SCALE : -1e30f;
            s[nt][2] = allow_code(gq1, tq1, kc0) ? s[nt][2] * ATT_SCALE : -1e30f;
            s[nt][3] = allow_code(gq1, tq1, kc1) ? s[nt][3] * ATT_SCALE : -1e30f;
        }

        float mx0 = -1e30f, mx1 = -1e30f;
        #pragma unroll
        for (int nt = 0; nt < 8; nt++) {
            mx0 = fmaxf(mx0, fmaxf(s[nt][0], s[nt][1]));
            mx1 = fmaxf(mx1, fmaxf(s[nt][2], s[nt][3]));
        }
        mx0 = fmaxf(mx0, __shfl_xor_sync(0xffffffffu, mx0, 1));
        mx0 = fmaxf(mx0, __shfl_xor_sync(0xffffffffu, mx0, 2));
        mx1 = fmaxf(mx1, __shfl_xor_sync(0xffffffffu, mx1, 1));
        mx1 = fmaxf(mx1, __shfl_xor_sync(0xffffffffu, mx1, 2));
        float mn0 = fmaxf(m0, mx0), mn1 = fmaxf(m1, mx1);
        float corr0 = __expf(m0 - mn0), corr1 = __expf(m1 - mn1);
        m0 = mn0; m1 = mn1;
        l0 *= corr0; l1 *= corr1;
        #pragma unroll
        for (int nt = 0; nt < 8; nt++) {
            o[nt][0] *= corr0; o[nt][1] *= corr0;
            o[nt][2] *= corr1; o[nt][3] *= corr1;
        }

        #pragma unroll
        for (int kv = 0; kv < 4; kv++) {
            unsigned ph[4], pl[4];
            #pragma unroll
            for (int half = 0; half < 2; half++) {
                int nt = kv * 2 + half;
                float p0 = __expf(s[nt][0] - m0);
                float p1 = __expf(s[nt][1] - m0);
                float p2 = __expf(s[nt][2] - m1);
                float p3 = __expf(s[nt][3] - m1);
                l0 += p0 + p1;
                l1 += p2 + p3;
                __nv_bfloat16 h0, lo0, h1, lo1, h2, lo2, h3, lo3;
                split2(p0, h0, lo0); split2(p1, h1, lo1);
                split2(p2, h2, lo2); split2(p3, h3, lo3);
                ph[half * 2 + 0] = pack_bf2(h0, h1);
                ph[half * 2 + 1] = pack_bf2(h2, h3);
                pl[half * 2 + 0] = pack_bf2(lo0, lo1);
                pl[half * 2 + 1] = pack_bf2(lo2, lo3);
            }
            #pragma unroll
            for (int dg = 0; dg < 4; dg++) {
                unsigned vh[4], vl[4];
                unsigned addr = sbase + kb + (unsigned)(kv * 16 * (ARS * 2)) + dg * 32;
                ldsm_x4t(vh, addr + AT_VH * 2);
                ldsm_x4t(vl, addr + AT_VL * 2);
                #pragma unroll
                for (int half = 0; half < 2; half++) {
                    int nt = dg * 2 + half;
                    unsigned bhp[2] = {vh[half], vh[2 + half]};
                    unsigned blp[2] = {vl[half], vl[2 + half]};
                    mma_bf16(o[nt], ph, bhp);
                    mma_bf16(o[nt], ph, blp);
                    mma_bf16(o[nt], pl, bhp);
                }
            }
        }
    }

    l0 += __shfl_xor_sync(0xffffffffu, l0, 1);
    l0 += __shfl_xor_sync(0xffffffffu, l0, 2);
    l1 += __shfl_xor_sync(0xffffffffu, l1, 1);
    l1 += __shfl_xor_sync(0xffffffffu, l1, 2);
    float li0 = 1.0f / l0, li1 = 1.0f / l1;

    #pragma unroll
    for (int nt = 0; nt < 8; nt++) {
        int d = h * HD_ + nt * 8 + tg2;
        if (r0 < T_) {
            size_t off = ((size_t)(b * T_ + r0)) * D_ + d;
            float v0 = o[nt][0] * li0, v1 = o[nt][1] * li0;
            __half h0, lo0, h1, lo1;
            split2h(v0, h0, lo0); split2h(v1, h1, lo1);
            *(unsigned*)(oh_ + off) = pack_h2(h0, h1);
            *(unsigned*)(ol_ + off) = pack_h2(lo0, lo1);
        }
        if (r1 < T_) {
            size_t off = ((size_t)(b * T_ + r1)) * D_ + d;
            float v2 = o[nt][2] * li1, v3 = o[nt][3] * li1;
            __half h2, lo2, h3, lo3;
            split2h(v2, h2, lo2); split2h(v3, h3, lo3);
            *(unsigned*)(oh_ + off) = pack_h2(h2, h3);
            *(unsigned*)(ol_ + off) = pack_h2(lo2, lo3);
        }
    }
}

// ---------------- host orchestration ----------------
extern "C" void kernel_launch(void* const* d_in, const int* in_sizes, int n_in,
                              void* d_out, int out_size) {
    (void)in_sizes; (void)n_in; (void)out_size;

    const float* prefix = (const float*)d_in[0];
    const float* obs    = (const float*)d_in[2];
    const float* rdo    = (const float*)d_in[4];
    const float* ln1_s  = (const float*)d_in[6];
    const float* ln1_b  = (const float*)d_in[7];
    const float* wqkv   = (const float*)d_in[8];
    const float* bqkv   = (const float*)d_in[9];
    const float* wo     = (const float*)d_in[10];
    const float* bo     = (const float*)d_in[11];
    const float* ln2_s  = (const float*)d_in[12];
    const float* ln2_b  = (const float*)d_in[13];
    const float* w1     = (const float*)d_in[14];
    const float* b1     = (const float*)d_in[15];
    const float* w2     = (const float*)d_in[16];
    const float* b2     = (const float*)d_in[17];
    const float* lnf_s  = (const float*)d_in[18];
    const float* lnf_b  = (const float*)d_in[19];
    float* out = (float*)d_out;

    float* x;
    __half *yhi, *ylo, *atthi, *attlo, *ffnhi, *ffnlo;
    __nv_bfloat16 *qkvhi, *qkvlo;
    __half *wqkvT_hi, *wqkvT_lo, *woT_hi, *woT_lo, *w1T_hi, *w1T_lo, *w2T_hi, *w2T_lo;
    cudaGetSymbolAddress((void**)&x,     g_x);
    cudaGetSymbolAddress((void**)&yhi,   g_y_hi);
    cudaGetSymbolAddress((void**)&ylo,   g_y_lo);
    cudaGetSymbolAddress((void**)&qkvhi, g_qkv_hi);
    cudaGetSymbolAddress((void**)&qkvlo, g_qkv_lo);
    cudaGetSymbolAddress((void**)&atthi, g_att_hi);
    cudaGetSymbolAddress((void**)&attlo, g_att_lo);
    cudaGetSymbolAddress((void**)&ffnhi, g_ffn_hi);
    cudaGetSymbolAddress((void**)&ffnlo, g_ffn_lo);
    cudaGetSymbolAddress((void**)&wqkvT_hi, g_wqkvT_hi);
    cudaGetSymbolAddress((void**)&wqkvT_lo, g_wqkvT_lo);
    cudaGetSymbolAddress((void**)&woT_hi,   g_woT_hi);
    cudaGetSymbolAddress((void**)&woT_lo,   g_woT_lo);
    cudaGetSymbolAddress((void**)&w1T_hi,   g_w1T_hi);
    cudaGetSymbolAddress((void**)&w1T_lo,   g_w1T_lo);
    cudaGetSymbolAddress((void**)&w2T_hi,   g_w2T_hi);
    cudaGetSymbolAddress((void**)&w2T_lo,   g_w2T_lo);

    cudaFuncSetAttribute(wmma_gemm<0>, cudaFuncAttributeMaxDynamicSharedMemorySize, SMEM_GEMM);
    cudaFuncSetAttribute(wmma_gemm<1>, cudaFuncAttributeMaxDynamicSharedMemorySize, SMEM_GEMM);
    cudaFuncSetAttribute(wmma_gemm<2>, cudaFuncAttributeMaxDynamicSharedMemorySize, SMEM_GEMM);
    cudaFuncSetAttribute(attn_mma, cudaFuncAttributeMaxDynamicSharedMemorySize, ATTN_SMEM);

    assemble_kernel<<<2048, 256>>>(prefix, obs, rdo);

    wsplit_all_kernel<<<dim3(6912, L_), dim3(32, 8)>>>(
        wqkv, wo, w1, w2,
        wqkvT_hi, wqkvT_lo, woT_hi, woT_lo, w1T_hi, w1T_lo, w2T_hi, w2T_lo);

    const dim3 g_qkv_grid(3 * D_ / BN, M_ / BM);   // (18, 86)
    const dim3 g_wo_grid (D_ / BN,     M_ / BM);   // (6, 86)
    const dim3 g_w1_grid (F_ / BN,     M_ / BM);   // (24, 86)
    const dim3 g_attn((T_ + 63) / 64, NH_, B_);    // (22, 12, 8)

    for (int l = 0; l < L_; l++) {
        ln_split_kernel<<<M_, 256>>>(x, ln1_s + (size_t)l * D_, ln1_b + (size_t)l * D_, yhi, ylo);
        wmma_gemm<0><<<g_qkv_grid, 256, SMEM_GEMM>>>(
            yhi, ylo,
            wqkvT_hi + (size_t)l * 3 * D_ * D_, wqkvT_lo + (size_t)l * 3 * D_ * D_,
            bqkv + (size_t)l * 3 * D_, nullptr, nullptr,
            qkvhi, qkvlo, nullptr, nullptr, 3 * D_, D_);
        attn_mma<<<g_attn, 128, ATTN_SMEM>>>(qkvhi, qkvlo, atthi, attlo);
        wmma_gemm<2><<<g_wo_grid, 256, SMEM_GEMM>>>(
            atthi, attlo,
            woT_hi + (size_t)l * D_ * D_, woT_lo + (size_t)l * D_ * D_,
            bo + (size_t)l * D_, x, x,
            nullptr, nullptr, nullptr, nullptr, D_, D_);
        ln_split_kernel<<<M_, 256>>>(x, ln2_s + (size_t)l * D_, ln2_b + (size_t)l * D_, yhi, ylo);
        wmma_gemm<1><<<g_w1_grid, 256, SMEM_GEMM>>>(
            yhi, ylo,
            w1T_hi + (size_t)l * F_ * D_, w1T_lo + (size_t)l * F_ * D_,
            b1 + (size_t)l * F_, nullptr, nullptr,
            nullptr, nullptr, ffnhi, ffnlo, F_, D_);
        wmma_gemm<2><<<g_wo_grid, 256, SMEM_GEMM>>>(
            ffnhi, ffnlo,
            w2T_hi + (size_t)l * D_ * F_, w2T_lo + (size_t)l * D_ * F_,
            b2 + (size_t)l * D_, x, x,
            nullptr, nullptr, nullptr, nullptr, D_, F_);
    }

    ln_kernel<<<M_, 256>>>(x, lnf_s, lnf_b, out);
}

// round 12
// speedup vs baseline: 2.3320x; 1.1554x over previous
#include <cuda_runtime.h>
#include <cuda_bf16.h>
#include <math.h>
#include <stdint.h>

// ---------------- problem constants ----------------
namespace {
constexpr int B_  = 8;
constexpr int P_  = 16;
constexpr int HOR = 10;
constexpr int NO_ = 128;
constexpr int NR_ = 8;
constexpr int D_  = 768;
constexpr int NH_ = 12;
constexpr int HD_ = 64;
constexpr int F_  = 3072;
constexpr int L_  = 12;
constexpr int TPS = NO_ + NR_;          // 136
constexpr int T_  = P_ + HOR * TPS;     // 1376
constexpr int M_  = B_ * T_;            // 11008
constexpr float LN_EPS = 1e-6f;
constexpr float ATT_SCALE = 0.125f;     // 1/sqrt(64)

// GEMM tiling: 256 threads, 2x4 warp grid (64x32 warp tile), BK=32, 2-stage cp.async,
// sized for 2 CTAs/SM
constexpr int BM = 128;
constexpr int BN = 128;
constexpr int BK = 32;
constexpr int RS = 40;                   // SMEM row stride in bf16 (80B), conflict-free ldmatrix
constexpr int TILE_B = 128 * RS * 2;     // 10240 bytes per operand tile
constexpr int STAGE_B = 4 * TILE_B;      // Ahi,Alo,Bhi,Blo = 40960
constexpr int SMEM_GEMM = 2 * STAGE_B;   // 81920

// attention smem: Q (hi/lo) + 2-stage K/V (hi/lo) + double-buffered key codes
constexpr int ARS   = 72;                // 144B row stride, conflict-free
constexpr int ATSZ  = 64 * ARS;          // bf16 units per tile quarter (4608)
constexpr int AT_QH = 0;
constexpr int AT_QL = ATSZ;
constexpr int AT_TSZB = ATSZ * 2;        // 9216 bytes per tile quarter
constexpr int AT_CODE_B = 10 * AT_TSZB;  // byte offset of key codes (92160)
constexpr int ATTN_SMEM = AT_CODE_B + 2 * 64 * 4;   // 92672 bytes
}

// ---------------- scratch (device globals: no cudaMalloc allowed) ----------------
__device__ float g_x[(size_t)M_ * D_];
__device__ __nv_bfloat16 g_y_hi  [(size_t)M_ * D_];
__device__ __nv_bfloat16 g_y_lo  [(size_t)M_ * D_];
__device__ __nv_bfloat16 g_qkv_hi[(size_t)M_ * 3 * D_];
__device__ __nv_bfloat16 g_qkv_lo[(size_t)M_ * 3 * D_];
__device__ __nv_bfloat16 g_att_hi[(size_t)M_ * D_];
__device__ __nv_bfloat16 g_att_lo[(size_t)M_ * D_];
__device__ __nv_bfloat16 g_ffn_hi[(size_t)M_ * F_];
__device__ __nv_bfloat16 g_ffn_lo[(size_t)M_ * F_];
__device__ __nv_bfloat16 g_wqkvT_hi[(size_t)L_ * 3 * D_ * D_];
__device__ __nv_bfloat16 g_wqkvT_lo[(size_t)L_ * 3 * D_ * D_];
__device__ __nv_bfloat16 g_woT_hi  [(size_t)L_ * D_ * D_];
__device__ __nv_bfloat16 g_woT_lo  [(size_t)L_ * D_ * D_];
__device__ __nv_bfloat16 g_w1T_hi  [(size_t)L_ * F_ * D_];
__device__ __nv_bfloat16 g_w1T_lo  [(size_t)L_ * F_ * D_];
__device__ __nv_bfloat16 g_w2T_hi  [(size_t)L_ * D_ * F_];
__device__ __nv_bfloat16 g_w2T_lo  [(size_t)L_ * D_ * F_];

// ---------------- mma / async helpers ----------------
__device__ __forceinline__ unsigned smem_u32(const void* p) {
    return (unsigned)__cvta_generic_to_shared(p);
}
__device__ __forceinline__ void ldsm_x4(unsigned* r, unsigned addr) {
    asm volatile("ldmatrix.sync.aligned.m8n8.x4.shared.b16 {%0,%1,%2,%3}, [%4];"
                 : "=r"(r[0]), "=r"(r[1]), "=r"(r[2]), "=r"(r[3]) : "r"(addr));
}
__device__ __forceinline__ void ldsm_x4t(unsigned* r, unsigned addr) {
    asm volatile("ldmatrix.sync.aligned.m8n8.x4.trans.shared.b16 {%0,%1,%2,%3}, [%4];"
                 : "=r"(r[0]), "=r"(r[1]), "=r"(r[2]), "=r"(r[3]) : "r"(addr));
}
__device__ __forceinline__ void mma_bf16(float* c, const unsigned* a, const unsigned* b) {
    asm volatile(
        "mma.sync.aligned.m16n8k16.row.col.f32.bf16.bf16.f32 "
        "{%0,%1,%2,%3}, {%4,%5,%6,%7}, {%8,%9}, {%0,%1,%2,%3};"
        : "+f"(c[0]), "+f"(c[1]), "+f"(c[2]), "+f"(c[3])
        : "r"(a[0]), "r"(a[1]), "r"(a[2]), "r"(a[3]), "r"(b[0]), "r"(b[1]));
}
__device__ __forceinline__ void cp16(unsigned saddr, const void* g) {
    asm volatile("cp.async.cg.shared.global [%0], [%1], 16;" :: "r"(saddr), "l"(g));
}
__device__ __forceinline__ void cp_commit() {
    asm volatile("cp.async.commit_group;" ::: "memory");
}
template <int N>
__device__ __forceinline__ void cp_wait() {
    asm volatile("cp.async.wait_group %0;" :: "n"(N) : "memory");
}
__device__ __forceinline__ unsigned pack_bf2(__nv_bfloat16 a, __nv_bfloat16 b) {
    __nv_bfloat162 t(a, b);
    return *(unsigned*)&t;
}
__device__ __forceinline__ void split2(float v, __nv_bfloat16& h, __nv_bfloat16& l) {
    h = __float2bfloat16(v);
    l = __float2bfloat16(v - __bfloat162float(h));
}

// ---------------- misc helpers ----------------
__device__ __forceinline__ float gelu_tanh(float x) {
    float x3 = x * x * x;
    return 0.5f * x * (1.0f + tanhf(0.7978845608028654f * (x + 0.044715f * x3)));
}
__device__ __forceinline__ int tok_group(int i) {
    if (i < P_) return 0;
    return (((i - P_) % TPS) < NO_) ? 1 : 2;
}
__device__ __forceinline__ int tok_ts(int i) {
    return (i < P_) ? -1 : (i - P_) / TPS;
}
__device__ __forceinline__ bool allow_code(int gq, int tq, int kc) {
    int gk = kc & 3;
    int tk = kc >> 2;
    if (gk == 0) return true;
    if (gq == 0) return false;
    if (tk > tq) return false;
    return (gk == 1) || (gq == 2);
}

// ---------------- assemble ----------------
__global__ void assemble_kernel(const float* __restrict__ prefix,
                                const float* __restrict__ obs,
                                const float* __restrict__ rdo) {
    for (int idx = blockIdx.x * blockDim.x + threadIdx.x;
         idx < M_ * D_; idx += gridDim.x * blockDim.x) {
        int d = idx % D_;
        int bt = idx / D_;
        int t = bt % T_;
        int b = bt / T_;
        float v;
        if (t < P_) {
            v = prefix[((size_t)b * P_ + t) * D_ + d];
        } else {
            int tt = t - P_;
            int ho = tt / TPS;
            int r  = tt % TPS;
            if (r < NO_)
                v = obs[(((size_t)b * HOR + ho) * NO_ + r) * D_ + d];
            else
                v = rdo[(((size_t)b * HOR + ho) * NR_ + (r - NO_)) * D_ + d];
        }
        g_x[idx] = v;
    }
}

// ---------------- fused weight transpose + split ----------------
__global__ void wsplit_all_kernel(const float* __restrict__ wqkv, const float* __restrict__ wo,
                                  const float* __restrict__ w1, const float* __restrict__ w2,
                                  __nv_bfloat16* __restrict__ qh, __nv_bfloat16* __restrict__ ql,
                                  __nv_bfloat16* __restrict__ oh, __nv_bfloat16* __restrict__ ol,
                                  __nv_bfloat16* __restrict__ h1, __nv_bfloat16* __restrict__ l1,
                                  __nv_bfloat16* __restrict__ h2, __nv_bfloat16* __restrict__ l2) {
    __shared__ float t[32][33];
    const int l = blockIdx.y;
    int bx = blockIdx.x;
    const float* src;
    __nv_bfloat16 *hiT, *loT;
    int R, C;
    if (bx < 1728) {
        src = wqkv + (size_t)l * D_ * 3 * D_;
        hiT = qh + (size_t)l * 3 * D_ * D_;  loT = ql + (size_t)l * 3 * D_ * D_;
        R = D_; C = 3 * D_;
    } else if (bx < 2304) {
        bx -= 1728;
        src = wo + (size_t)l * D_ * D_;
        hiT = oh + (size_t)l * D_ * D_;  loT = ol + (size_t)l * D_ * D_;
        R = D_; C = D_;
    } else if (bx < 4608) {
        bx -= 2304;
        src = w1 + (size_t)l * D_ * F_;
        hiT = h1 + (size_t)l * F_ * D_;  loT = l1 + (size_t)l * F_ * D_;
        R = D_; C = F_;
    } else {
        bx -= 4608;
        src = w2 + (size_t)l * F_ * D_;
        hiT = h2 + (size_t)l * D_ * F_;  loT = l2 + (size_t)l * D_ * F_;
        R = F_; C = D_;
    }
    const int cols = C / 32;
    const int cb = (bx % cols) * 32, rb = (bx / cols) * 32;
    const int tx = threadIdx.x, ty = threadIdx.y;
    #pragma unroll
    for (int i = 0; i < 32; i += 8)
        t[ty + i][tx] = src[(size_t)(rb + ty + i) * C + cb + tx];
    __syncthreads();
    #pragma unroll
    for (int i = 0; i < 32; i += 8) {
        float v = t[tx][ty + i];
        __nv_bfloat16 h, lo;
        split2(v, h, lo);
        size_t o = (size_t)(cb + ty + i) * R + rb + tx;
        hiT[o] = h;
        loT[o] = lo;
    }
}

// ---------------- layernorm ----------------
__device__ __forceinline__ float block_reduce_sum(float v, float* red) {
    int lane = threadIdx.x & 31;
    int wid  = threadIdx.x >> 5;
    #pragma unroll
    for (int o = 16; o; o >>= 1) v += __shfl_down_sync(0xffffffffu, v, o);
    if (lane == 0) red[wid] = v;
    __syncthreads();
    if (threadIdx.x < 32) {
        float t = (threadIdx.x < 8) ? red[threadIdx.x] : 0.0f;
        #pragma unroll
        for (int o = 4; o; o >>= 1) t += __shfl_down_sync(0xffffffffu, t, o);
        if (threadIdx.x == 0) red[32] = t;
    }
    __syncthreads();
    return red[32];
}

__global__ void ln_kernel(const float* __restrict__ x,
                          const float* __restrict__ s,
                          const float* __restrict__ b,
                          float* __restrict__ y) {
    __shared__ float red[33];
    int row = blockIdx.x;
    const float* xp = x + (size_t)row * D_;
    float v0 = xp[threadIdx.x];
    float v1 = xp[threadIdx.x + 256];
    float v2 = xp[threadIdx.x + 512];
    float mu = block_reduce_sum(v0 + v1 + v2, red) * (1.0f / D_);
    float d0 = v0 - mu, d1 = v1 - mu, d2 = v2 - mu;
    float var = block_reduce_sum(d0 * d0 + d1 * d1 + d2 * d2, red) * (1.0f / D_);
    float inv = rsqrtf(var + LN_EPS);
    float* yp = y + (size_t)row * D_;
    yp[threadIdx.x      ] = d0 * inv * s[threadIdx.x      ] + b[threadIdx.x      ];
    yp[threadIdx.x + 256] = d1 * inv * s[threadIdx.x + 256] + b[threadIdx.x + 256];
    yp[threadIdx.x + 512] = d2 * inv * s[threadIdx.x + 512] + b[threadIdx.x + 512];
}

__global__ void ln_split_kernel(const float* __restrict__ x,
                                const float* __restrict__ s,
                                const float* __restrict__ b,
                                __nv_bfloat16* __restrict__ yhi,
                                __nv_bfloat16* __restrict__ ylo) {
    __shared__ float red[33];
    int row = blockIdx.x;
    const float* xp = x + (size_t)row * D_;
    float v0 = xp[threadIdx.x];
    float v1 = xp[threadIdx.x + 256];
    float v2 = xp[threadIdx.x + 512];
    float mu = block_reduce_sum(v0 + v1 + v2, red) * (1.0f / D_);
    float d0 = v0 - mu, d1 = v1 - mu, d2 = v2 - mu;
    float var = block_reduce_sum(d0 * d0 + d1 * d1 + d2 * d2, red) * (1.0f / D_);
    float inv = rsqrtf(var + LN_EPS);
    size_t base = (size_t)row * D_;
    #pragma unroll
    for (int i = 0; i < 3; i++) {
        int c = threadIdx.x + i * 256;
        float dv = (i == 0 ? d0 : (i == 1 ? d1 : d2));
        float v = dv * inv * s[c] + b[c];
        __nv_bfloat16 h, l;
        split2(v, h, l);
        yhi[base + c] = h;
        ylo[base + c] = l;
    }
}

// ---------------- split-bf16 warp-mma GEMM (R8: 2 CTAs/SM, BK=32, 2-stage cp.async) ----------------
template <int EPI>
__global__ __launch_bounds__(256, 2) void wmma_gemm(
    const __nv_bfloat16* __restrict__ Ahi, const __nv_bfloat16* __restrict__ Alo,
    const __nv_bfloat16* __restrict__ Whi, const __nv_bfloat16* __restrict__ Wlo,
    const float* __restrict__ bias, const float* __restrict__ R,
    float* __restrict__ C,
    __nv_bfloat16* __restrict__ Chi, __nv_bfloat16* __restrict__ Clo,
    int Ndim, int Kdim) {
    extern __shared__ char smem[];
    const unsigned sbase = smem_u32(smem);
    const int tid = threadIdx.x;
    const int lane = tid & 31;
    const int wid = tid >> 5;
    const int warp_m = wid & 1;
    const int warp_n = wid >> 1;
    const int bm = blockIdx.y * BM;
    const int bn = blockIdx.x * BN;
    const int NK = Kdim / BK;

    const int r_ = tid >> 2, cc_ = tid & 3;
    const int r2_ = r_ + 64;
    const unsigned so1 = (unsigned)(r_ * (RS * 2) + cc_ * 16);
    const unsigned so2 = (unsigned)(r2_ * (RS * 2) + cc_ * 16);

    auto issue_stage = [&](int st) {
        const unsigned sb = sbase + (unsigned)((st & 1) * STAGE_B);
        const int k0 = st * BK;
        size_t a1 = (size_t)(bm + r_)  * Kdim + k0 + 8 * cc_;
        size_t a2 = (size_t)(bm + r2_) * Kdim + k0 + 8 * cc_;
        size_t b1 = (size_t)(bn + r_)  * Kdim + k0 + 8 * cc_;
        size_t b2 = (size_t)(bn + r2_) * Kdim + k0 + 8 * cc_;
        cp16(sb + so1,              Ahi + a1);
        cp16(sb + so2,              Ahi + a2);
        cp16(sb + TILE_B + so1,     Alo + a1);
        cp16(sb + TILE_B + so2,     Alo + a2);
        cp16(sb + 2 * TILE_B + so1, Whi + b1);
        cp16(sb + 2 * TILE_B + so2, Whi + b2);
        cp16(sb + 3 * TILE_B + so1, Wlo + b1);
        cp16(sb + 3 * TILE_B + so2, Wlo + b2);
        cp_commit();
    };

    const unsigned a_base = (unsigned)((warp_m * 64 + (lane & 15)) * (RS * 2) + (lane >> 4) * 16);
    const unsigned b_row = (unsigned)(warp_n * 32 + (lane & 7) + ((lane >> 4) << 3));
    const unsigned b_base = (unsigned)(b_row * (RS * 2) + (((lane >> 3) & 1) * 16));

    float acc[4][4][4];
    #pragma unroll
    for (int mt = 0; mt < 4; mt++)
        #pragma unroll
        for (int nt = 0; nt < 4; nt++)
            #pragma unroll
            for (int r = 0; r < 4; r++) acc[mt][nt][r] = 0.0f;

    issue_stage(0);

    for (int i = 0; i < NK; i++) {
        cp_wait<0>();
        __syncthreads();
        if (i + 1 < NK) issue_stage(i + 1);

        const unsigned tAhi = sbase + (unsigned)((i & 1) * STAGE_B);
        const unsigned tAlo = tAhi + TILE_B;
        const unsigned tBhi = tAlo + TILE_B;
        const unsigned tBlo = tBhi + TILE_B;

        #pragma unroll
        for (int ks = 0; ks < 2; ks++) {
            unsigned fbh[2][4], fbl[2][4];
            #pragma unroll
            for (int pr = 0; pr < 2; pr++) {
                unsigned bo = b_base + (unsigned)(pr * 16 * (RS * 2) + ks * 32);
                ldsm_x4(fbh[pr], tBhi + bo);
                ldsm_x4(fbl[pr], tBlo + bo);
            }
            #pragma unroll
            for (int mt = 0; mt < 4; mt++) {
                unsigned fah[4], fal[4];
                unsigned ao = a_base + (unsigned)(mt * 16 * (RS * 2) + ks * 32);
                ldsm_x4(fah, tAhi + ao);
                ldsm_x4(fal, tAlo + ao);
                #pragma unroll
                for (int nt = 0; nt < 4; nt++) {
                    const unsigned* bH = &fbh[nt >> 1][(nt & 1) * 2];
                    const unsigned* bL = &fbl[nt >> 1][(nt & 1) * 2];
                    mma_bf16(acc[mt][nt], fah, bH);
                    mma_bf16(acc[mt][nt], fah, bL);
                    mma_bf16(acc[mt][nt], fal, bH);
                }
            }
        }
    }

    // ---- epilogue ----
    const int g = lane >> 2, tg = lane & 3;
    #pragma unroll
    for (int mt = 0; mt < 4; mt++) {
        #pragma unroll
        for (int nt = 0; nt < 4; nt++) {
            int row0 = bm + warp_m * 64 + mt * 16 + g;
            int col  = bn + warp_n * 32 + nt * 8 + tg * 2;
            float2 bv = *(const float2*)(bias + col);
            float c0 = acc[mt][nt][0] + bv.x;
            float c1 = acc[mt][nt][1] + bv.y;
            float c2 = acc[mt][nt][2] + bv.x;
            float c3 = acc[mt][nt][3] + bv.y;
            size_t o0 = (size_t)row0 * Ndim + col;
            size_t o1 = o0 + (size_t)8 * Ndim;
            if (EPI == 2) {
                float2 r0 = *(const float2*)(R + o0);
                float2 r1 = *(const float2*)(R + o1);
                c0 += r0.x; c1 += r0.y; c2 += r1.x; c3 += r1.y;
                *(float2*)(C + o0) = make_float2(c0, c1);
                *(float2*)(C + o1) = make_float2(c2, c3);
            } else {
                if (EPI == 1) {
                    c0 = gelu_tanh(c0); c1 = gelu_tanh(c1);
                    c2 = gelu_tanh(c2); c3 = gelu_tanh(c3);
                }
                __nv_bfloat16 h0, l0v, h1, l1v, h2, l2v, h3, l3v;
                split2(c0, h0, l0v); split2(c1, h1, l1v);
                split2(c2, h2, l2v); split2(c3, h3, l3v);
                *(unsigned*)(Chi + o0) = pack_bf2(h0, h1);
                *(unsigned*)(Clo + o0) = pack_bf2(l0v, l1v);
                *(unsigned*)(Chi + o1) = pack_bf2(h2, h3);
                *(unsigned*)(Clo + o1) = pack_bf2(l2v, l3v);
            }
        }
    }
}

// ---------------- tensor-core flash attention, cp.async 2-stage K/V pipeline ----------------
__global__ __launch_bounds__(128) void attn_mma(
    const __nv_bfloat16* __restrict__ qh_, const __nv_bfloat16* __restrict__ ql_,
    __nv_bfloat16* __restrict__ oh_, __nv_bfloat16* __restrict__ ol_) {
    extern __shared__ char smem[];
    __nv_bfloat16* sb = (__nv_bfloat16*)smem;
    int* kcode = (int*)(smem + AT_CODE_B);      // 2 x 64 ints
    const unsigned sbase = smem_u32(smem);
    const int h = blockIdx.y, b = blockIdx.z;
    const int q0 = blockIdx.x * 64;
    const int tid = threadIdx.x;
    const int lane = tid & 31;
    const int warp = tid >> 5;
    const int tg2 = (lane & 3) * 2;

    const int rlast = min(q0 + 63, T_ - 1);
    const int kmax = P_ + (tok_ts(rlast) + 1) * TPS;   // <= T_
    const int ntiles = (kmax + 63) / 64;

    // ---- load Q tile (64 rows x 64 dims, hi/lo) ----
    for (int idx = tid; idx < 64 * 8; idx += 128) {
        int r = idx >> 3, c = idx & 7;
        int gr = min(q0 + r, T_ - 1);
        size_t src = ((size_t)(b * T_ + gr)) * (3 * D_) + h * HD_ + c * 8;
        *(uint4*)&sb[AT_QH + r * ARS + c * 8] = *(const uint4*)(qh_ + src);
        *(uint4*)&sb[AT_QL + r * ARS + c * 8] = *(const uint4*)(ql_ + src);
    }

    // ---- K/V stage prefetch via cp.async ----
    auto issue_kv = [&](int it) {
        const int s = it & 1;
        const unsigned base = sbase + (unsigned)((2 + s * 4) * AT_TSZB);
        const int k0 = it * 64;
        #pragma unroll
        for (int i = 0; i < 4; i++) {
            int idx = tid + i * 128;          // 0..511
            int r = idx >> 3, c = idx & 7;
            int kr = min(k0 + r, T_ - 1);     // clamp; masked keys never contribute
            size_t src = ((size_t)(b * T_ + kr)) * (3 * D_) + D_ + h * HD_ + c * 8;
            unsigned o = (unsigned)(r * ARS * 2 + c * 16);
            cp16(base + o,                qh_ + src);         // KH
            cp16(base + AT_TSZB + o,      ql_ + src);         // KL
            cp16(base + 2 * AT_TSZB + o,  qh_ + src + D_);    // VH
            cp16(base + 3 * AT_TSZB + o,  ql_ + src + D_);    // VL
        }
        cp_commit();
        if (tid < 64) {
            int kg = k0 + tid;
            kcode[s * 64 + tid] = (kg < kmax)
                                ? ((tok_ts(kg) << 2) | tok_group(kg))
                                : ((0x3FFF << 2) | 3);
        }
    };

    issue_kv(0);
    __syncthreads();   // Q tile visible for ldsm

    unsigned qfh[4][4], qfl[4][4];
    {
        unsigned rowoff = (unsigned)((warp * 16 + (lane & 15)) * (ARS * 2)) + (lane >> 4) * 16;
        #pragma unroll
        for (int ks = 0; ks < 4; ks++) {
            ldsm_x4(qfh[ks], sbase + AT_QH * 2 + rowoff + ks * 32);
            ldsm_x4(qfl[ks], sbase + AT_QL * 2 + rowoff + ks * 32);
        }
    }

    const int r0 = q0 + warp * 16 + (lane >> 2);
    const int r1 = r0 + 8;
    const int rc0 = min(r0, T_ - 1), rc1 = min(r1, T_ - 1);
    const int gq0 = tok_group(rc0), tq0 = tok_ts(rc0);
    const int gq1 = tok_group(rc1), tq1 = tok_ts(rc1);

    float m0 = -1e30f, m1 = -1e30f, l0 = 0.0f, l1 = 0.0f;
    float o[8][4];
    #pragma unroll
    for (int nt = 0; nt < 8; nt++)
        #pragma unroll
        for (int r = 0; r < 4; r++) o[nt][r] = 0.0f;

    const unsigned kb = (unsigned)(((lane & 7) + ((lane >> 4) << 3)) * (ARS * 2)) +
                        ((lane >> 3) & 1) * 16;

    for (int it = 0; it < ntiles; it++) {
        cp_wait<0>();
        __syncthreads();
        if (it + 1 < ntiles) issue_kv(it + 1);

        const int s = it & 1;
        const unsigned tKH = sbase + (unsigned)((2 + s * 4) * AT_TSZB);
        const unsigned tKL = tKH + AT_TSZB;
        const unsigned tVH = tKL + AT_TSZB;
        const unsigned tVL = tVH + AT_TSZB;
        const int* kc = kcode + s * 64;

        // ---- scores ----
        float sc[8][4];
        #pragma unroll
        for (int nt = 0; nt < 8; nt++)
            #pragma unroll
            for (int r = 0; r < 4; r++) sc[nt][r] = 0.0f;

        #pragma unroll
        for (int kg = 0; kg < 4; kg++) {
            #pragma unroll
            for (int ks = 0; ks < 4; ks++) {
                unsigned kh[4], kl[4];
                unsigned addr = kb + (unsigned)(kg * 16 * (ARS * 2)) + ks * 32;
                ldsm_x4(kh, tKH + addr);
                ldsm_x4(kl, tKL + addr);
                #pragma unroll
                for (int half = 0; half < 2; half++) {
                    int nt = kg * 2 + half;
                    mma_bf16(sc[nt], qfh[ks], &kh[half * 2]);
                    mma_bf16(sc[nt], qfh[ks], &kl[half * 2]);
                    mma_bf16(sc[nt], qfl[ks], &kh[half * 2]);
                }
            }
        }

        // ---- mask + scale ----
        #pragma unroll
        for (int nt = 0; nt < 8; nt++) {
            int kc0 = kc[nt * 8 + tg2];
            int kc1 = kc[nt * 8 + tg2 + 1];
            sc[nt][0] = allow_code(gq0, tq0, kc0) ? sc[nt][0] * ATT_SCALE : -1e30f;
            sc[nt][1] = allow_code(gq0, tq0, kc1) ? sc[nt][1] * ATT_SCALE : -1e30f;
            sc[nt][2] = allow_code(gq1, tq1, kc0) ? sc[nt][2] * ATT_SCALE : -1e30f;
            sc[nt][3] = allow_code(gq1, tq1, kc1) ? sc[nt][3] * ATT_SCALE : -1e30f;
        }

        // ---- online softmax ----
        float mx0 = -1e30f, mx1 = -1e30f;
        #pragma unroll
        for (int nt = 0; nt < 8; nt++) {
            mx0 = fmaxf(mx0, fmaxf(sc[nt][0], sc[nt][1]));
            mx1 = fmaxf(mx1, fmaxf(sc[nt][2], sc[nt][3]));
        }
        mx0 = fmaxf(mx0, __shfl_xor_sync(0xffffffffu, mx0, 1));
        mx0 = fmaxf(mx0, __shfl_xor_sync(0xffffffffu, mx0, 2));
        mx1 = fmaxf(mx1, __shfl_xor_sync(0xffffffffu, mx1, 1));
        mx1 = fmaxf(mx1, __shfl_xor_sync(0xffffffffu, mx1, 2));
        float mn0 = fmaxf(m0, mx0), mn1 = fmaxf(m1, mx1);
        float corr0 = __expf(m0 - mn0), corr1 = __expf(m1 - mn1);
        m0 = mn0; m1 = mn1;
        l0 *= corr0; l1 *= corr1;
        #pragma unroll
        for (int nt = 0; nt < 8; nt++) {
            o[nt][0] *= corr0; o[nt][1] *= corr0;
            o[nt][2] *= corr1; o[nt][3] *= corr1;
        }

        // ---- P = exp(S-m), split, O += P V ----
        #pragma unroll
        for (int kv = 0; kv < 4; kv++) {
            unsigned ph[4], pl[4];
            #pragma unroll
            for (int half = 0; half < 2; half++) {
                int nt = kv * 2 + half;
                float p0 = __expf(sc[nt][0] - m0);
                float p1 = __expf(sc[nt][1] - m0);
                float p2 = __expf(sc[nt][2] - m1);
                float p3 = __expf(sc[nt][3] - m1);
                l0 += p0 + p1;
                l1 += p2 + p3;
                __nv_bfloat16 h0, lo0, h1, lo1, h2, lo2, h3, lo3;
                split2(p0, h0, lo0); split2(p1, h1, lo1);
                split2(p2, h2, lo2); split2(p3, h3, lo3);
                ph[half * 2 + 0] = pack_bf2(h0, h1);
                ph[half * 2 + 1] = pack_bf2(h2, h3);
                pl[half * 2 + 0] = pack_bf2(lo0, lo1);
                pl[half * 2 + 1] = pack_bf2(lo2, lo3);
            }
            #pragma unroll
            for (int dg = 0; dg < 4; dg++) {
                unsigned vh[4], vl[4];
                unsigned addr = kb + (unsigned)(kv * 16 * (ARS * 2)) + dg * 32;
                ldsm_x4t(vh, tVH + addr);
                ldsm_x4t(vl, tVL + addr);
                #pragma unroll
                for (int half = 0; half < 2; half++) {
                    int nt = dg * 2 + half;
                    unsigned bhp[2] = {vh[half], vh[2 + half]};
                    unsigned blp[2] = {vl[half], vl[2 + half]};
                    mma_bf16(o[nt], ph, bhp);
                    mma_bf16(o[nt], ph, blp);
                    mma_bf16(o[nt], pl, bhp);
                }
            }
        }
    }

    // ---- finalize ----
    l0 += __shfl_xor_sync(0xffffffffu, l0, 1);
    l0 += __shfl_xor_sync(0xffffffffu, l0, 2);
    l1 += __shfl_xor_sync(0xffffffffu, l1, 1);
    l1 += __shfl_xor_sync(0xffffffffu, l1, 2);
    float li0 = 1.0f / l0, li1 = 1.0f / l1;

    #pragma unroll
    for (int nt = 0; nt < 8; nt++) {
        int d = h * HD_ + nt * 8 + tg2;
        if (r0 < T_) {
            size_t off = ((size_t)(b * T_ + r0)) * D_ + d;
            float v0 = o[nt][0] * li0, v1 = o[nt][1] * li0;
            __nv_bfloat16 h0, lo0, h1, lo1;
            split2(v0, h0, lo0); split2(v1, h1, lo1);
            *(unsigned*)(oh_ + off) = pack_bf2(h0, h1);
            *(unsigned*)(ol_ + off) = pack_bf2(lo0, lo1);
        }
        if (r1 < T_) {
            size_t off = ((size_t)(b * T_ + r1)) * D_ + d;
            float v2 = o[nt][2] * li1, v3 = o[nt][3] * li1;
            __nv_bfloat16 h2, lo2, h3, lo3;
            split2(v2, h2, lo2); split2(v3, h3, lo3);
            *(unsigned*)(oh_ + off) = pack_bf2(h2, h3);
            *(unsigned*)(ol_ + off) = pack_bf2(lo2, lo3);
        }
    }
}

// ---------------- host orchestration ----------------
extern "C" void kernel_launch(void* const* d_in, const int* in_sizes, int n_in,
                              void* d_out, int out_size) {
    (void)in_sizes; (void)n_in; (void)out_size;

    const float* prefix = (const float*)d_in[0];
    const float* obs    = (const float*)d_in[2];
    const float* rdo    = (const float*)d_in[4];
    const float* ln1_s  = (const float*)d_in[6];
    const float* ln1_b  = (const float*)d_in[7];
    const float* wqkv   = (const float*)d_in[8];
    const float* bqkv   = (const float*)d_in[9];
    const float* wo     = (const float*)d_in[10];
    const float* bo     = (const float*)d_in[11];
    const float* ln2_s  = (const float*)d_in[12];
    const float* ln2_b  = (const float*)d_in[13];
    const float* w1     = (const float*)d_in[14];
    const float* b1     = (const float*)d_in[15];
    const float* w2     = (const float*)d_in[16];
    const float* b2     = (const float*)d_in[17];
    const float* lnf_s  = (const float*)d_in[18];
    const float* lnf_b  = (const float*)d_in[19];
    float* out = (float*)d_out;

    float* x;
    __nv_bfloat16 *yhi, *ylo, *qkvhi, *qkvlo, *atthi, *attlo, *ffnhi, *ffnlo;
    __nv_bfloat16 *wqkvT_hi, *wqkvT_lo, *woT_hi, *woT_lo, *w1T_hi, *w1T_lo, *w2T_hi, *w2T_lo;
    cudaGetSymbolAddress((void**)&x,     g_x);
    cudaGetSymbolAddress((void**)&yhi,   g_y_hi);
    cudaGetSymbolAddress((void**)&ylo,   g_y_lo);
    cudaGetSymbolAddress((void**)&qkvhi, g_qkv_hi);
    cudaGetSymbolAddress((void**)&qkvlo, g_qkv_lo);
    cudaGetSymbolAddress((void**)&atthi, g_att_hi);
    cudaGetSymbolAddress((void**)&attlo, g_att_lo);
    cudaGetSymbolAddress((void**)&ffnhi, g_ffn_hi);
    cudaGetSymbolAddress((void**)&ffnlo, g_ffn_lo);
    cudaGetSymbolAddress((void**)&wqkvT_hi, g_wqkvT_hi);
    cudaGetSymbolAddress((void**)&wqkvT_lo, g_wqkvT_lo);
    cudaGetSymbolAddress((void**)&woT_hi,   g_woT_hi);
    cudaGetSymbolAddress((void**)&woT_lo,   g_woT_lo);
    cudaGetSymbolAddress((void**)&w1T_hi,   g_w1T_hi);
    cudaGetSymbolAddress((void**)&w1T_lo,   g_w1T_lo);
    cudaGetSymbolAddress((void**)&w2T_hi,   g_w2T_hi);
    cudaGetSymbolAddress((void**)&w2T_lo,   g_w2T_lo);

    cudaFuncSetAttribute(wmma_gemm<0>, cudaFuncAttributeMaxDynamicSharedMemorySize, SMEM_GEMM);
    cudaFuncSetAttribute(wmma_gemm<1>, cudaFuncAttributeMaxDynamicSharedMemorySize, SMEM_GEMM);
    cudaFuncSetAttribute(wmma_gemm<2>, cudaFuncAttributeMaxDynamicSharedMemorySize, SMEM_GEMM);
    cudaFuncSetAttribute(attn_mma, cudaFuncAttributeMaxDynamicSharedMemorySize, ATTN_SMEM);

    assemble_kernel<<<2048, 256>>>(prefix, obs, rdo);

    wsplit_all_kernel<<<dim3(6912, L_), dim3(32, 8)>>>(
        wqkv, wo, w1, w2,
        wqkvT_hi, wqkvT_lo, woT_hi, woT_lo, w1T_hi, w1T_lo, w2T_hi, w2T_lo);

    const dim3 g_qkv_grid(3 * D_ / BN, M_ / BM);   // (18, 86)
    const dim3 g_wo_grid (D_ / BN,     M_ / BM);   // (6, 86)
    const dim3 g_w1_grid (F_ / BN,     M_ / BM);   // (24, 86)
    const dim3 g_attn((T_ + 63) / 64, NH_, B_);    // (22, 12, 8)

    for (int l = 0; l < L_; l++) {
        ln_split_kernel<<<M_, 256>>>(x, ln1_s + (size_t)l * D_, ln1_b + (size_t)l * D_, yhi, ylo);
        wmma_gemm<0><<<g_qkv_grid, 256, SMEM_GEMM>>>(
            yhi, ylo,
            wqkvT_hi + (size_t)l * 3 * D_ * D_, wqkvT_lo + (size_t)l * 3 * D_ * D_,
            bqkv + (size_t)l * 3 * D_, nullptr, nullptr, qkvhi, qkvlo, 3 * D_, D_);
        attn_mma<<<g_attn, 128, ATTN_SMEM>>>(qkvhi, qkvlo, atthi, attlo);
        wmma_gemm<2><<<g_wo_grid, 256, SMEM_GEMM>>>(
            atthi, attlo,
            woT_hi + (size_t)l * D_ * D_, woT_lo + (size_t)l * D_ * D_,
            bo + (size_t)l * D_, x, x, nullptr, nullptr, D_, D_);
        ln_split_kernel<<<M_, 256>>>(x, ln2_s + (size_t)l * D_, ln2_b + (size_t)l * D_, yhi, ylo);
        wmma_gemm<1><<<g_w1_grid, 256, SMEM_GEMM>>>(
            yhi, ylo,
            w1T_hi + (size_t)l * F_ * D_, w1T_lo + (size_t)l * F_ * D_,
            b1 + (size_t)l * F_, nullptr, nullptr, ffnhi, ffnlo, F_, D_);
        wmma_gemm<2><<<g_wo_grid, 256, SMEM_GEMM>>>(
            ffnhi, ffnlo,
            w2T_hi + (size_t)l * D_ * F_, w2T_lo + (size_t)l * D_ * F_,
            b2 + (size_t)l * D_, x, x, nullptr, nullptr, D_, F_);
    }

    ln_kernel<<<M_, 256>>>(x, lnf_s, lnf_b, out);
}

// round 13
// speedup vs baseline: 2.9718x; 1.2743x over previous
#include <cuda_runtime.h>
#include <cuda_bf16.h>
#include <cuda_fp16.h>
#include <math.h>
#include <stdint.h>

// ---------------- problem constants ----------------
namespace {
constexpr int B_  = 8;
constexpr int P_  = 16;
constexpr int HOR = 10;
constexpr int NO_ = 128;
constexpr int NR_ = 8;
constexpr int D_  = 768;
constexpr int NH_ = 12;
constexpr int HD_ = 64;
constexpr int F_  = 3072;
constexpr int L_  = 12;
constexpr int TPS = NO_ + NR_;          // 136
constexpr int T_  = P_ + HOR * TPS;     // 1376
constexpr int M_  = B_ * T_;            // 11008
constexpr float LN_EPS = 1e-6f;
constexpr float ATT_SCALE = 0.125f;     // 1/sqrt(64)

// GEMM tiling: 256 threads, 2x4 warp grid, BK=32, 2-stage cp.async, 2 CTAs/SM
// operands: A = fp16 hi+lo (2 tiles), W = single fp16 (1 tile)
constexpr int BM = 128;
constexpr int BN = 128;
constexpr int BK = 32;
constexpr int RS = 40;                   // SMEM row stride in fp16 (80B), conflict-free ldmatrix
constexpr int TILE_B = 128 * RS * 2;     // 10240 bytes per operand tile
constexpr int STAGE_B = 3 * TILE_B;      // Ahi,Alo,W = 30720
constexpr int SMEM_GEMM = 2 * STAGE_B;   // 61440

// attention smem: Q (hi/lo) + 2-stage K/V (hi/lo) + double-buffered key codes (bf16 path)
constexpr int ARS   = 72;                // 144B row stride, conflict-free
constexpr int ATSZ  = 64 * ARS;          // bf16 units per tile quarter (4608)
constexpr int AT_QH = 0;
constexpr int AT_QL = ATSZ;
constexpr int AT_TSZB = ATSZ * 2;        // 9216 bytes per tile quarter
constexpr int AT_CODE_B = 10 * AT_TSZB;  // 92160
constexpr int ATTN_SMEM = AT_CODE_B + 2 * 64 * 4;   // 92672 bytes
}

// ---------------- scratch (device globals: no cudaMalloc allowed) ----------------
__device__ float g_x[(size_t)M_ * D_];
// fp16-split activations (GEMM A operands)
__device__ __half g_y_hi  [(size_t)M_ * D_];
__device__ __half g_y_lo  [(size_t)M_ * D_];
__device__ __half g_att_hi[(size_t)M_ * D_];
__device__ __half g_att_lo[(size_t)M_ * D_];
__device__ __half g_ffn_hi[(size_t)M_ * F_];
__device__ __half g_ffn_lo[(size_t)M_ * F_];
// qkv split bf16 (attention path, unchanged 3-term)
__device__ __nv_bfloat16 g_qkv_hi[(size_t)M_ * 3 * D_];
__device__ __nv_bfloat16 g_qkv_lo[(size_t)M_ * 3 * D_];
// single-fp16 transposed weights [N, K]
__device__ __half g_wqkvT[(size_t)L_ * 3 * D_ * D_];
__device__ __half g_woT  [(size_t)L_ * D_ * D_];
__device__ __half g_w1T  [(size_t)L_ * F_ * D_];
__device__ __half g_w2T  [(size_t)L_ * D_ * F_];

// ---------------- mma / async helpers ----------------
__device__ __forceinline__ unsigned smem_u32(const void* p) {
    return (unsigned)__cvta_generic_to_shared(p);
}
__device__ __forceinline__ void ldsm_x4(unsigned* r, unsigned addr) {
    asm volatile("ldmatrix.sync.aligned.m8n8.x4.shared.b16 {%0,%1,%2,%3}, [%4];"
                 : "=r"(r[0]), "=r"(r[1]), "=r"(r[2]), "=r"(r[3]) : "r"(addr));
}
__device__ __forceinline__ void ldsm_x4t(unsigned* r, unsigned addr) {
    asm volatile("ldmatrix.sync.aligned.m8n8.x4.trans.shared.b16 {%0,%1,%2,%3}, [%4];"
                 : "=r"(r[0]), "=r"(r[1]), "=r"(r[2]), "=r"(r[3]) : "r"(addr));
}
__device__ __forceinline__ void mma_bf16(float* c, const unsigned* a, const unsigned* b) {
    asm volatile(
        "mma.sync.aligned.m16n8k16.row.col.f32.bf16.bf16.f32 "
        "{%0,%1,%2,%3}, {%4,%5,%6,%7}, {%8,%9}, {%0,%1,%2,%3};"
        : "+f"(c[0]), "+f"(c[1]), "+f"(c[2]), "+f"(c[3])
        : "r"(a[0]), "r"(a[1]), "r"(a[2]), "r"(a[3]), "r"(b[0]), "r"(b[1]));
}
__device__ __forceinline__ void mma_f16f32(float* c, const unsigned* a, const unsigned* b) {
    asm volatile(
        "mma.sync.aligned.m16n8k16.row.col.f32.f16.f16.f32 "
        "{%0,%1,%2,%3}, {%4,%5,%6,%7}, {%8,%9}, {%0,%1,%2,%3};"
        : "+f"(c[0]), "+f"(c[1]), "+f"(c[2]), "+f"(c[3])
        : "r"(a[0]), "r"(a[1]), "r"(a[2]), "r"(a[3]), "r"(b[0]), "r"(b[1]));
}
__device__ __forceinline__ void cp16(unsigned saddr, const void* g) {
    asm volatile("cp.async.cg.shared.global [%0], [%1], 16;" :: "r"(saddr), "l"(g));
}
__device__ __forceinline__ void cp_commit() {
    asm volatile("cp.async.commit_group;" ::: "memory");
}
template <int N>
__device__ __forceinline__ void cp_wait() {
    asm volatile("cp.async.wait_group %0;" :: "n"(N) : "memory");
}
__device__ __forceinline__ unsigned pack_bf2(__nv_bfloat16 a, __nv_bfloat16 b) {
    __nv_bfloat162 t(a, b);
    return *(unsigned*)&t;
}
__device__ __forceinline__ unsigned pack_h2(__half a, __half b) {
    __half2 t(a, b);
    return *(unsigned*)&t;
}
__device__ __forceinline__ void split2(float v, __nv_bfloat16& h, __nv_bfloat16& l) {
    h = __float2bfloat16(v);
    l = __float2bfloat16(v - __bfloat162float(h));
}
__device__ __forceinline__ void split2h(float v, __half& h, __half& l) {
    h = __float2half(v);
    l = __float2half(v - __half2float(h));
}

// ---------------- misc helpers ----------------
__device__ __forceinline__ float gelu_tanh(float x) {
    float x3 = x * x * x;
    return 0.5f * x * (1.0f + tanhf(0.7978845608028654f * (x + 0.044715f * x3)));
}
__device__ __forceinline__ int tok_group(int i) {
    if (i < P_) return 0;
    return (((i - P_) % TPS) < NO_) ? 1 : 2;
}
__device__ __forceinline__ int tok_ts(int i) {
    return (i < P_) ? -1 : (i - P_) / TPS;
}
__device__ __forceinline__ bool allow_code(int gq, int tq, int kc) {
    int gk = kc & 3;
    int tk = kc >> 2;
    if (gk == 0) return true;
    if (gq == 0) return false;
    if (tk > tq) return false;
    return (gk == 1) || (gq == 2);
}

// ---------------- assemble ----------------
__global__ void assemble_kernel(const float* __restrict__ prefix,
                                const float* __restrict__ obs,
                                const float* __restrict__ rdo) {
    for (int idx = blockIdx.x * blockDim.x + threadIdx.x;
         idx < M_ * D_; idx += gridDim.x * blockDim.x) {
        int d = idx % D_;
        int bt = idx / D_;
        int t = bt % T_;
        int b = bt / T_;
        float v;
        if (t < P_) {
            v = prefix[((size_t)b * P_ + t) * D_ + d];
        } else {
            int tt = t - P_;
            int ho = tt / TPS;
            int r  = tt % TPS;
            if (r < NO_)
                v = obs[(((size_t)b * HOR + ho) * NO_ + r) * D_ + d];
            else
                v = rdo[(((size_t)b * HOR + ho) * NR_ + (r - NO_)) * D_ + d];
        }
        g_x[idx] = v;
    }
}

// ---------------- fused weight transpose + fp16 convert ----------------
__global__ void wconv_all_kernel(const float* __restrict__ wqkv, const float* __restrict__ wo,
                                 const float* __restrict__ w1, const float* __restrict__ w2,
                                 __half* __restrict__ q16, __half* __restrict__ o16,
                                 __half* __restrict__ f16a, __half* __restrict__ f16b) {
    __shared__ float t[32][33];
    const int l = blockIdx.y;
    int bx = blockIdx.x;
    const float* src;
    __half* dstT;
    int R, C;
    if (bx < 1728) {
        src = wqkv + (size_t)l * D_ * 3 * D_;
        dstT = q16 + (size_t)l * 3 * D_ * D_;
        R = D_; C = 3 * D_;
    } else if (bx < 2304) {
        bx -= 1728;
        src = wo + (size_t)l * D_ * D_;
        dstT = o16 + (size_t)l * D_ * D_;
        R = D_; C = D_;
    } else if (bx < 4608) {
        bx -= 2304;
        src = w1 + (size_t)l * D_ * F_;
        dstT = f16a + (size_t)l * F_ * D_;
        R = D_; C = F_;
    } else {
        bx -= 4608;
        src = w2 + (size_t)l * F_ * D_;
        dstT = f16b + (size_t)l * D_ * F_;
        R = F_; C = D_;
    }
    const int cols = C / 32;
    const int cb = (bx % cols) * 32, rb = (bx / cols) * 32;
    const int tx = threadIdx.x, ty = threadIdx.y;
    #pragma unroll
    for (int i = 0; i < 32; i += 8)
        t[ty + i][tx] = src[(size_t)(rb + ty + i) * C + cb + tx];
    __syncthreads();
    #pragma unroll
    for (int i = 0; i < 32; i += 8)
        dstT[(size_t)(cb + ty + i) * R + rb + tx] = __float2half(t[tx][ty + i]);
}

// ---------------- layernorm ----------------
__device__ __forceinline__ float block_reduce_sum(float v, float* red) {
    int lane = threadIdx.x & 31;
    int wid  = threadIdx.x >> 5;
    #pragma unroll
    for (int o = 16; o; o >>= 1) v += __shfl_down_sync(0xffffffffu, v, o);
    if (lane == 0) red[wid] = v;
    __syncthreads();
    if (threadIdx.x < 32) {
        float t = (threadIdx.x < 8) ? red[threadIdx.x] : 0.0f;
        #pragma unroll
        for (int o = 4; o; o >>= 1) t += __shfl_down_sync(0xffffffffu, t, o);
        if (threadIdx.x == 0) red[32] = t;
    }
    __syncthreads();
    return red[32];
}

__global__ void ln_kernel(const float* __restrict__ x,
                          const float* __restrict__ s,
                          const float* __restrict__ b,
                          float* __restrict__ y) {
    __shared__ float red[33];
    int row = blockIdx.x;
    const float* xp = x + (size_t)row * D_;
    float v0 = xp[threadIdx.x];
    float v1 = xp[threadIdx.x + 256];
    float v2 = xp[threadIdx.x + 512];
    float mu = block_reduce_sum(v0 + v1 + v2, red) * (1.0f / D_);
    float d0 = v0 - mu, d1 = v1 - mu, d2 = v2 - mu;
    float var = block_reduce_sum(d0 * d0 + d1 * d1 + d2 * d2, red) * (1.0f / D_);
    float inv = rsqrtf(var + LN_EPS);
    float* yp = y + (size_t)row * D_;
    yp[threadIdx.x      ] = d0 * inv * s[threadIdx.x      ] + b[threadIdx.x      ];
    yp[threadIdx.x + 256] = d1 * inv * s[threadIdx.x + 256] + b[threadIdx.x + 256];
    yp[threadIdx.x + 512] = d2 * inv * s[threadIdx.x + 512] + b[threadIdx.x + 512];
}

__global__ void ln_split_kernel(const float* __restrict__ x,
                                const float* __restrict__ s,
                                const float* __restrict__ b,
                                __half* __restrict__ yhi,
                                __half* __restrict__ ylo) {
    __shared__ float red[33];
    int row = blockIdx.x;
    const float* xp = x + (size_t)row * D_;
    float v0 = xp[threadIdx.x];
    float v1 = xp[threadIdx.x + 256];
    float v2 = xp[threadIdx.x + 512];
    float mu = block_reduce_sum(v0 + v1 + v2, red) * (1.0f / D_);
    float d0 = v0 - mu, d1 = v1 - mu, d2 = v2 - mu;
    float var = block_reduce_sum(d0 * d0 + d1 * d1 + d2 * d2, red) * (1.0f / D_);
    float inv = rsqrtf(var + LN_EPS);
    size_t base = (size_t)row * D_;
    #pragma unroll
    for (int i = 0; i < 3; i++) {
        int c = threadIdx.x + i * 256;
        float dv = (i == 0 ? d0 : (i == 1 ? d1 : d2));
        float v = dv * inv * s[c] + b[c];
        __half h, l;
        split2h(v, h, l);
        yhi[base + c] = h;
        ylo[base + c] = l;
    }
}

// ---------------- asymmetric fp16 warp-mma GEMM: 2 MMAs per k16 ----------------
// C[M,N] = (Ahi+Alo)[M,K] @ W16[N,K]^T + bias
// EPI 0: write split bf16 (qkv) ; EPI 1: gelu -> split fp16 ; EPI 2: +R -> fp32
template <int EPI>
__global__ __launch_bounds__(256, 2) void wmma_gemm(
    const __half* __restrict__ Ahi, const __half* __restrict__ Alo,
    const __half* __restrict__ W,
    const float* __restrict__ bias, const float* __restrict__ R,
    float* __restrict__ C,
    __nv_bfloat16* __restrict__ Cbh, __nv_bfloat16* __restrict__ Cbl,
    __half* __restrict__ Chh, __half* __restrict__ Chl,
    int Ndim, int Kdim) {
    extern __shared__ char smem[];
    const unsigned sbase = smem_u32(smem);
    const int tid = threadIdx.x;
    const int lane = tid & 31;
    const int wid = tid >> 5;
    const int warp_m = wid & 1;          // 2 warp rows (64 M each)
    const int warp_n = wid >> 1;         // 4 warp cols (32 N each)
    const int bm = blockIdx.y * BM;
    const int bn = blockIdx.x * BN;
    const int NK = Kdim / BK;

    const int r_ = tid >> 2, cc_ = tid & 3;
    const int r2_ = r_ + 64;
    const unsigned so1 = (unsigned)(r_ * (RS * 2) + cc_ * 16);
    const unsigned so2 = (unsigned)(r2_ * (RS * 2) + cc_ * 16);

    auto issue_stage = [&](int st) {
        const unsigned sb = sbase + (unsigned)((st & 1) * STAGE_B);
        const int k0 = st * BK;
        size_t a1 = (size_t)(bm + r_)  * Kdim + k0 + 8 * cc_;
        size_t a2 = (size_t)(bm + r2_) * Kdim + k0 + 8 * cc_;
        size_t b1 = (size_t)(bn + r_)  * Kdim + k0 + 8 * cc_;
        size_t b2 = (size_t)(bn + r2_) * Kdim + k0 + 8 * cc_;
        cp16(sb + so1,              Ahi + a1);
        cp16(sb + so2,              Ahi + a2);
        cp16(sb + TILE_B + so1,     Alo + a1);
        cp16(sb + TILE_B + so2,     Alo + a2);
        cp16(sb + 2 * TILE_B + so1, W + b1);
        cp16(sb + 2 * TILE_B + so2, W + b2);
        cp_commit();
    };

    const unsigned a_base = (unsigned)((warp_m * 64 + (lane & 15)) * (RS * 2) + (lane >> 4) * 16);
    const unsigned b_row = (unsigned)(warp_n * 32 + (lane & 7) + ((lane >> 4) << 3));
    const unsigned b_base = (unsigned)(b_row * (RS * 2) + (((lane >> 3) & 1) * 16));

    float acc[4][4][4];
    #pragma unroll
    for (int mt = 0; mt < 4; mt++)
        #pragma unroll
        for (int nt = 0; nt < 4; nt++)
            #pragma unroll
            for (int r = 0; r < 4; r++) acc[mt][nt][r] = 0.0f;

    issue_stage(0);

    for (int i = 0; i < NK; i++) {
        cp_wait<0>();
        __syncthreads();
        if (i + 1 < NK) issue_stage(i + 1);

        const unsigned tAhi = sbase + (unsigned)((i & 1) * STAGE_B);
        const unsigned tAlo = tAhi + TILE_B;
        const unsigned tW   = tAlo + TILE_B;

        #pragma unroll
        for (int ks = 0; ks < 2; ks++) {
            unsigned fbw[2][4];
            #pragma unroll
            for (int pr = 0; pr < 2; pr++) {
                unsigned bo = b_base + (unsigned)(pr * 16 * (RS * 2) + ks * 32);
                ldsm_x4(fbw[pr], tW + bo);
            }
            #pragma unroll
            for (int mt = 0; mt < 4; mt++) {
                unsigned fah[4], fal[4];
                unsigned ao = a_base + (unsigned)(mt * 16 * (RS * 2) + ks * 32);
                ldsm_x4(fah, tAhi + ao);
                ldsm_x4(fal, tAlo + ao);
                #pragma unroll
                for (int nt = 0; nt < 4; nt++) {
                    const unsigned* bW = &fbw[nt >> 1][(nt & 1) * 2];
                    mma_f16f32(acc[mt][nt], fah, bW);
                    mma_f16f32(acc[mt][nt], fal, bW);
                }
            }
        }
    }

    // ---- epilogue ----
    const int g = lane >> 2, tg = lane & 3;
    #pragma unroll
    for (int mt = 0; mt < 4; mt++) {
        #pragma unroll
        for (int nt = 0; nt < 4; nt++) {
            int row0 = bm + warp_m * 64 + mt * 16 + g;
            int col  = bn + warp_n * 32 + nt * 8 + tg * 2;
            float2 bv = *(const float2*)(bias + col);
            float c0 = acc[mt][nt][0] + bv.x;
            float c1 = acc[mt][nt][1] + bv.y;
            float c2 = acc[mt][nt][2] + bv.x;
            float c3 = acc[mt][nt][3] + bv.y;
            size_t o0 = (size_t)row0 * Ndim + col;
            size_t o1 = o0 + (size_t)8 * Ndim;
            if (EPI == 2) {
                float2 r0 = *(const float2*)(R + o0);
                float2 r1 = *(const float2*)(R + o1);
                c0 += r0.x; c1 += r0.y; c2 += r1.x; c3 += r1.y;
                *(float2*)(C + o0) = make_float2(c0, c1);
                *(float2*)(C + o1) = make_float2(c2, c3);
            } else if (EPI == 0) {
                __nv_bfloat16 h0, l0v, h1, l1v, h2, l2v, h3, l3v;
                split2(c0, h0, l0v); split2(c1, h1, l1v);
                split2(c2, h2, l2v); split2(c3, h3, l3v);
                *(unsigned*)(Cbh + o0) = pack_bf2(h0, h1);
                *(unsigned*)(Cbl + o0) = pack_bf2(l0v, l1v);
                *(unsigned*)(Cbh + o1) = pack_bf2(h2, h3);
                *(unsigned*)(Cbl + o1) = pack_bf2(l2v, l3v);
            } else {
                c0 = gelu_tanh(c0); c1 = gelu_tanh(c1);
                c2 = gelu_tanh(c2); c3 = gelu_tanh(c3);
                __half h0, l0v, h1, l1v, h2, l2v, h3, l3v;
                split2h(c0, h0, l0v); split2h(c1, h1, l1v);
                split2h(c2, h2, l2v); split2h(c3, h3, l3v);
                *(unsigned*)(Chh + o0) = pack_h2(h0, h1);
                *(unsigned*)(Chl + o0) = pack_h2(l0v, l1v);
                *(unsigned*)(Chh + o1) = pack_h2(h2, h3);
                *(unsigned*)(Chl + o1) = pack_h2(l2v, l3v);
            }
        }
    }
}

// ---------------- tensor-core flash attention (bf16 3-term, cp.async K/V pipeline) ----------------
__global__ __launch_bounds__(128) void attn_mma(
    const __nv_bfloat16* __restrict__ qh_, const __nv_bfloat16* __restrict__ ql_,
    __half* __restrict__ oh_, __half* __restrict__ ol_) {
    extern __shared__ char smem[];
    __nv_bfloat16* sb = (__nv_bfloat16*)smem;
    int* kcode = (int*)(smem + AT_CODE_B);
    const unsigned sbase = smem_u32(smem);
    const int h = blockIdx.y, b = blockIdx.z;
    const int q0 = blockIdx.x * 64;
    const int tid = threadIdx.x;
    const int lane = tid & 31;
    const int warp = tid >> 5;
    const int tg2 = (lane & 3) * 2;

    const int rlast = min(q0 + 63, T_ - 1);
    const int kmax = P_ + (tok_ts(rlast) + 1) * TPS;
    const int ntiles = (kmax + 63) / 64;

    for (int idx = tid; idx < 64 * 8; idx += 128) {
        int r = idx >> 3, c = idx & 7;
        int gr = min(q0 + r, T_ - 1);
        size_t src = ((size_t)(b * T_ + gr)) * (3 * D_) + h * HD_ + c * 8;
        *(uint4*)&sb[AT_QH + r * ARS + c * 8] = *(const uint4*)(qh_ + src);
        *(uint4*)&sb[AT_QL + r * ARS + c * 8] = *(const uint4*)(ql_ + src);
    }

    auto issue_kv = [&](int it) {
        const int s = it & 1;
        const unsigned base = sbase + (unsigned)((2 + s * 4) * AT_TSZB);
        const int k0 = it * 64;
        #pragma unroll
        for (int i = 0; i < 4; i++) {
            int idx = tid + i * 128;
            int r = idx >> 3, c = idx & 7;
            int kr = min(k0 + r, T_ - 1);
            size_t src = ((size_t)(b * T_ + kr)) * (3 * D_) + D_ + h * HD_ + c * 8;
            unsigned o = (unsigned)(r * ARS * 2 + c * 16);
            cp16(base + o,               qh_ + src);
            cp16(base + AT_TSZB + o,     ql_ + src);
            cp16(base + 2 * AT_TSZB + o, qh_ + src + D_);
            cp16(base + 3 * AT_TSZB + o, ql_ + src + D_);
        }
        cp_commit();
        if (tid < 64) {
            int kg = k0 + tid;
            kcode[s * 64 + tid] = (kg < kmax)
                                ? ((tok_ts(kg) << 2) | tok_group(kg))
                                : ((0x3FFF << 2) | 3);
        }
    };

    issue_kv(0);
    __syncthreads();

    unsigned qfh[4][4], qfl[4][4];
    {
        unsigned rowoff = (unsigned)((warp * 16 + (lane & 15)) * (ARS * 2)) + (lane >> 4) * 16;
        #pragma unroll
        for (int ks = 0; ks < 4; ks++) {
            ldsm_x4(qfh[ks], sbase + AT_QH * 2 + rowoff + ks * 32);
            ldsm_x4(qfl[ks], sbase + AT_QL * 2 + rowoff + ks * 32);
        }
    }

    const int r0 = q0 + warp * 16 + (lane >> 2);
    const int r1 = r0 + 8;
    const int rc0 = min(r0, T_ - 1), rc1 = min(r1, T_ - 1);
    const int gq0 = tok_group(rc0), tq0 = tok_ts(rc0);
    const int gq1 = tok_group(rc1), tq1 = tok_ts(rc1);

    float m0 = -1e30f, m1 = -1e30f, l0 = 0.0f, l1 = 0.0f;
    float o[8][4];
    #pragma unroll
    for (int nt = 0; nt < 8; nt++)
        #pragma unroll
        for (int r = 0; r < 4; r++) o[nt][r] = 0.0f;

    const unsigned kb = (unsigned)(((lane & 7) + ((lane >> 4) << 3)) * (ARS * 2)) +
                        ((lane >> 3) & 1) * 16;

    for (int it = 0; it < ntiles; it++) {
        cp_wait<0>();
        __syncthreads();
        if (it + 1 < ntiles) issue_kv(it + 1);

        const int s = it & 1;
        const unsigned tKH = sbase + (unsigned)((2 + s * 4) * AT_TSZB);
        const unsigned tKL = tKH + AT_TSZB;
        const unsigned tVH = tKL + AT_TSZB;
        const unsigned tVL = tVH + AT_TSZB;
        const int* kc = kcode + s * 64;

        float sc[8][4];
        #pragma unroll
        for (int nt = 0; nt < 8; nt++)
            #pragma unroll
            for (int r = 0; r < 4; r++) sc[nt][r] = 0.0f;

        #pragma unroll
        for (int kg = 0; kg < 4; kg++) {
            #pragma unroll
            for (int ks = 0; ks < 4; ks++) {
                unsigned kh[4], kl[4];
                unsigned addr = kb + (unsigned)(kg * 16 * (ARS * 2)) + ks * 32;
                ldsm_x4(kh, tKH + addr);
                ldsm_x4(kl, tKL + addr);
                #pragma unroll
                for (int half = 0; half < 2; half++) {
                    int nt = kg * 2 + half;
                    mma_bf16(sc[nt], qfh[ks], &kh[half * 2]);
                    mma_bf16(sc[nt], qfh[ks], &kl[half * 2]);
                    mma_bf16(sc[nt], qfl[ks], &kh[half * 2]);
                }
            }
        }

        #pragma unroll
        for (int nt = 0; nt < 8; nt++) {
            int kc0 = kc[nt * 8 + tg2];
            int kc1 = kc[nt * 8 + tg2 + 1];
            sc[nt][0] = allow_code(gq0, tq0, kc0) ? sc[nt][0] * ATT_SCALE : -1e30f;
            sc[nt][1] = allow_code(gq0, tq0, kc1) ? sc[nt][1] * ATT_SCALE : -1e30f;
            sc[nt][2] = allow_code(gq1, tq1, kc0) ? sc[nt][2] * ATT_SCALE : -1e30f;
            sc[nt][3] = allow_code(gq1, tq1, kc1) ? sc[nt][3] * ATT_SCALE : -1e30f;
        }

        float mx0 = -1e30f, mx1 = -1e30f;
        #pragma unroll
        for (int nt = 0; nt < 8; nt++) {
            mx0 = fmaxf(mx0, fmaxf(sc[nt][0], sc[nt][1]));
            mx1 = fmaxf(mx1, fmaxf(sc[nt][2], sc[nt][3]));
        }
        mx0 = fmaxf(mx0, __shfl_xor_sync(0xffffffffu, mx0, 1));
        mx0 = fmaxf(mx0, __shfl_xor_sync(0xffffffffu, mx0, 2));
        mx1 = fmaxf(mx1, __shfl_xor_sync(0xffffffffu, mx1, 1));
        mx1 = fmaxf(mx1, __shfl_xor_sync(0xffffffffu, mx1, 2));
        float mn0 = fmaxf(m0, mx0), mn1 = fmaxf(m1, mx1);
        float corr0 = __expf(m0 - mn0), corr1 = __expf(m1 - mn1);
        m0 = mn0; m1 = mn1;
        l0 *= corr0; l1 *= corr1;
        #pragma unroll
        for (int nt = 0; nt < 8; nt++) {
            o[nt][0] *= corr0; o[nt][1] *= corr0;
            o[nt][2] *= corr1; o[nt][3] *= corr1;
        }

        #pragma unroll
        for (int kv = 0; kv < 4; kv++) {
            unsigned ph[4], pl[4];
            #pragma unroll
            for (int half = 0; half < 2; half++) {
                int nt = kv * 2 + half;
                float p0 = __expf(sc[nt][0] - m0);
                float p1 = __expf(sc[nt][1] - m0);
                float p2 = __expf(sc[nt][2] - m1);
                float p3 = __expf(sc[nt][3] - m1);
                l0 += p0 + p1;
                l1 += p2 + p3;
                __nv_bfloat16 h0, lo0, h1, lo1, h2, lo2, h3, lo3;
                split2(p0, h0, lo0); split2(p1, h1, lo1);
                split2(p2, h2, lo2); split2(p3, h3, lo3);
                ph[half * 2 + 0] = pack_bf2(h0, h1);
                ph[half * 2 + 1] = pack_bf2(h2, h3);
                pl[half * 2 + 0] = pack_bf2(lo0, lo1);
                pl[half * 2 + 1] = pack_bf2(lo2, lo3);
            }
            #pragma unroll
            for (int dg = 0; dg < 4; dg++) {
                unsigned vh[4], vl[4];
                unsigned addr = kb + (unsigned)(kv * 16 * (ARS * 2)) + dg * 32;
                ldsm_x4t(vh, tVH + addr);
                ldsm_x4t(vl, tVL + addr);
                #pragma unroll
                for (int half = 0; half < 2; half++) {
                    int nt = dg * 2 + half;
                    unsigned bhp[2] = {vh[half], vh[2 + half]};
                    unsigned blp[2] = {vl[half], vl[2 + half]};
                    mma_bf16(o[nt], ph, bhp);
                    mma_bf16(o[nt], ph, blp);
                    mma_bf16(o[nt], pl, bhp);
                }
            }
        }
    }

    l0 += __shfl_xor_sync(0xffffffffu, l0, 1);
    l0 += __shfl_xor_sync(0xffffffffu, l0, 2);
    l1 += __shfl_xor_sync(0xffffffffu, l1, 1);
    l1 += __shfl_xor_sync(0xffffffffu, l1, 2);
    float li0 = 1.0f / l0, li1 = 1.0f / l1;

    #pragma unroll
    for (int nt = 0; nt < 8; nt++) {
        int d = h * HD_ + nt * 8 + tg2;
        if (r0 < T_) {
            size_t off = ((size_t)(b * T_ + r0)) * D_ + d;
            float v0 = o[nt][0] * li0, v1 = o[nt][1] * li0;
            __half h0, lo0, h1, lo1;
            split2h(v0, h0, lo0); split2h(v1, h1, lo1);
            *(unsigned*)(oh_ + off) = pack_h2(h0, h1);
            *(unsigned*)(ol_ + off) = pack_h2(lo0, lo1);
        }
        if (r1 < T_) {
            size_t off = ((size_t)(b * T_ + r1)) * D_ + d;
            float v2 = o[nt][2] * li1, v3 = o[nt][3] * li1;
            __half h2, lo2, h3, lo3;
            split2h(v2, h2, lo2); split2h(v3, h3, lo3);
            *(unsigned*)(oh_ + off) = pack_h2(h2, h3);
            *(unsigned*)(ol_ + off) = pack_h2(lo2, lo3);
        }
    }
}

// ---------------- host orchestration ----------------
extern "C" void kernel_launch(void* const* d_in, const int* in_sizes, int n_in,
                              void* d_out, int out_size) {
    (void)in_sizes; (void)n_in; (void)out_size;

    const float* prefix = (const float*)d_in[0];
    const float* obs    = (const float*)d_in[2];
    const float* rdo    = (const float*)d_in[4];
    const float* ln1_s  = (const float*)d_in[6];
    const float* ln1_b  = (const float*)d_in[7];
    const float* wqkv   = (const float*)d_in[8];
    const float* bqkv   = (const float*)d_in[9];
    const float* wo     = (const float*)d_in[10];
    const float* bo     = (const float*)d_in[11];
    const float* ln2_s  = (const float*)d_in[12];
    const float* ln2_b  = (const float*)d_in[13];
    const float* w1     = (const float*)d_in[14];
    const float* b1     = (const float*)d_in[15];
    const float* w2     = (const float*)d_in[16];
    const float* b2     = (const float*)d_in[17];
    const float* lnf_s  = (const float*)d_in[18];
    const float* lnf_b  = (const float*)d_in[19];
    float* out = (float*)d_out;

    float* x;
    __half *yhi, *ylo, *atthi, *attlo, *ffnhi, *ffnlo;
    __nv_bfloat16 *qkvhi, *qkvlo;
    __half *wqkvT, *woT, *w1T, *w2T;
    cudaGetSymbolAddress((void**)&x,     g_x);
    cudaGetSymbolAddress((void**)&yhi,   g_y_hi);
    cudaGetSymbolAddress((void**)&ylo,   g_y_lo);
    cudaGetSymbolAddress((void**)&qkvhi, g_qkv_hi);
    cudaGetSymbolAddress((void**)&qkvlo, g_qkv_lo);
    cudaGetSymbolAddress((void**)&atthi, g_att_hi);
    cudaGetSymbolAddress((void**)&attlo, g_att_lo);
    cudaGetSymbolAddress((void**)&ffnhi, g_ffn_hi);
    cudaGetSymbolAddress((void**)&ffnlo, g_ffn_lo);
    cudaGetSymbolAddress((void**)&wqkvT, g_wqkvT);
    cudaGetSymbolAddress((void**)&woT,   g_woT);
    cudaGetSymbolAddress((void**)&w1T,   g_w1T);
    cudaGetSymbolAddress((void**)&w2T,   g_w2T);

    cudaFuncSetAttribute(wmma_gemm<0>, cudaFuncAttributeMaxDynamicSharedMemorySize, SMEM_GEMM);
    cudaFuncSetAttribute(wmma_gemm<1>, cudaFuncAttributeMaxDynamicSharedMemorySize, SMEM_GEMM);
    cudaFuncSetAttribute(wmma_gemm<2>, cudaFuncAttributeMaxDynamicSharedMemorySize, SMEM_GEMM);
    cudaFuncSetAttribute(attn_mma, cudaFuncAttributeMaxDynamicSharedMemorySize, ATTN_SMEM);

    assemble_kernel<<<2048, 256>>>(prefix, obs, rdo);

    wconv_all_kernel<<<dim3(6912, L_), dim3(32, 8)>>>(
        wqkv, wo, w1, w2, wqkvT, woT, w1T, w2T);

    const dim3 g_qkv_grid(3 * D_ / BN, M_ / BM);   // (18, 86)
    const dim3 g_wo_grid (D_ / BN,     M_ / BM);   // (6, 86)
    const dim3 g_w1_grid (F_ / BN,     M_ / BM);   // (24, 86)
    const dim3 g_attn((T_ + 63) / 64, NH_, B_);    // (22, 12, 8)

    for (int l = 0; l < L_; l++) {
        ln_split_kernel<<<M_, 256>>>(x, ln1_s + (size_t)l * D_, ln1_b + (size_t)l * D_, yhi, ylo);
        wmma_gemm<0><<<g_qkv_grid, 256, SMEM_GEMM>>>(
            yhi, ylo, wqkvT + (size_t)l * 3 * D_ * D_,
            bqkv + (size_t)l * 3 * D_, nullptr, nullptr,
            qkvhi, qkvlo, nullptr, nullptr, 3 * D_, D_);
        attn_mma<<<g_attn, 128, ATTN_SMEM>>>(qkvhi, qkvlo, atthi, attlo);
        wmma_gemm<2><<<g_wo_grid, 256, SMEM_GEMM>>>(
            atthi, attlo, woT + (size_t)l * D_ * D_,
            bo + (size_t)l * D_, x, x,
            nullptr, nullptr, nullptr, nullptr, D_, D_);
        ln_split_kernel<<<M_, 256>>>(x, ln2_s + (size_t)l * D_, ln2_b + (size_t)l * D_, yhi, ylo);
        wmma_gemm<1><<<g_w1_grid, 256, SMEM_GEMM>>>(
            yhi, ylo, w1T + (size_t)l * F_ * D_,
            b1 + (size_t)l * F_, nullptr, nullptr,
            nullptr, nullptr, ffnhi, ffnlo, F_, D_);
        wmma_gemm<2><<<g_wo_grid, 256, SMEM_GEMM>>>(
            ffnhi, ffnlo, w2T + (size_t)l * D_ * F_,
            b2 + (size_t)l * D_, x, x,
            nullptr, nullptr, nullptr, nullptr, D_, F_);
    }

    ln_kernel<<<M_, 256>>>(x, lnf_s, lnf_b, out);
}

// round 14
// speedup vs baseline: 3.3094x; 1.1136x over previous
#include <cuda_runtime.h>
#include <cuda_fp16.h>
#include <math.h>
#include <stdint.h>

// ---------------- problem constants ----------------
namespace {
constexpr int B_  = 8;
constexpr int P_  = 16;
constexpr int HOR = 10;
constexpr int NO_ = 128;
constexpr int NR_ = 8;
constexpr int D_  = 768;
constexpr int NH_ = 12;
constexpr int HD_ = 64;
constexpr int F_  = 3072;
constexpr int L_  = 12;
constexpr int TPS = NO_ + NR_;          // 136
constexpr int T_  = P_ + HOR * TPS;     // 1376
constexpr int M_  = B_ * T_;            // 11008
constexpr float LN_EPS = 1e-6f;
constexpr float ATT_SCALE = 0.125f;     // 1/sqrt(64)

// GEMM tiling: 256 threads, 2x4 warp grid, BK=32, 2-stage cp.async, 2 CTAs/SM
// operands: A = fp16 hi+lo (2 tiles), W = single fp16 (1 tile)
constexpr int BM = 128;
constexpr int BN = 128;
constexpr int BK = 32;
constexpr int RS = 40;                   // SMEM row stride in fp16 (80B), conflict-free ldmatrix
constexpr int TILE_B = 128 * RS * 2;     // 10240 bytes per operand tile
constexpr int STAGE_B = 3 * TILE_B;      // Ahi,Alo,W = 30720
constexpr int SMEM_GEMM = 2 * STAGE_B;   // 61440

// attention smem: Q (hi/lo) + 2-stage (K,V single fp16) + double-buffered key codes
constexpr int ARS   = 72;                // 144B row stride, conflict-free
constexpr int ATSZ  = 64 * ARS;          // fp16 units per tile quarter (4608)
constexpr int AT_QH = 0;
constexpr int AT_QL = ATSZ;
constexpr int AT_TSZB = ATSZ * 2;        // 9216 bytes per tile quarter
constexpr int AT_CODE_B = 6 * AT_TSZB;   // 55296
constexpr int ATTN_SMEM = AT_CODE_B + 2 * 64 * 4;   // 55808 bytes
}

// ---------------- scratch (device globals: no cudaMalloc allowed) ----------------
__device__ float g_x[(size_t)M_ * D_];
// fp16-split activations
__device__ __half g_y_hi  [(size_t)M_ * D_];
__device__ __half g_y_lo  [(size_t)M_ * D_];
__device__ __half g_att_hi[(size_t)M_ * D_];
__device__ __half g_att_lo[(size_t)M_ * D_];
__device__ __half g_ffn_hi[(size_t)M_ * F_];
__device__ __half g_ffn_lo[(size_t)M_ * F_];
// qkv split fp16 (attention: Q uses hi+lo; K,V use hi only)
__device__ __half g_qkv_hi[(size_t)M_ * 3 * D_];
__device__ __half g_qkv_lo[(size_t)M_ * 3 * D_];
// single-fp16 transposed weights [N, K]
__device__ __half g_wqkvT[(size_t)L_ * 3 * D_ * D_];
__device__ __half g_woT  [(size_t)L_ * D_ * D_];
__device__ __half g_w1T  [(size_t)L_ * F_ * D_];
__device__ __half g_w2T  [(size_t)L_ * D_ * F_];

// ---------------- mma / async helpers ----------------
__device__ __forceinline__ unsigned smem_u32(const void* p) {
    return (unsigned)__cvta_generic_to_shared(p);
}
__device__ __forceinline__ void ldsm_x4(unsigned* r, unsigned addr) {
    asm volatile("ldmatrix.sync.aligned.m8n8.x4.shared.b16 {%0,%1,%2,%3}, [%4];"
                 : "=r"(r[0]), "=r"(r[1]), "=r"(r[2]), "=r"(r[3]) : "r"(addr));
}
__device__ __forceinline__ void ldsm_x4t(unsigned* r, unsigned addr) {
    asm volatile("ldmatrix.sync.aligned.m8n8.x4.trans.shared.b16 {%0,%1,%2,%3}, [%4];"
                 : "=r"(r[0]), "=r"(r[1]), "=r"(r[2]), "=r"(r[3]) : "r"(addr));
}
__device__ __forceinline__ void mma_f16f32(float* c, const unsigned* a, const unsigned* b) {
    asm volatile(
        "mma.sync.aligned.m16n8k16.row.col.f32.f16.f16.f32 "
        "{%0,%1,%2,%3}, {%4,%5,%6,%7}, {%8,%9}, {%0,%1,%2,%3};"
        : "+f"(c[0]), "+f"(c[1]), "+f"(c[2]), "+f"(c[3])
        : "r"(a[0]), "r"(a[1]), "r"(a[2]), "r"(a[3]), "r"(b[0]), "r"(b[1]));
}
__device__ __forceinline__ void cp16(unsigned saddr, const void* g) {
    asm volatile("cp.async.cg.shared.global [%0], [%1], 16;" :: "r"(saddr), "l"(g));
}
__device__ __forceinline__ void cp_commit() {
    asm volatile("cp.async.commit_group;" ::: "memory");
}
template <int N>
__device__ __forceinline__ void cp_wait() {
    asm volatile("cp.async.wait_group %0;" :: "n"(N) : "memory");
}
__device__ __forceinline__ unsigned pack_h2(__half a, __half b) {
    __half2 t(a, b);
    return *(unsigned*)&t;
}
__device__ __forceinline__ void split2h(float v, __half& h, __half& l) {
    h = __float2half(v);
    l = __float2half(v - __half2float(h));
}

// ---------------- misc helpers ----------------
__device__ __forceinline__ float gelu_tanh(float x) {
    float x3 = x * x * x;
    return 0.5f * x * (1.0f + tanhf(0.7978845608028654f * (x + 0.044715f * x3)));
}
__device__ __forceinline__ int tok_group(int i) {
    if (i < P_) return 0;
    return (((i - P_) % TPS) < NO_) ? 1 : 2;
}
__device__ __forceinline__ int tok_ts(int i) {
    return (i < P_) ? -1 : (i - P_) / TPS;
}
__device__ __forceinline__ bool allow_code(int gq, int tq, int kc) {
    int gk = kc & 3;
    int tk = kc >> 2;
    if (gk == 0) return true;
    if (gq == 0) return false;
    if (tk > tq) return false;
    return (gk == 1) || (gq == 2);
}

// ---------------- assemble ----------------
__global__ void assemble_kernel(const float* __restrict__ prefix,
                                const float* __restrict__ obs,
                                const float* __restrict__ rdo) {
    for (int idx = blockIdx.x * blockDim.x + threadIdx.x;
         idx < M_ * D_; idx += gridDim.x * blockDim.x) {
        int d = idx % D_;
        int bt = idx / D_;
        int t = bt % T_;
        int b = bt / T_;
        float v;
        if (t < P_) {
            v = prefix[((size_t)b * P_ + t) * D_ + d];
        } else {
            int tt = t - P_;
            int ho = tt / TPS;
            int r  = tt % TPS;
            if (r < NO_)
                v = obs[(((size_t)b * HOR + ho) * NO_ + r) * D_ + d];
            else
                v = rdo[(((size_t)b * HOR + ho) * NR_ + (r - NO_)) * D_ + d];
        }
        g_x[idx] = v;
    }
}

// ---------------- fused weight transpose + fp16 convert ----------------
__global__ void wconv_all_kernel(const float* __restrict__ wqkv, const float* __restrict__ wo,
                                 const float* __restrict__ w1, const float* __restrict__ w2,
                                 __half* __restrict__ q16, __half* __restrict__ o16,
                                 __half* __restrict__ f16a, __half* __restrict__ f16b) {
    __shared__ float t[32][33];
    const int l = blockIdx.y;
    int bx = blockIdx.x;
    const float* src;
    __half* dstT;
    int R, C;
    if (bx < 1728) {
        src = wqkv + (size_t)l * D_ * 3 * D_;
        dstT = q16 + (size_t)l * 3 * D_ * D_;
        R = D_; C = 3 * D_;
    } else if (bx < 2304) {
        bx -= 1728;
        src = wo + (size_t)l * D_ * D_;
        dstT = o16 + (size_t)l * D_ * D_;
        R = D_; C = D_;
    } else if (bx < 4608) {
        bx -= 2304;
        src = w1 + (size_t)l * D_ * F_;
        dstT = f16a + (size_t)l * F_ * D_;
        R = D_; C = F_;
    } else {
        bx -= 4608;
        src = w2 + (size_t)l * F_ * D_;
        dstT = f16b + (size_t)l * D_ * F_;
        R = F_; C = D_;
    }
    const int cols = C / 32;
    const int cb = (bx % cols) * 32, rb = (bx / cols) * 32;
    const int tx = threadIdx.x, ty = threadIdx.y;
    #pragma unroll
    for (int i = 0; i < 32; i += 8)
        t[ty + i][tx] = src[(size_t)(rb + ty + i) * C + cb + tx];
    __syncthreads();
    #pragma unroll
    for (int i = 0; i < 32; i += 8)
        dstT[(size_t)(cb + ty + i) * R + rb + tx] = __float2half(t[tx][ty + i]);
}

// ---------------- layernorm ----------------
__device__ __forceinline__ float block_reduce_sum(float v, float* red) {
    int lane = threadIdx.x & 31;
    int wid  = threadIdx.x >> 5;
    #pragma unroll
    for (int o = 16; o; o >>= 1) v += __shfl_down_sync(0xffffffffu, v, o);
    if (lane == 0) red[wid] = v;
    __syncthreads();
    if (threadIdx.x < 32) {
        float t = (threadIdx.x < 8) ? red[threadIdx.x] : 0.0f;
        #pragma unroll
        for (int o = 4; o; o >>= 1) t += __shfl_down_sync(0xffffffffu, t, o);
        if (threadIdx.x == 0) red[32] = t;
    }
    __syncthreads();
    return red[32];
}

__global__ void ln_kernel(const float* __restrict__ x,
                          const float* __restrict__ s,
                          const float* __restrict__ b,
                          float* __restrict__ y) {
    __shared__ float red[33];
    int row = blockIdx.x;
    const float* xp = x + (size_t)row * D_;
    float v0 = xp[threadIdx.x];
    float v1 = xp[threadIdx.x + 256];
    float v2 = xp[threadIdx.x + 512];
    float mu = block_reduce_sum(v0 + v1 + v2, red) * (1.0f / D_);
    float d0 = v0 - mu, d1 = v1 - mu, d2 = v2 - mu;
    float var = block_reduce_sum(d0 * d0 + d1 * d1 + d2 * d2, red) * (1.0f / D_);
    float inv = rsqrtf(var + LN_EPS);
    float* yp = y + (size_t)row * D_;
    yp[threadIdx.x      ] = d0 * inv * s[threadIdx.x      ] + b[threadIdx.x      ];
    yp[threadIdx.x + 256] = d1 * inv * s[threadIdx.x + 256] + b[threadIdx.x + 256];
    yp[threadIdx.x + 512] = d2 * inv * s[threadIdx.x + 512] + b[threadIdx.x + 512];
}

__global__ void ln_split_kernel(const float* __restrict__ x,
                                const float* __restrict__ s,
                                const float* __restrict__ b,
                                __half* __restrict__ yhi,
                                __half* __restrict__ ylo) {
    __shared__ float red[33];
    int row = blockIdx.x;
    const float* xp = x + (size_t)row * D_;
    float v0 = xp[threadIdx.x];
    float v1 = xp[threadIdx.x + 256];
    float v2 = xp[threadIdx.x + 512];
    float mu = block_reduce_sum(v0 + v1 + v2, red) * (1.0f / D_);
    float d0 = v0 - mu, d1 = v1 - mu, d2 = v2 - mu;
    float var = block_reduce_sum(d0 * d0 + d1 * d1 + d2 * d2, red) * (1.0f / D_);
    float inv = rsqrtf(var + LN_EPS);
    size_t base = (size_t)row * D_;
    #pragma unroll
    for (int i = 0; i < 3; i++) {
        int c = threadIdx.x + i * 256;
        float dv = (i == 0 ? d0 : (i == 1 ? d1 : d2));
        float v = dv * inv * s[c] + b[c];
        __half h, l;
        split2h(v, h, l);
        yhi[base + c] = h;
        ylo[base + c] = l;
    }
}

// ---------------- asymmetric fp16 warp-mma GEMM: 2 MMAs per k16 ----------------
// C[M,N] = (Ahi+Alo)[M,K] @ W16[N,K]^T + bias
// EPI 0: write split fp16 ; EPI 1: gelu -> split fp16 ; EPI 2: +R -> fp32
template <int EPI>
__global__ __launch_bounds__(256, 2) void wmma_gemm(
    const __half* __restrict__ Ahi, const __half* __restrict__ Alo,
    const __half* __restrict__ W,
    const float* __restrict__ bias, const float* __restrict__ R,
    float* __restrict__ C,
    __half* __restrict__ Chh, __half* __restrict__ Chl,
    int Ndim, int Kdim) {
    extern __shared__ char smem[];
    const unsigned sbase = smem_u32(smem);
    const int tid = threadIdx.x;
    const int lane = tid & 31;
    const int wid = tid >> 5;
    const int warp_m = wid & 1;
    const int warp_n = wid >> 1;
    const int bm = blockIdx.y * BM;
    const int bn = blockIdx.x * BN;
    const int NK = Kdim / BK;

    const int r_ = tid >> 2, cc_ = tid & 3;
    const int r2_ = r_ + 64;
    const unsigned so1 = (unsigned)(r_ * (RS * 2) + cc_ * 16);
    const unsigned so2 = (unsigned)(r2_ * (RS * 2) + cc_ * 16);

    auto issue_stage = [&](int st) {
        const unsigned sb = sbase + (unsigned)((st & 1) * STAGE_B);
        const int k0 = st * BK;
        size_t a1 = (size_t)(bm + r_)  * Kdim + k0 + 8 * cc_;
        size_t a2 = (size_t)(bm + r2_) * Kdim + k0 + 8 * cc_;
        size_t b1 = (size_t)(bn + r_)  * Kdim + k0 + 8 * cc_;
        size_t b2 = (size_t)(bn + r2_) * Kdim + k0 + 8 * cc_;
        cp16(sb + so1,              Ahi + a1);
        cp16(sb + so2,              Ahi + a2);
        cp16(sb + TILE_B + so1,     Alo + a1);
        cp16(sb + TILE_B + so2,     Alo + a2);
        cp16(sb + 2 * TILE_B + so1, W + b1);
        cp16(sb + 2 * TILE_B + so2, W + b2);
        cp_commit();
    };

    const unsigned a_base = (unsigned)((warp_m * 64 + (lane & 15)) * (RS * 2) + (lane >> 4) * 16);
    const unsigned b_row = (unsigned)(warp_n * 32 + (lane & 7) + ((lane >> 4) << 3));
    const unsigned b_base = (unsigned)(b_row * (RS * 2) + (((lane >> 3) & 1) * 16));

    float acc[4][4][4];
    #pragma unroll
    for (int mt = 0; mt < 4; mt++)
        #pragma unroll
        for (int nt = 0; nt < 4; nt++)
            #pragma unroll
            for (int r = 0; r < 4; r++) acc[mt][nt][r] = 0.0f;

    issue_stage(0);

    for (int i = 0; i < NK; i++) {
        cp_wait<0>();
        __syncthreads();
        if (i + 1 < NK) issue_stage(i + 1);

        const unsigned tAhi = sbase + (unsigned)((i & 1) * STAGE_B);
        const unsigned tAlo = tAhi + TILE_B;
        const unsigned tW   = tAlo + TILE_B;

        #pragma unroll
        for (int ks = 0; ks < 2; ks++) {
            unsigned fbw[2][4];
            #pragma unroll
            for (int pr = 0; pr < 2; pr++) {
                unsigned bo = b_base + (unsigned)(pr * 16 * (RS * 2) + ks * 32);
                ldsm_x4(fbw[pr], tW + bo);
            }
            #pragma unroll
            for (int mt = 0; mt < 4; mt++) {
                unsigned fah[4], fal[4];
                unsigned ao = a_base + (unsigned)(mt * 16 * (RS * 2) + ks * 32);
                ldsm_x4(fah, tAhi + ao);
                ldsm_x4(fal, tAlo + ao);
                #pragma unroll
                for (int nt = 0; nt < 4; nt++) {
                    const unsigned* bW = &fbw[nt >> 1][(nt & 1) * 2];
                    mma_f16f32(acc[mt][nt], fah, bW);
                    mma_f16f32(acc[mt][nt], fal, bW);
                }
            }
        }
    }

    // ---- epilogue ----
    const int g = lane >> 2, tg = lane & 3;
    #pragma unroll
    for (int mt = 0; mt < 4; mt++) {
        #pragma unroll
        for (int nt = 0; nt < 4; nt++) {
            int row0 = bm + warp_m * 64 + mt * 16 + g;
            int col  = bn + warp_n * 32 + nt * 8 + tg * 2;
            float2 bv = *(const float2*)(bias + col);
            float c0 = acc[mt][nt][0] + bv.x;
            float c1 = acc[mt][nt][1] + bv.y;
            float c2 = acc[mt][nt][2] + bv.x;
            float c3 = acc[mt][nt][3] + bv.y;
            size_t o0 = (size_t)row0 * Ndim + col;
            size_t o1 = o0 + (size_t)8 * Ndim;
            if (EPI == 2) {
                float2 r0 = *(const float2*)(R + o0);
                float2 r1 = *(const float2*)(R + o1);
                c0 += r0.x; c1 += r0.y; c2 += r1.x; c3 += r1.y;
                *(float2*)(C + o0) = make_float2(c0, c1);
                *(float2*)(C + o1) = make_float2(c2, c3);
            } else {
                if (EPI == 1) {
                    c0 = gelu_tanh(c0); c1 = gelu_tanh(c1);
                    c2 = gelu_tanh(c2); c3 = gelu_tanh(c3);
                }
                __half h0, l0v, h1, l1v, h2, l2v, h3, l3v;
                split2h(c0, h0, l0v); split2h(c1, h1, l1v);
                split2h(c2, h2, l2v); split2h(c3, h3, l3v);
                *(unsigned*)(Chh + o0) = pack_h2(h0, h1);
                *(unsigned*)(Chl + o0) = pack_h2(l0v, l1v);
                *(unsigned*)(Chh + o1) = pack_h2(h2, h3);
                *(unsigned*)(Chl + o1) = pack_h2(l2v, l3v);
            }
        }
    }
}

// ---------------- asymmetric fp16 flash attention (Q hi/lo, K/V single fp16) ----------------
__global__ __launch_bounds__(128) void attn_mma(
    const __half* __restrict__ qh_, const __half* __restrict__ ql_,
    __half* __restrict__ oh_, __half* __restrict__ ol_) {
    extern __shared__ char smem[];
    __half* sb = (__half*)smem;
    int* kcode = (int*)(smem + AT_CODE_B);
    const unsigned sbase = smem_u32(smem);
    const int h = blockIdx.y, b = blockIdx.z;
    const int q0 = blockIdx.x * 64;
    const int tid = threadIdx.x;
    const int lane = tid & 31;
    const int warp = tid >> 5;
    const int tg2 = (lane & 3) * 2;

    const int rlast = min(q0 + 63, T_ - 1);
    const int kmax = P_ + (tok_ts(rlast) + 1) * TPS;
    const int ntiles = (kmax + 63) / 64;

    // ---- load Q tile (hi/lo fp16) ----
    for (int idx = tid; idx < 64 * 8; idx += 128) {
        int r = idx >> 3, c = idx & 7;
        int gr = min(q0 + r, T_ - 1);
        size_t src = ((size_t)(b * T_ + gr)) * (3 * D_) + h * HD_ + c * 8;
        *(uint4*)&sb[AT_QH + r * ARS + c * 8] = *(const uint4*)(qh_ + src);
        *(uint4*)&sb[AT_QL + r * ARS + c * 8] = *(const uint4*)(ql_ + src);
    }

    // ---- 2-stage K/V prefetch (hi only) ----
    auto issue_kv = [&](int it) {
        const int s = it & 1;
        const unsigned base = sbase + (unsigned)((2 + s * 2) * AT_TSZB);
        const int k0 = it * 64;
        #pragma unroll
        for (int i = 0; i < 4; i++) {
            int idx = tid + i * 128;
            int r = idx >> 3, c = idx & 7;
            int kr = min(k0 + r, T_ - 1);
            size_t src = ((size_t)(b * T_ + kr)) * (3 * D_) + D_ + h * HD_ + c * 8;
            unsigned o = (unsigned)(r * ARS * 2 + c * 16);
            cp16(base + o,           qh_ + src);        // K
            cp16(base + AT_TSZB + o, qh_ + src + D_);   // V
        }
        cp_commit();
        if (tid < 64) {
            int kg = k0 + tid;
            kcode[s * 64 + tid] = (kg < kmax)
                                ? ((tok_ts(kg) << 2) | tok_group(kg))
                                : ((0x3FFF << 2) | 3);
        }
    };

    issue_kv(0);
    __syncthreads();

    unsigned qfh[4][4], qfl[4][4];
    {
        unsigned rowoff = (unsigned)((warp * 16 + (lane & 15)) * (ARS * 2)) + (lane >> 4) * 16;
        #pragma unroll
        for (int ks = 0; ks < 4; ks++) {
            ldsm_x4(qfh[ks], sbase + AT_QH * 2 + rowoff + ks * 32);
            ldsm_x4(qfl[ks], sbase + AT_QL * 2 + rowoff + ks * 32);
        }
    }

    const int r0 = q0 + warp * 16 + (lane >> 2);
    const int r1 = r0 + 8;
    const int rc0 = min(r0, T_ - 1), rc1 = min(r1, T_ - 1);
    const int gq0 = tok_group(rc0), tq0 = tok_ts(rc0);
    const int gq1 = tok_group(rc1), tq1 = tok_ts(rc1);

    float m0 = -1e30f, m1 = -1e30f, l0 = 0.0f, l1 = 0.0f;
    float o[8][4];
    #pragma unroll
    for (int nt = 0; nt < 8; nt++)
        #pragma unroll
        for (int r = 0; r < 4; r++) o[nt][r] = 0.0f;

    const unsigned kb = (unsigned)(((lane & 7) + ((lane >> 4) << 3)) * (ARS * 2)) +
                        ((lane >> 3) & 1) * 16;

    for (int it = 0; it < ntiles; it++) {
        cp_wait<0>();
        __syncthreads();
        if (it + 1 < ntiles) issue_kv(it + 1);

        const int s = it & 1;
        const unsigned tK = sbase + (unsigned)((2 + s * 2) * AT_TSZB);
        const unsigned tV = tK + AT_TSZB;
        const int* kc = kcode + s * 64;

        // ---- scores: Qhi*K + Qlo*K ----
        float sc[8][4];
        #pragma unroll
        for (int nt = 0; nt < 8; nt++)
            #pragma unroll
            for (int r = 0; r < 4; r++) sc[nt][r] = 0.0f;

        #pragma unroll
        for (int kg = 0; kg < 4; kg++) {
            #pragma unroll
            for (int ks = 0; ks < 4; ks++) {
                unsigned kh[4];
                unsigned addr = kb + (unsigned)(kg * 16 * (ARS * 2)) + ks * 32;
                ldsm_x4(kh, tK + addr);
                #pragma unroll
                for (int half = 0; half < 2; half++) {
                    int nt = kg * 2 + half;
                    mma_f16f32(sc[nt], qfh[ks], &kh[half * 2]);
                    mma_f16f32(sc[nt], qfl[ks], &kh[half * 2]);
                }
            }
        }

        // ---- mask + scale ----
        #pragma unroll
        for (int nt = 0; nt < 8; nt++) {
            int kc0 = kc[nt * 8 + tg2];
            int kc1 = kc[nt * 8 + tg2 + 1];
            sc[nt][0] = allow_code(gq0, tq0, kc0) ? sc[nt][0] * ATT_SCALE : -1e30f;
            sc[nt][1] = allow_code(gq0, tq0, kc1) ? sc[nt][1] * ATT_SCALE : -1e30f;
            sc[nt][2] = allow_code(gq1, tq1, kc0) ? sc[nt][2] * ATT_SCALE : -1e30f;
            sc[nt][3] = allow_code(gq1, tq1, kc1) ? sc[nt][3] * ATT_SCALE : -1e30f;
        }

        // ---- online softmax ----
        float mx0 = -1e30f, mx1 = -1e30f;
        #pragma unroll
        for (int nt = 0; nt < 8; nt++) {
            mx0 = fmaxf(mx0, fmaxf(sc[nt][0], sc[nt][1]));
            mx1 = fmaxf(mx1, fmaxf(sc[nt][2], sc[nt][3]));
        }
        mx0 = fmaxf(mx0, __shfl_xor_sync(0xffffffffu, mx0, 1));
        mx0 = fmaxf(mx0, __shfl_xor_sync(0xffffffffu, mx0, 2));
        mx1 = fmaxf(mx1, __shfl_xor_sync(0xffffffffu, mx1, 1));
        mx1 = fmaxf(mx1, __shfl_xor_sync(0xffffffffu, mx1, 2));
        float mn0 = fmaxf(m0, mx0), mn1 = fmaxf(m1, mx1);
        float corr0 = __expf(m0 - mn0), corr1 = __expf(m1 - mn1);
        m0 = mn0; m1 = mn1;
        l0 *= corr0; l1 *= corr1;
        #pragma unroll
        for (int nt = 0; nt < 8; nt++) {
            o[nt][0] *= corr0; o[nt][1] *= corr0;
            o[nt][2] *= corr1; o[nt][3] *= corr1;
        }

        // ---- P (hi/lo fp16), O += Phi*V + Plo*V ----
        #pragma unroll
        for (int kv = 0; kv < 4; kv++) {
            unsigned ph[4], pl[4];
            #pragma unroll
            for (int half = 0; half < 2; half++) {
                int nt = kv * 2 + half;
                float p0 = __expf(sc[nt][0] - m0);
                float p1 = __expf(sc[nt][1] - m0);
                float p2 = __expf(sc[nt][2] - m1);
                float p3 = __expf(sc[nt][3] - m1);
                l0 += p0 + p1;
                l1 += p2 + p3;
                __half h0, lo0, h1, lo1, h2, lo2, h3, lo3;
                split2h(p0, h0, lo0); split2h(p1, h1, lo1);
                split2h(p2, h2, lo2); split2h(p3, h3, lo3);
                ph[half * 2 + 0] = pack_h2(h0, h1);
                ph[half * 2 + 1] = pack_h2(h2, h3);
                pl[half * 2 + 0] = pack_h2(lo0, lo1);
                pl[half * 2 + 1] = pack_h2(lo2, lo3);
            }
            #pragma unroll
            for (int dg = 0; dg < 4; dg++) {
                unsigned vh[4];
                unsigned addr = kb + (unsigned)(kv * 16 * (ARS * 2)) + dg * 32;
                ldsm_x4t(vh, tV + addr);
                #pragma unroll
                for (int half = 0; half < 2; half++) {
                    int nt = dg * 2 + half;
                    unsigned bp[2] = {vh[half], vh[2 + half]};
                    mma_f16f32(o[nt], ph, bp);
                    mma_f16f32(o[nt], pl, bp);
                }
            }
        }
    }

    // ---- finalize ----
    l0 += __shfl_xor_sync(0xffffffffu, l0, 1);
    l0 += __shfl_xor_sync(0xffffffffu, l0, 2);
    l1 += __shfl_xor_sync(0xffffffffu, l1, 1);
    l1 += __shfl_xor_sync(0xffffffffu, l1, 2);
    float li0 = 1.0f / l0, li1 = 1.0f / l1;

    #pragma unroll
    for (int nt = 0; nt < 8; nt++) {
        int d = h * HD_ + nt * 8 + tg2;
        if (r0 < T_) {
            size_t off = ((size_t)(b * T_ + r0)) * D_ + d;
            float v0 = o[nt][0] * li0, v1 = o[nt][1] * li0;
            __half h0, lo0, h1, lo1;
            split2h(v0, h0, lo0); split2h(v1, h1, lo1);
            *(unsigned*)(oh_ + off) = pack_h2(h0, h1);
            *(unsigned*)(ol_ + off) = pack_h2(lo0, lo1);
        }
        if (r1 < T_) {
            size_t off = ((size_t)(b * T_ + r1)) * D_ + d;
            float v2 = o[nt][2] * li1, v3 = o[nt][3] * li1;
            __half h2, lo2, h3, lo3;
            split2h(v2, h2, lo2); split2h(v3, h3, lo3);
            *(unsigned*)(oh_ + off) = pack_h2(h2, h3);
            *(unsigned*)(ol_ + off) = pack_h2(lo2, lo3);
        }
    }
}

// ---------------- host orchestration ----------------
extern "C" void kernel_launch(void* const* d_in, const int* in_sizes, int n_in,
                              void* d_out, int out_size) {
    (void)in_sizes; (void)n_in; (void)out_size;

    const float* prefix = (const float*)d_in[0];
    const float* obs    = (const float*)d_in[2];
    const float* rdo    = (const float*)d_in[4];
    const float* ln1_s  = (const float*)d_in[6];
    const float* ln1_b  = (const float*)d_in[7];
    const float* wqkv   = (const float*)d_in[8];
    const float* bqkv   = (const float*)d_in[9];
    const float* wo     = (const float*)d_in[10];
    const float* bo     = (const float*)d_in[11];
    const float* ln2_s  = (const float*)d_in[12];
    const float* ln2_b  = (const float*)d_in[13];
    const float* w1     = (const float*)d_in[14];
    const float* b1     = (const float*)d_in[15];
    const float* w2     = (const float*)d_in[16];
    const float* b2     = (const float*)d_in[17];
    const float* lnf_s  = (const float*)d_in[18];
    const float* lnf_b  = (const float*)d_in[19];
    float* out = (float*)d_out;

    float* x;
    __half *yhi, *ylo, *atthi, *attlo, *ffnhi, *ffnlo, *qkvhi, *qkvlo;
    __half *wqkvT, *woT, *w1T, *w2T;
    cudaGetSymbolAddress((void**)&x,     g_x);
    cudaGetSymbolAddress((void**)&yhi,   g_y_hi);
    cudaGetSymbolAddress((void**)&ylo,   g_y_lo);
    cudaGetSymbolAddress((void**)&qkvhi, g_qkv_hi);
    cudaGetSymbolAddress((void**)&qkvlo, g_qkv_lo);
    cudaGetSymbolAddress((void**)&atthi, g_att_hi);
    cudaGetSymbolAddress((void**)&attlo, g_att_lo);
    cudaGetSymbolAddress((void**)&ffnhi, g_ffn_hi);
    cudaGetSymbolAddress((void**)&ffnlo, g_ffn_lo);
    cudaGetSymbolAddress((void**)&wqkvT, g_wqkvT);
    cudaGetSymbolAddress((void**)&woT,   g_woT);
    cudaGetSymbolAddress((void**)&w1T,   g_w1T);
    cudaGetSymbolAddress((void**)&w2T,   g_w2T);

    cudaFuncSetAttribute(wmma_gemm<0>, cudaFuncAttributeMaxDynamicSharedMemorySize, SMEM_GEMM);
    cudaFuncSetAttribute(wmma_gemm<1>, cudaFuncAttributeMaxDynamicSharedMemorySize, SMEM_GEMM);
    cudaFuncSetAttribute(wmma_gemm<2>, cudaFuncAttributeMaxDynamicSharedMemorySize, SMEM_GEMM);
    cudaFuncSetAttribute(attn_mma, cudaFuncAttributeMaxDynamicSharedMemorySize, ATTN_SMEM);

    assemble_kernel<<<2048, 256>>>(prefix, obs, rdo);

    wconv_all_kernel<<<dim3(6912, L_), dim3(32, 8)>>>(
        wqkv, wo, w1, w2, wqkvT, woT, w1T, w2T);

    const dim3 g_qkv_grid(3 * D_ / BN, M_ / BM);   // (18, 86)
    const dim3 g_wo_grid (D_ / BN,     M_ / BM);   // (6, 86)
    const dim3 g_w1_grid (F_ / BN,     M_ / BM);   // (24, 86)
    const dim3 g_attn((T_ + 63) / 64, NH_, B_);    // (22, 12, 8)

    for (int l = 0; l < L_; l++) {
        ln_split_kernel<<<M_, 256>>>(x, ln1_s + (size_t)l * D_, ln1_b + (size_t)l * D_, yhi, ylo);
        wmma_gemm<0><<<g_qkv_grid, 256, SMEM_GEMM>>>(
            yhi, ylo, wqkvT + (size_t)l * 3 * D_ * D_,
            bqkv + (size_t)l * 3 * D_, nullptr, nullptr,
            qkvhi, qkvlo, 3 * D_, D_);
        attn_mma<<<g_attn, 128, ATTN_SMEM>>>(qkvhi, qkvlo, atthi, attlo);
        wmma_gemm<2><<<g_wo_grid, 256, SMEM_GEMM>>>(
            atthi, attlo, woT + (size_t)l * D_ * D_,
            bo + (size_t)l * D_, x, x,
            nullptr, nullptr, D_, D_);
        ln_split_kernel<<<M_, 256>>>(x, ln2_s + (size_t)l * D_, ln2_b + (size_t)l * D_, yhi, ylo);
        wmma_gemm<1><<<g_w1_grid, 256, SMEM_GEMM>>>(
            yhi, ylo, w1T + (size_t)l * F_ * D_,
            b1 + (size_t)l * F_, nullptr, nullptr,
            ffnhi, ffnlo, F_, D_);
        wmma_gemm<2><<<g_wo_grid, 256, SMEM_GEMM>>>(
            ffnhi, ffnlo, w2T + (size_t)l * D_ * F_,
            b2 + (size_t)l * D_, x, x,
            nullptr, nullptr, D_, F_);
    }

    ln_kernel<<<M_, 256>>>(x, lnf_s, lnf_b, out);
}

// round 15
// speedup vs baseline: 4.6990x; 1.4199x over previous
#include <cuda_runtime.h>
#include <cuda_fp16.h>
#include <math.h>
#include <stdint.h>

// ---------------- problem constants ----------------
namespace {
constexpr int B_  = 8;
constexpr int P_  = 16;
constexpr int HOR = 10;
constexpr int NO_ = 128;
constexpr int NR_ = 8;
constexpr int D_  = 768;
constexpr int NH_ = 12;
constexpr int HD_ = 64;
constexpr int F_  = 3072;
constexpr int L_  = 12;
constexpr int TPS = NO_ + NR_;          // 136
constexpr int T_  = P_ + HOR * TPS;     // 1376
constexpr int M_  = B_ * T_;            // 11008
constexpr float LN_EPS = 1e-6f;
constexpr float ATT_SCALE = 0.125f;     // 1/sqrt(64)

// GEMM tiling: 256 threads, 2x4 warp grid, BK=32, 2-stage cp.async, 2 CTAs/SM
// operands: A = single fp16 (1 tile), W = single fp16 (1 tile) -> 1 MMA per k16
constexpr int BM = 128;
constexpr int BN = 128;
constexpr int BK = 32;
constexpr int RS = 40;                   // SMEM row stride in fp16 (80B), conflict-free ldmatrix
constexpr int TILE_B = 128 * RS * 2;     // 10240 bytes per operand tile
constexpr int STAGE_B = 2 * TILE_B;      // A, W = 20480
constexpr int SMEM_GEMM = 2 * STAGE_B;   // 40960

// attention smem: Q (hi/lo) + 2-stage (K,V single fp16) + double-buffered key codes
constexpr int ARS   = 72;                // 144B row stride, conflict-free
constexpr int ATSZ  = 64 * ARS;          // fp16 units per tile quarter (4608)
constexpr int AT_QH = 0;
constexpr int AT_QL = ATSZ;
constexpr int AT_TSZB = ATSZ * 2;        // 9216 bytes per tile quarter
constexpr int AT_CODE_B = 6 * AT_TSZB;   // 55296
constexpr int ATTN_SMEM = AT_CODE_B + 2 * 64 * 4;   // 55808 bytes
}

// ---------------- scratch (device globals: no cudaMalloc allowed) ----------------
__device__ float g_x[(size_t)M_ * D_];
// single-fp16 activations (GEMM A operands)
__device__ __half g_y  [(size_t)M_ * D_];
__device__ __half g_att[(size_t)M_ * D_];
__device__ __half g_ffn[(size_t)M_ * F_];
// qkv split fp16 (attention: Q uses hi+lo; K,V use hi only)
__device__ __half g_qkv_hi[(size_t)M_ * 3 * D_];
__device__ __half g_qkv_lo[(size_t)M_ * 3 * D_];
// single-fp16 transposed weights [N, K]
__device__ __half g_wqkvT[(size_t)L_ * 3 * D_ * D_];
__device__ __half g_woT  [(size_t)L_ * D_ * D_];
__device__ __half g_w1T  [(size_t)L_ * F_ * D_];
__device__ __half g_w2T  [(size_t)L_ * D_ * F_];

// ---------------- mma / async helpers ----------------
__device__ __forceinline__ unsigned smem_u32(const void* p) {
    return (unsigned)__cvta_generic_to_shared(p);
}
__device__ __forceinline__ void ldsm_x4(unsigned* r, unsigned addr) {
    asm volatile("ldmatrix.sync.aligned.m8n8.x4.shared.b16 {%0,%1,%2,%3}, [%4];"
                 : "=r"(r[0]), "=r"(r[1]), "=r"(r[2]), "=r"(r[3]) : "r"(addr));
}
__device__ __forceinline__ void ldsm_x4t(unsigned* r, unsigned addr) {
    asm volatile("ldmatrix.sync.aligned.m8n8.x4.trans.shared.b16 {%0,%1,%2,%3}, [%4];"
                 : "=r"(r[0]), "=r"(r[1]), "=r"(r[2]), "=r"(r[3]) : "r"(addr));
}
__device__ __forceinline__ void mma_f16f32(float* c, const unsigned* a, const unsigned* b) {
    asm volatile(
        "mma.sync.aligned.m16n8k16.row.col.f32.f16.f16.f32 "
        "{%0,%1,%2,%3}, {%4,%5,%6,%7}, {%8,%9}, {%0,%1,%2,%3};"
        : "+f"(c[0]), "+f"(c[1]), "+f"(c[2]), "+f"(c[3])
        : "r"(a[0]), "r"(a[1]), "r"(a[2]), "r"(a[3]), "r"(b[0]), "r"(b[1]));
}
__device__ __forceinline__ void cp16(unsigned saddr, const void* g) {
    asm volatile("cp.async.cg.shared.global [%0], [%1], 16;" :: "r"(saddr), "l"(g));
}
__device__ __forceinline__ void cp_commit() {
    asm volatile("cp.async.commit_group;" ::: "memory");
}
template <int N>
__device__ __forceinline__ void cp_wait() {
    asm volatile("cp.async.wait_group %0;" :: "n"(N) : "memory");
}
__device__ __forceinline__ unsigned pack_h2(__half a, __half b) {
    __half2 t(a, b);
    return *(unsigned*)&t;
}
__device__ __forceinline__ void split2h(float v, __half& h, __half& l) {
    h = __float2half(v);
    l = __float2half(v - __half2float(h));
}

// ---------------- misc helpers ----------------
__device__ __forceinline__ float gelu_tanh(float x) {
    float x3 = x * x * x;
    return 0.5f * x * (1.0f + tanhf(0.7978845608028654f * (x + 0.044715f * x3)));
}
__device__ __forceinline__ int tok_group(int i) {
    if (i < P_) return 0;
    return (((i - P_) % TPS) < NO_) ? 1 : 2;
}
__device__ __forceinline__ int tok_ts(int i) {
    return (i < P_) ? -1 : (i - P_) / TPS;
}
__device__ __forceinline__ bool allow_code(int gq, int tq, int kc) {
    int gk = kc & 3;
    int tk = kc >> 2;
    if (gk == 0) return true;
    if (gq == 0) return false;
    if (tk > tq) return false;
    return (gk == 1) || (gq == 2);
}

// ---------------- assemble ----------------
__global__ void assemble_kernel(const float* __restrict__ prefix,
                                const float* __restrict__ obs,
                                const float* __restrict__ rdo) {
    for (int idx = blockIdx.x * blockDim.x + threadIdx.x;
         idx < M_ * D_; idx += gridDim.x * blockDim.x) {
        int d = idx % D_;
        int bt = idx / D_;
        int t = bt % T_;
        int b = bt / T_;
        float v;
        if (t < P_) {
            v = prefix[((size_t)b * P_ + t) * D_ + d];
        } else {
            int tt = t - P_;
            int ho = tt / TPS;
            int r  = tt % TPS;
            if (r < NO_)
                v = obs[(((size_t)b * HOR + ho) * NO_ + r) * D_ + d];
            else
                v = rdo[(((size_t)b * HOR + ho) * NR_ + (r - NO_)) * D_ + d];
        }
        g_x[idx] = v;
    }
}

// ---------------- fused weight transpose + fp16 convert ----------------
__global__ void wconv_all_kernel(const float* __restrict__ wqkv, const float* __restrict__ wo,
                                 const float* __restrict__ w1, const float* __restrict__ w2,
                                 __half* __restrict__ q16, __half* __restrict__ o16,
                                 __half* __restrict__ f16a, __half* __restrict__ f16b) {
    __shared__ float t[32][33];
    const int l = blockIdx.y;
    int bx = blockIdx.x;
    const float* src;
    __half* dstT;
    int R, C;
    if (bx < 1728) {
        src = wqkv + (size_t)l * D_ * 3 * D_;
        dstT = q16 + (size_t)l * 3 * D_ * D_;
        R = D_; C = 3 * D_;
    } else if (bx < 2304) {
        bx -= 1728;
        src = wo + (size_t)l * D_ * D_;
        dstT = o16 + (size_t)l * D_ * D_;
        R = D_; C = D_;
    } else if (bx < 4608) {
        bx -= 2304;
        src = w1 + (size_t)l * D_ * F_;
        dstT = f16a + (size_t)l * F_ * D_;
        R = D_; C = F_;
    } else {
        bx -= 4608;
        src = w2 + (size_t)l * F_ * D_;
        dstT = f16b + (size_t)l * D_ * F_;
        R = F_; C = D_;
    }
    const int cols = C / 32;
    const int cb = (bx % cols) * 32, rb = (bx / cols) * 32;
    const int tx = threadIdx.x, ty = threadIdx.y;
    #pragma unroll
    for (int i = 0; i < 32; i += 8)
        t[ty + i][tx] = src[(size_t)(rb + ty + i) * C + cb + tx];
    __syncthreads();
    #pragma unroll
    for (int i = 0; i < 32; i += 8)
        dstT[(size_t)(cb + ty + i) * R + rb + tx] = __float2half(t[tx][ty + i]);
}

// ---------------- layernorm ----------------
__device__ __forceinline__ float block_reduce_sum(float v, float* red) {
    int lane = threadIdx.x & 31;
    int wid  = threadIdx.x >> 5;
    #pragma unroll
    for (int o = 16; o; o >>= 1) v += __shfl_down_sync(0xffffffffu, v, o);
    if (lane == 0) red[wid] = v;
    __syncthreads();
    if (threadIdx.x < 32) {
        float t = (threadIdx.x < 8) ? red[threadIdx.x] : 0.0f;
        #pragma unroll
        for (int o = 4; o; o >>= 1) t += __shfl_down_sync(0xffffffffu, t, o);
        if (threadIdx.x == 0) red[32] = t;
    }
    __syncthreads();
    return red[32];
}

__global__ void ln_kernel(const float* __restrict__ x,
                          const float* __restrict__ s,
                          const float* __restrict__ b,
                          float* __restrict__ y) {
    __shared__ float red[33];
    int row = blockIdx.x;
    const float* xp = x + (size_t)row * D_;
    float v0 = xp[threadIdx.x];
    float v1 = xp[threadIdx.x + 256];
    float v2 = xp[threadIdx.x + 512];
    float mu = block_reduce_sum(v0 + v1 + v2, red) * (1.0f / D_);
    float d0 = v0 - mu, d1 = v1 - mu, d2 = v2 - mu;
    float var = block_reduce_sum(d0 * d0 + d1 * d1 + d2 * d2, red) * (1.0f / D_);
    float inv = rsqrtf(var + LN_EPS);
    float* yp = y + (size_t)row * D_;
    yp[threadIdx.x      ] = d0 * inv * s[threadIdx.x      ] + b[threadIdx.x      ];
    yp[threadIdx.x + 256] = d1 * inv * s[threadIdx.x + 256] + b[threadIdx.x + 256];
    yp[threadIdx.x + 512] = d2 * inv * s[threadIdx.x + 512] + b[threadIdx.x + 512];
}

// LN -> single fp16
__global__ void ln_h_kernel(const float* __restrict__ x,
                            const float* __restrict__ s,
                            const float* __restrict__ b,
                            __half* __restrict__ y) {
    __shared__ float red[33];
    int row = blockIdx.x;
    const float* xp = x + (size_t)row * D_;
    float v0 = xp[threadIdx.x];
    float v1 = xp[threadIdx.x + 256];
    float v2 = xp[threadIdx.x + 512];
    float mu = block_reduce_sum(v0 + v1 + v2, red) * (1.0f / D_);
    float d0 = v0 - mu, d1 = v1 - mu, d2 = v2 - mu;
    float var = block_reduce_sum(d0 * d0 + d1 * d1 + d2 * d2, red) * (1.0f / D_);
    float inv = rsqrtf(var + LN_EPS);
    size_t base = (size_t)row * D_;
    y[base + threadIdx.x      ] = __float2half(d0 * inv * s[threadIdx.x      ] + b[threadIdx.x      ]);
    y[base + threadIdx.x + 256] = __float2half(d1 * inv * s[threadIdx.x + 256] + b[threadIdx.x + 256]);
    y[base + threadIdx.x + 512] = __float2half(d2 * inv * s[threadIdx.x + 512] + b[threadIdx.x + 512]);
}

// ---------------- pure fp16 warp-mma GEMM: 1 MMA per k16 ----------------
// C[M,N] = A16[M,K] @ W16[N,K]^T + bias
// EPI 0: write split fp16 (qkv hi/lo) ; EPI 1: gelu -> single fp16 ; EPI 2: +R -> fp32
template <int EPI>
__global__ __launch_bounds__(256, 2) void wmma_gemm(
    const __half* __restrict__ A,
    const __half* __restrict__ W,
    const float* __restrict__ bias, const float* __restrict__ R,
    float* __restrict__ C,
    __half* __restrict__ Chh, __half* __restrict__ Chl,
    int Ndim, int Kdim) {
    extern __shared__ char smem[];
    const unsigned sbase = smem_u32(smem);
    const int tid = threadIdx.x;
    const int lane = tid & 31;
    const int wid = tid >> 5;
    const int warp_m = wid & 1;
    const int warp_n = wid >> 1;
    const int bm = blockIdx.y * BM;
    const int bn = blockIdx.x * BN;
    const int NK = Kdim / BK;

    const int r_ = tid >> 2, cc_ = tid & 3;
    const int r2_ = r_ + 64;
    const unsigned so1 = (unsigned)(r_ * (RS * 2) + cc_ * 16);
    const unsigned so2 = (unsigned)(r2_ * (RS * 2) + cc_ * 16);

    auto issue_stage = [&](int st) {
        const unsigned sb = sbase + (unsigned)((st & 1) * STAGE_B);
        const int k0 = st * BK;
        size_t a1 = (size_t)(bm + r_)  * Kdim + k0 + 8 * cc_;
        size_t a2 = (size_t)(bm + r2_) * Kdim + k0 + 8 * cc_;
        size_t b1 = (size_t)(bn + r_)  * Kdim + k0 + 8 * cc_;
        size_t b2 = (size_t)(bn + r2_) * Kdim + k0 + 8 * cc_;
        cp16(sb + so1,          A + a1);
        cp16(sb + so2,          A + a2);
        cp16(sb + TILE_B + so1, W + b1);
        cp16(sb + TILE_B + so2, W + b2);
        cp_commit();
    };

    const unsigned a_base = (unsigned)((warp_m * 64 + (lane & 15)) * (RS * 2) + (lane >> 4) * 16);
    const unsigned b_row = (unsigned)(warp_n * 32 + (lane & 7) + ((lane >> 4) << 3));
    const unsigned b_base = (unsigned)(b_row * (RS * 2) + (((lane >> 3) & 1) * 16));

    float acc[4][4][4];
    #pragma unroll
    for (int mt = 0; mt < 4; mt++)
        #pragma unroll
        for (int nt = 0; nt < 4; nt++)
            #pragma unroll
            for (int r = 0; r < 4; r++) acc[mt][nt][r] = 0.0f;

    issue_stage(0);

    for (int i = 0; i < NK; i++) {
        cp_wait<0>();
        __syncthreads();
        if (i + 1 < NK) issue_stage(i + 1);

        const unsigned tA = sbase + (unsigned)((i & 1) * STAGE_B);
        const unsigned tW = tA + TILE_B;

        #pragma unroll
        for (int ks = 0; ks < 2; ks++) {
            unsigned fbw[2][4];
            #pragma unroll
            for (int pr = 0; pr < 2; pr++) {
                unsigned bo = b_base + (unsigned)(pr * 16 * (RS * 2) + ks * 32);
                ldsm_x4(fbw[pr], tW + bo);
            }
            #pragma unroll
            for (int mt = 0; mt < 4; mt++) {
                unsigned fa[4];
                unsigned ao = a_base + (unsigned)(mt * 16 * (RS * 2) + ks * 32);
                ldsm_x4(fa, tA + ao);
                #pragma unroll
                for (int nt = 0; nt < 4; nt++)
                    mma_f16f32(acc[mt][nt], fa, &fbw[nt >> 1][(nt & 1) * 2]);
            }
        }
    }

    // ---- epilogue ----
    const int g = lane >> 2, tg = lane & 3;
    #pragma unroll
    for (int mt = 0; mt < 4; mt++) {
        #pragma unroll
        for (int nt = 0; nt < 4; nt++) {
            int row0 = bm + warp_m * 64 + mt * 16 + g;
            int col  = bn + warp_n * 32 + nt * 8 + tg * 2;
            float2 bv = *(const float2*)(bias + col);
            float c0 = acc[mt][nt][0] + bv.x;
            float c1 = acc[mt][nt][1] + bv.y;
            float c2 = acc[mt][nt][2] + bv.x;
            float c3 = acc[mt][nt][3] + bv.y;
            size_t o0 = (size_t)row0 * Ndim + col;
            size_t o1 = o0 + (size_t)8 * Ndim;
            if (EPI == 2) {
                float2 r0 = *(const float2*)(R + o0);
                float2 r1 = *(const float2*)(R + o1);
                c0 += r0.x; c1 += r0.y; c2 += r1.x; c3 += r1.y;
                *(float2*)(C + o0) = make_float2(c0, c1);
                *(float2*)(C + o1) = make_float2(c2, c3);
            } else if (EPI == 0) {
                __half h0, l0v, h1, l1v, h2, l2v, h3, l3v;
                split2h(c0, h0, l0v); split2h(c1, h1, l1v);
                split2h(c2, h2, l2v); split2h(c3, h3, l3v);
                *(unsigned*)(Chh + o0) = pack_h2(h0, h1);
                *(unsigned*)(Chl + o0) = pack_h2(l0v, l1v);
                *(unsigned*)(Chh + o1) = pack_h2(h2, h3);
                *(unsigned*)(Chl + o1) = pack_h2(l2v, l3v);
            } else {
                c0 = gelu_tanh(c0); c1 = gelu_tanh(c1);
                c2 = gelu_tanh(c2); c3 = gelu_tanh(c3);
                *(unsigned*)(Chh + o0) = pack_h2(__float2half(c0), __float2half(c1));
                *(unsigned*)(Chh + o1) = pack_h2(__float2half(c2), __float2half(c3));
            }
        }
    }
}

// ---------------- asymmetric fp16 flash attention (Q hi/lo, K/V single fp16) ----------------
// output: single fp16 (att)
__global__ __launch_bounds__(128) void attn_mma(
    const __half* __restrict__ qh_, const __half* __restrict__ ql_,
    __half* __restrict__ o_) {
    extern __shared__ char smem[];
    __half* sb = (__half*)smem;
    int* kcode = (int*)(smem + AT_CODE_B);
    const unsigned sbase = smem_u32(smem);
    const int h = blockIdx.y, b = blockIdx.z;
    const int q0 = blockIdx.x * 64;
    const int tid = threadIdx.x;
    const int lane = tid & 31;
    const int warp = tid >> 5;
    const int tg2 = (lane & 3) * 2;

    const int rlast = min(q0 + 63, T_ - 1);
    const int kmax = P_ + (tok_ts(rlast) + 1) * TPS;
    const int ntiles = (kmax + 63) / 64;

    for (int idx = tid; idx < 64 * 8; idx += 128) {
        int r = idx >> 3, c = idx & 7;
        int gr = min(q0 + r, T_ - 1);
        size_t src = ((size_t)(b * T_ + gr)) * (3 * D_) + h * HD_ + c * 8;
        *(uint4*)&sb[AT_QH + r * ARS + c * 8] = *(const uint4*)(qh_ + src);
        *(uint4*)&sb[AT_QL + r * ARS + c * 8] = *(const uint4*)(ql_ + src);
    }

    auto issue_kv = [&](int it) {
        const int s = it & 1;
        const unsigned base = sbase + (unsigned)((2 + s * 2) * AT_TSZB);
        const int k0 = it * 64;
        #pragma unroll
        for (int i = 0; i < 4; i++) {
            int idx = tid + i * 128;
            int r = idx >> 3, c = idx & 7;
            int kr = min(k0 + r, T_ - 1);
            size_t src = ((size_t)(b * T_ + kr)) * (3 * D_) + D_ + h * HD_ + c * 8;
            unsigned o = (unsigned)(r * ARS * 2 + c * 16);
            cp16(base + o,           qh_ + src);        // K
            cp16(base + AT_TSZB + o, qh_ + src + D_);   // V
        }
        cp_commit();
        if (tid < 64) {
            int kg = k0 + tid;
            kcode[s * 64 + tid] = (kg < kmax)
                                ? ((tok_ts(kg) << 2) | tok_group(kg))
                                : ((0x3FFF << 2) | 3);
        }
    };

    issue_kv(0);
    __syncthreads();

    unsigned qfh[4][4], qfl[4][4];
    {
        unsigned rowoff = (unsigned)((warp * 16 + (lane & 15)) * (ARS * 2)) + (lane >> 4) * 16;
        #pragma unroll
        for (int ks = 0; ks < 4; ks++) {
            ldsm_x4(qfh[ks], sbase + AT_QH * 2 + rowoff + ks * 32);
            ldsm_x4(qfl[ks], sbase + AT_QL * 2 + rowoff + ks * 32);
        }
    }

    const int r0 = q0 + warp * 16 + (lane >> 2);
    const int r1 = r0 + 8;
    const int rc0 = min(r0, T_ - 1), rc1 = min(r1, T_ - 1);
    const int gq0 = tok_group(rc0), tq0 = tok_ts(rc0);
    const int gq1 = tok_group(rc1), tq1 = tok_ts(rc1);

    float m0 = -1e30f, m1 = -1e30f, l0 = 0.0f, l1 = 0.0f;
    float o[8][4];
    #pragma unroll
    for (int nt = 0; nt < 8; nt++)
        #pragma unroll
        for (int r = 0; r < 4; r++) o[nt][r] = 0.0f;

    const unsigned kb = (unsigned)(((lane & 7) + ((lane >> 4) << 3)) * (ARS * 2)) +
                        ((lane >> 3) & 1) * 16;

    for (int it = 0; it < ntiles; it++) {
        cp_wait<0>();
        __syncthreads();
        if (it + 1 < ntiles) issue_kv(it + 1);

        const int s = it & 1;
        const unsigned tK = sbase + (unsigned)((2 + s * 2) * AT_TSZB);
        const unsigned tV = tK + AT_TSZB;
        const int* kc = kcode + s * 64;

        float sc[8][4];
        #pragma unroll
        for (int nt = 0; nt < 8; nt++)
            #pragma unroll
            for (int r = 0; r < 4; r++) sc[nt][r] = 0.0f;

        #pragma unroll
        for (int kg = 0; kg < 4; kg++) {
            #pragma unroll
            for (int ks = 0; ks < 4; ks++) {
                unsigned kh[4];
                unsigned addr = kb + (unsigned)(kg * 16 * (ARS * 2)) + ks * 32;
                ldsm_x4(kh, tK + addr);
                #pragma unroll
                for (int half = 0; half < 2; half++) {
                    int nt = kg * 2 + half;
                    mma_f16f32(sc[nt], qfh[ks], &kh[half * 2]);
                    mma_f16f32(sc[nt], qfl[ks], &kh[half * 2]);
                }
            }
        }

        #pragma unroll
        for (int nt = 0; nt < 8; nt++) {
            int kc0 = kc[nt * 8 + tg2];
            int kc1 = kc[nt * 8 + tg2 + 1];
            sc[nt][0] = allow_code(gq0, tq0, kc0) ? sc[nt][0] * ATT_SCALE : -1e30f;
            sc[nt][1] = allow_code(gq0, tq0, kc1) ? sc[nt][1] * ATT_SCALE : -1e30f;
            sc[nt][2] = allow_code(gq1, tq1, kc0) ? sc[nt][2] * ATT_SCALE : -1e30f;
            sc[nt][3] = allow_code(gq1, tq1, kc1) ? sc[nt][3] * ATT_SCALE : -1e30f;
        }

        float mx0 = -1e30f, mx1 = -1e30f;
        #pragma unroll
        for (int nt = 0; nt < 8; nt++) {
            mx0 = fmaxf(mx0, fmaxf(sc[nt][0], sc[nt][1]));
            mx1 = fmaxf(mx1, fmaxf(sc[nt][2], sc[nt][3]));
        }
        mx0 = fmaxf(mx0, __shfl_xor_sync(0xffffffffu, mx0, 1));
        mx0 = fmaxf(mx0, __shfl_xor_sync(0xffffffffu, mx0, 2));
        mx1 = fmaxf(mx1, __shfl_xor_sync(0xffffffffu, mx1, 1));
        mx1 = fmaxf(mx1, __shfl_xor_sync(0xffffffffu, mx1, 2));
        float mn0 = fmaxf(m0, mx0), mn1 = fmaxf(m1, mx1);
        float corr0 = __expf(m0 - mn0), corr1 = __expf(m1 - mn1);
        m0 = mn0; m1 = mn1;
        l0 *= corr0; l1 *= corr1;
        #pragma unroll
        for (int nt = 0; nt < 8; nt++) {
            o[nt][0] *= corr0; o[nt][1] *= corr0;
            o[nt][2] *= corr1; o[nt][3] *= corr1;
        }

        #pragma unroll
        for (int kv = 0; kv < 4; kv++) {
            unsigned ph[4], pl[4];
            #pragma unroll
            for (int half = 0; half < 2; half++) {
                int nt = kv * 2 + half;
                float p0 = __expf(sc[nt][0] - m0);
                float p1 = __expf(sc[nt][1] - m0);
                float p2 = __expf(sc[nt][2] - m1);
                float p3 = __expf(sc[nt][3] - m1);
                l0 += p0 + p1;
                l1 += p2 + p3;
                __half h0, lo0, h1, lo1, h2, lo2, h3, lo3;
                split2h(p0, h0, lo0); split2h(p1, h1, lo1);
                split2h(p2, h2, lo2); split2h(p3, h3, lo3);
                ph[half * 2 + 0] = pack_h2(h0, h1);
                ph[half * 2 + 1] = pack_h2(h2, h3);
                pl[half * 2 + 0] = pack_h2(lo0, lo1);
                pl[half * 2 + 1] = pack_h2(lo2, lo3);
            }
            #pragma unroll
            for (int dg = 0; dg < 4; dg++) {
                unsigned vh[4];
                unsigned addr = kb + (unsigned)(kv * 16 * (ARS * 2)) + dg * 32;
                ldsm_x4t(vh, tV + addr);
                #pragma unroll
                for (int half = 0; half < 2; half++) {
                    int nt = dg * 2 + half;
                    unsigned bp[2] = {vh[half], vh[2 + half]};
                    mma_f16f32(o[nt], ph, bp);
                    mma_f16f32(o[nt], pl, bp);
                }
            }
        }
    }

    l0 += __shfl_xor_sync(0xffffffffu, l0, 1);
    l0 += __shfl_xor_sync(0xffffffffu, l0, 2);
    l1 += __shfl_xor_sync(0xffffffffu, l1, 1);
    l1 += __shfl_xor_sync(0xffffffffu, l1, 2);
    float li0 = 1.0f / l0, li1 = 1.0f / l1;

    #pragma unroll
    for (int nt = 0; nt < 8; nt++) {
        int d = h * HD_ + nt * 8 + tg2;
        if (r0 < T_) {
            size_t off = ((size_t)(b * T_ + r0)) * D_ + d;
            *(unsigned*)(o_ + off) = pack_h2(__float2half(o[nt][0] * li0),
                                             __float2half(o[nt][1] * li0));
        }
        if (r1 < T_) {
            size_t off = ((size_t)(b * T_ + r1)) * D_ + d;
            *(unsigned*)(o_ + off) = pack_h2(__float2half(o[nt][2] * li1),
                                             __float2half(o[nt][3] * li1));
        }
    }
}

// ---------------- host orchestration ----------------
extern "C" void kernel_launch(void* const* d_in, const int* in_sizes, int n_in,
                              void* d_out, int out_size) {
    (void)in_sizes; (void)n_in; (void)out_size;

    const float* prefix = (const float*)d_in[0];
    const float* obs    = (const float*)d_in[2];
    const float* rdo    = (const float*)d_in[4];
    const float* ln1_s  = (const float*)d_in[6];
    const float* ln1_b  = (const float*)d_in[7];
    const float* wqkv   = (const float*)d_in[8];
    const float* bqkv   = (const float*)d_in[9];
    const float* wo     = (const float*)d_in[10];
    const float* bo     = (const float*)d_in[11];
    const float* ln2_s  = (const float*)d_in[12];
    const float* ln2_b  = (const float*)d_in[13];
    const float* w1     = (const float*)d_in[14];
    const float* b1     = (const float*)d_in[15];
    const float* w2     = (const float*)d_in[16];
    const float* b2     = (const float*)d_in[17];
    const float* lnf_s  = (const float*)d_in[18];
    const float* lnf_b  = (const float*)d_in[19];
    float* out = (float*)d_out;

    float* x;
    __half *y, *att, *ffn, *qkvhi, *qkvlo;
    __half *wqkvT, *woT, *w1T, *w2T;
    cudaGetSymbolAddress((void**)&x,     g_x);
    cudaGetSymbolAddress((void**)&y,     g_y);
    cudaGetSymbolAddress((void**)&att,   g_att);
    cudaGetSymbolAddress((void**)&ffn,   g_ffn);
    cudaGetSymbolAddress((void**)&qkvhi, g_qkv_hi);
    cudaGetSymbolAddress((void**)&qkvlo, g_qkv_lo);
    cudaGetSymbolAddress((void**)&wqkvT, g_wqkvT);
    cudaGetSymbolAddress((void**)&woT,   g_woT);
    cudaGetSymbolAddress((void**)&w1T,   g_w1T);
    cudaGetSymbolAddress((void**)&w2T,   g_w2T);

    cudaFuncSetAttribute(wmma_gemm<0>, cudaFuncAttributeMaxDynamicSharedMemorySize, SMEM_GEMM);
    cudaFuncSetAttribute(wmma_gemm<1>, cudaFuncAttributeMaxDynamicSharedMemorySize, SMEM_GEMM);
    cudaFuncSetAttribute(wmma_gemm<2>, cudaFuncAttributeMaxDynamicSharedMemorySize, SMEM_GEMM);
    cudaFuncSetAttribute(attn_mma, cudaFuncAttributeMaxDynamicSharedMemorySize, ATTN_SMEM);

    assemble_kernel<<<2048, 256>>>(prefix, obs, rdo);

    wconv_all_kernel<<<dim3(6912, L_), dim3(32, 8)>>>(
        wqkv, wo, w1, w2, wqkvT, woT, w1T, w2T);

    const dim3 g_qkv_grid(3 * D_ / BN, M_ / BM);   // (18, 86)
    const dim3 g_wo_grid (D_ / BN,     M_ / BM);   // (6, 86)
    const dim3 g_w1_grid (F_ / BN,     M_ / BM);   // (24, 86)
    const dim3 g_attn((T_ + 63) / 64, NH_, B_);    // (22, 12, 8)

    for (int l = 0; l < L_; l++) {
        ln_h_kernel<<<M_, 256>>>(x, ln1_s + (size_t)l * D_, ln1_b + (size_t)l * D_, y);
        wmma_gemm<0><<<g_qkv_grid, 256, SMEM_GEMM>>>(
            y, wqkvT + (size_t)l * 3 * D_ * D_,
            bqkv + (size_t)l * 3 * D_, nullptr, nullptr,
            qkvhi, qkvlo, 3 * D_, D_);
        attn_mma<<<g_attn, 128, ATTN_SMEM>>>(qkvhi, qkvlo, att);
        wmma_gemm<2><<<g_wo_grid, 256, SMEM_GEMM>>>(
            att, woT + (size_t)l * D_ * D_,
            bo + (size_t)l * D_, x, x,
            nullptr, nullptr, D_, D_);
        ln_h_kernel<<<M_, 256>>>(x, ln2_s + (size_t)l * D_, ln2_b + (size_t)l * D_, y);
        wmma_gemm<1><<<g_w1_grid, 256, SMEM_GEMM>>>(
            y, w1T + (size_t)l * F_ * D_,
            b1 + (size_t)l * F_, nullptr, nullptr,
            ffn, nullptr, F_, D_);
        wmma_gemm<2><<<g_wo_grid, 256, SMEM_GEMM>>>(
            ffn, w2T + (size_t)l * D_ * F_,
            b2 + (size_t)l * D_, x, x,
            nullptr, nullptr, D_, F_);
    }

    ln_kernel<<<M_, 256>>>(x, lnf_s, lnf_b, out);
}

// round 16
// speedup vs baseline: 5.3321x; 1.1347x over previous
#include <cuda_runtime.h>
#include <cuda_fp16.h>
#include <math.h>
#include <stdint.h>

// ---------------- problem constants ----------------
namespace {
constexpr int B_  = 8;
constexpr int P_  = 16;
constexpr int HOR = 10;
constexpr int NO_ = 128;
constexpr int NR_ = 8;
constexpr int D_  = 768;
constexpr int NH_ = 12;
constexpr int HD_ = 64;
constexpr int F_  = 3072;
constexpr int L_  = 12;
constexpr int TPS = NO_ + NR_;          // 136
constexpr int T_  = P_ + HOR * TPS;     // 1376
constexpr int M_  = B_ * T_;            // 11008
constexpr float LN_EPS = 1e-6f;
constexpr float ATT_SCALE = 0.125f;     // 1/sqrt(64)

// GEMM tiling: 256 threads, 2x4 warp grid, BK=64, 2-stage cp.async, 2 CTAs/SM
constexpr int BM = 128;
constexpr int BN = 128;
constexpr int BK = 64;
constexpr int GRS = 72;                  // SMEM row stride in fp16 (144B), conflict-free ldmatrix
constexpr int TILE_B = 128 * GRS * 2;    // 18432 bytes per operand tile
constexpr int STAGE_B = 2 * TILE_B;      // A, W = 36864
constexpr int SMEM_GEMM = 2 * STAGE_B;   // 73728

// attention smem: Q (hi/lo) + 2-stage (K,V single fp16) + double-buffered key codes
constexpr int ARS   = 72;                // 144B row stride, conflict-free
constexpr int ATSZ  = 64 * ARS;          // fp16 units per tile quarter (4608)
constexpr int AT_QH = 0;
constexpr int AT_QL = ATSZ;
constexpr int AT_TSZB = ATSZ * 2;        // 9216 bytes per tile quarter
constexpr int AT_CODE_B = 6 * AT_TSZB;   // 55296
constexpr int ATTN_SMEM = AT_CODE_B + 2 * 64 * 4;   // 55808 bytes
}

// ---------------- scratch (device globals: no cudaMalloc allowed) ----------------
__device__ float g_x[(size_t)M_ * D_];
__device__ __half g_y  [(size_t)M_ * D_];
__device__ __half g_att[(size_t)M_ * D_];
__device__ __half g_ffn[(size_t)M_ * F_];
__device__ __half g_qkv_hi[(size_t)M_ * 3 * D_];
__device__ __half g_qkv_lo[(size_t)M_ * 3 * D_];
__device__ __half g_wqkvT[(size_t)L_ * 3 * D_ * D_];
__device__ __half g_woT  [(size_t)L_ * D_ * D_];
__device__ __half g_w1T  [(size_t)L_ * F_ * D_];
__device__ __half g_w2T  [(size_t)L_ * D_ * F_];

// ---------------- mma / async helpers ----------------
__device__ __forceinline__ unsigned smem_u32(const void* p) {
    return (unsigned)__cvta_generic_to_shared(p);
}
__device__ __forceinline__ void ldsm_x4(unsigned* r, unsigned addr) {
    asm volatile("ldmatrix.sync.aligned.m8n8.x4.shared.b16 {%0,%1,%2,%3}, [%4];"
                 : "=r"(r[0]), "=r"(r[1]), "=r"(r[2]), "=r"(r[3]) : "r"(addr));
}
__device__ __forceinline__ void ldsm_x4t(unsigned* r, unsigned addr) {
    asm volatile("ldmatrix.sync.aligned.m8n8.x4.trans.shared.b16 {%0,%1,%2,%3}, [%4];"
                 : "=r"(r[0]), "=r"(r[1]), "=r"(r[2]), "=r"(r[3]) : "r"(addr));
}
__device__ __forceinline__ void mma_f16f32(float* c, const unsigned* a, const unsigned* b) {
    asm volatile(
        "mma.sync.aligned.m16n8k16.row.col.f32.f16.f16.f32 "
        "{%0,%1,%2,%3}, {%4,%5,%6,%7}, {%8,%9}, {%0,%1,%2,%3};"
        : "+f"(c[0]), "+f"(c[1]), "+f"(c[2]), "+f"(c[3])
        : "r"(a[0]), "r"(a[1]), "r"(a[2]), "r"(a[3]), "r"(b[0]), "r"(b[1]));
}
__device__ __forceinline__ void cp16(unsigned saddr, const void* g) {
    asm volatile("cp.async.cg.shared.global [%0], [%1], 16;" :: "r"(saddr), "l"(g));
}
__device__ __forceinline__ void cp_commit() {
    asm volatile("cp.async.commit_group;" ::: "memory");
}
template <int N>
__device__ __forceinline__ void cp_wait() {
    asm volatile("cp.async.wait_group %0;" :: "n"(N) : "memory");
}
__device__ __forceinline__ unsigned pack_h2(__half a, __half b) {
    __half2 t(a, b);
    return *(unsigned*)&t;
}
__device__ __forceinline__ void split2h(float v, __half& h, __half& l) {
    h = __float2half(v);
    l = __float2half(v - __half2float(h));
}

// ---------------- misc helpers ----------------
__device__ __forceinline__ float gelu_tanh(float x) {
    float x3 = x * x * x;
    return 0.5f * x * (1.0f + tanhf(0.7978845608028654f * (x + 0.044715f * x3)));
}
__device__ __forceinline__ int tok_group(int i) {
    if (i < P_) return 0;
    return (((i - P_) % TPS) < NO_) ? 1 : 2;
}
__device__ __forceinline__ int tok_ts(int i) {
    return (i < P_) ? -1 : (i - P_) / TPS;
}
__device__ __forceinline__ bool allow_code(int gq, int tq, int kc) {
    int gk = kc & 3;
    int tk = kc >> 2;
    if (gk == 0) return true;
    if (gq == 0) return false;
    if (tk > tq) return false;
    return (gk == 1) || (gq == 2);
}

// ---------------- assemble ----------------
__global__ void assemble_kernel(const float* __restrict__ prefix,
                                const float* __restrict__ obs,
                                const float* __restrict__ rdo) {
    for (int idx = blockIdx.x * blockDim.x + threadIdx.x;
         idx < M_ * D_; idx += gridDim.x * blockDim.x) {
        int d = idx % D_;
        int bt = idx / D_;
        int t = bt % T_;
        int b = bt / T_;
        float v;
        if (t < P_) {
            v = prefix[((size_t)b * P_ + t) * D_ + d];
        } else {
            int tt = t - P_;
            int ho = tt / TPS;
            int r  = tt % TPS;
            if (r < NO_)
                v = obs[(((size_t)b * HOR + ho) * NO_ + r) * D_ + d];
            else
                v = rdo[(((size_t)b * HOR + ho) * NR_ + (r - NO_)) * D_ + d];
        }
        g_x[idx] = v;
    }
}

// ---------------- fused weight transpose + fp16 convert ----------------
__global__ void wconv_all_kernel(const float* __restrict__ wqkv, const float* __restrict__ wo,
                                 const float* __restrict__ w1, const float* __restrict__ w2,
                                 __half* __restrict__ q16, __half* __restrict__ o16,
                                 __half* __restrict__ f16a, __half* __restrict__ f16b) {
    __shared__ float t[32][33];
    const int l = blockIdx.y;
    int bx = blockIdx.x;
    const float* src;
    __half* dstT;
    int R, C;
    if (bx < 1728) {
        src = wqkv + (size_t)l * D_ * 3 * D_;
        dstT = q16 + (size_t)l * 3 * D_ * D_;
        R = D_; C = 3 * D_;
    } else if (bx < 2304) {
        bx -= 1728;
        src = wo + (size_t)l * D_ * D_;
        dstT = o16 + (size_t)l * D_ * D_;
        R = D_; C = D_;
    } else if (bx < 4608) {
        bx -= 2304;
        src = w1 + (size_t)l * D_ * F_;
        dstT = f16a + (size_t)l * F_ * D_;
        R = D_; C = F_;
    } else {
        bx -= 4608;
        src = w2 + (size_t)l * F_ * D_;
        dstT = f16b + (size_t)l * D_ * F_;
        R = F_; C = D_;
    }
    const int cols = C / 32;
    const int cb = (bx % cols) * 32, rb = (bx / cols) * 32;
    const int tx = threadIdx.x, ty = threadIdx.y;
    #pragma unroll
    for (int i = 0; i < 32; i += 8)
        t[ty + i][tx] = src[(size_t)(rb + ty + i) * C + cb + tx];
    __syncthreads();
    #pragma unroll
    for (int i = 0; i < 32; i += 8)
        dstT[(size_t)(cb + ty + i) * R + rb + tx] = __float2half(t[tx][ty + i]);
}

// ---------------- layernorm ----------------
__device__ __forceinline__ float block_reduce_sum(float v, float* red) {
    int lane = threadIdx.x & 31;
    int wid  = threadIdx.x >> 5;
    #pragma unroll
    for (int o = 16; o; o >>= 1) v += __shfl_down_sync(0xffffffffu, v, o);
    if (lane == 0) red[wid] = v;
    __syncthreads();
    if (threadIdx.x < 32) {
        float t = (threadIdx.x < 8) ? red[threadIdx.x] : 0.0f;
        #pragma unroll
        for (int o = 4; o; o >>= 1) t += __shfl_down_sync(0xffffffffu, t, o);
        if (threadIdx.x == 0) red[32] = t;
    }
    __syncthreads();
    return red[32];
}

__global__ void ln_kernel(const float* __restrict__ x,
                          const float* __restrict__ s,
                          const float* __restrict__ b,
                          float* __restrict__ y) {
    __shared__ float red[33];
    int row = blockIdx.x;
    const float* xp = x + (size_t)row * D_;
    float v0 = xp[threadIdx.x];
    float v1 = xp[threadIdx.x + 256];
    float v2 = xp[threadIdx.x + 512];
    float mu = block_reduce_sum(v0 + v1 + v2, red) * (1.0f / D_);
    float d0 = v0 - mu, d1 = v1 - mu, d2 = v2 - mu;
    float var = block_reduce_sum(d0 * d0 + d1 * d1 + d2 * d2, red) * (1.0f / D_);
    float inv = rsqrtf(var + LN_EPS);
    float* yp = y + (size_t)row * D_;
    yp[threadIdx.x      ] = d0 * inv * s[threadIdx.x      ] + b[threadIdx.x      ];
    yp[threadIdx.x + 256] = d1 * inv * s[threadIdx.x + 256] + b[threadIdx.x + 256];
    yp[threadIdx.x + 512] = d2 * inv * s[threadIdx.x + 512] + b[threadIdx.x + 512];
}

__global__ void ln_h_kernel(const float* __restrict__ x,
                            const float* __restrict__ s,
                            const float* __restrict__ b,
                            __half* __restrict__ y) {
    __shared__ float red[33];
    int row = blockIdx.x;
    const float* xp = x + (size_t)row * D_;
    float v0 = xp[threadIdx.x];
    float v1 = xp[threadIdx.x + 256];
    float v2 = xp[threadIdx.x + 512];
    float mu = block_reduce_sum(v0 + v1 + v2, red) * (1.0f / D_);
    float d0 = v0 - mu, d1 = v1 - mu, d2 = v2 - mu;
    float var = block_reduce_sum(d0 * d0 + d1 * d1 + d2 * d2, red) * (1.0f / D_);
    float inv = rsqrtf(var + LN_EPS);
    size_t base = (size_t)row * D_;
    y[base + threadIdx.x      ] = __float2half(d0 * inv * s[threadIdx.x      ] + b[threadIdx.x      ]);
    y[base + threadIdx.x + 256] = __float2half(d1 * inv * s[threadIdx.x + 256] + b[threadIdx.x + 256]);
    y[base + threadIdx.x + 512] = __float2half(d2 * inv * s[threadIdx.x + 512] + b[threadIdx.x + 512]);
}

// ---------------- pure fp16 warp-mma GEMM, BK=64 ----------------
// C[M,N] = A16[M,K] @ W16[N,K]^T + bias
// EPI 0: write split fp16 (qkv hi/lo) ; EPI 1: gelu -> single fp16 ; EPI 2: +R -> fp32
template <int EPI>
__global__ __launch_bounds__(256, 2) void wmma_gemm(
    const __half* __restrict__ A,
    const __half* __restrict__ W,
    const float* __restrict__ bias, const float* __restrict__ R,
    float* __restrict__ C,
    __half* __restrict__ Chh, __half* __restrict__ Chl,
    int Ndim, int Kdim) {
    extern __shared__ char smem[];
    const unsigned sbase = smem_u32(smem);
    const int tid = threadIdx.x;
    const int lane = tid & 31;
    const int wid = tid >> 5;
    const int warp_m = wid & 1;
    const int warp_n = wid >> 1;
    const int bm = blockIdx.y * BM;
    const int bn = blockIdx.x * BN;
    const int NK = Kdim / BK;

    auto issue_stage = [&](int st) {
        const unsigned sb = sbase + (unsigned)((st & 1) * STAGE_B);
        const int k0 = st * BK;
        #pragma unroll
        for (int i = 0; i < 4; i++) {
            int f = tid + i * 256;          // 0..1023
            int r = f >> 3, cc = f & 7;
            unsigned so = (unsigned)(r * (GRS * 2) + cc * 16);
            size_t ao = (size_t)(bm + r) * Kdim + k0 + 8 * cc;
            size_t bo = (size_t)(bn + r) * Kdim + k0 + 8 * cc;
            cp16(sb + so,          A + ao);
            cp16(sb + TILE_B + so, W + bo);
        }
        cp_commit();
    };

    const unsigned a_base = (unsigned)((warp_m * 64 + (lane & 15)) * (GRS * 2) + (lane >> 4) * 16);
    const unsigned b_row = (unsigned)(warp_n * 32 + (lane & 7) + ((lane >> 4) << 3));
    const unsigned b_base = (unsigned)(b_row * (GRS * 2) + (((lane >> 3) & 1) * 16));

    float acc[4][4][4];
    #pragma unroll
    for (int mt = 0; mt < 4; mt++)
        #pragma unroll
        for (int nt = 0; nt < 4; nt++)
            #pragma unroll
            for (int r = 0; r < 4; r++) acc[mt][nt][r] = 0.0f;

    issue_stage(0);

    for (int i = 0; i < NK; i++) {
        cp_wait<0>();
        __syncthreads();
        if (i + 1 < NK) issue_stage(i + 1);

        const unsigned tA = sbase + (unsigned)((i & 1) * STAGE_B);
        const unsigned tW = tA + TILE_B;

        #pragma unroll
        for (int ks = 0; ks < 4; ks++) {
            unsigned fbw[2][4];
            #pragma unroll
            for (int pr = 0; pr < 2; pr++) {
                unsigned bo = b_base + (unsigned)(pr * 16 * (GRS * 2) + ks * 32);
                ldsm_x4(fbw[pr], tW + bo);
            }
            #pragma unroll
            for (int mt = 0; mt < 4; mt++) {
                unsigned fa[4];
                unsigned ao = a_base + (unsigned)(mt * 16 * (GRS * 2) + ks * 32);
                ldsm_x4(fa, tA + ao);
                #pragma unroll
                for (int nt = 0; nt < 4; nt++)
                    mma_f16f32(acc[mt][nt], fa, &fbw[nt >> 1][(nt & 1) * 2]);
            }
        }
    }

    // ---- epilogue ----
    const int g = lane >> 2, tg = lane & 3;
    #pragma unroll
    for (int mt = 0; mt < 4; mt++) {
        #pragma unroll
        for (int nt = 0; nt < 4; nt++) {
            int row0 = bm + warp_m * 64 + mt * 16 + g;
            int col  = bn + warp_n * 32 + nt * 8 + tg * 2;
            float2 bv = *(const float2*)(bias + col);
            float c0 = acc[mt][nt][0] + bv.x;
            float c1 = acc[mt][nt][1] + bv.y;
            float c2 = acc[mt][nt][2] + bv.x;
            float c3 = acc[mt][nt][3] + bv.y;
            size_t o0 = (size_t)row0 * Ndim + col;
            size_t o1 = o0 + (size_t)8 * Ndim;
            if (EPI == 2) {
                float2 r0 = *(const float2*)(R + o0);
                float2 r1 = *(const float2*)(R + o1);
                c0 += r0.x; c1 += r0.y; c2 += r1.x; c3 += r1.y;
                *(float2*)(C + o0) = make_float2(c0, c1);
                *(float2*)(C + o1) = make_float2(c2, c3);
            } else if (EPI == 0) {
                __half h0, l0v, h1, l1v, h2, l2v, h3, l3v;
                split2h(c0, h0, l0v); split2h(c1, h1, l1v);
                split2h(c2, h2, l2v); split2h(c3, h3, l3v);
                *(unsigned*)(Chh + o0) = pack_h2(h0, h1);
                *(unsigned*)(Chl + o0) = pack_h2(l0v, l1v);
                *(unsigned*)(Chh + o1) = pack_h2(h2, h3);
                *(unsigned*)(Chl + o1) = pack_h2(l2v, l3v);
            } else {
                c0 = gelu_tanh(c0); c1 = gelu_tanh(c1);
                c2 = gelu_tanh(c2); c3 = gelu_tanh(c3);
                *(unsigned*)(Chh + o0) = pack_h2(__float2half(c0), __float2half(c1));
                *(unsigned*)(Chh + o1) = pack_h2(__float2half(c2), __float2half(c3));
            }
        }
    }
}

// ---------------- fp16 flash attention (Q hi/lo for QK; single-fp16 P for PV) ----------------
__global__ __launch_bounds__(128) void attn_mma(
    const __half* __restrict__ qh_, const __half* __restrict__ ql_,
    __half* __restrict__ o_) {
    extern __shared__ char smem[];
    __half* sb = (__half*)smem;
    int* kcode = (int*)(smem + AT_CODE_B);
    const unsigned sbase = smem_u32(smem);
    const int h = blockIdx.y, b = blockIdx.z;
    const int q0 = blockIdx.x * 64;
    const int tid = threadIdx.x;
    const int lane = tid & 31;
    const int warp = tid >> 5;
    const int tg2 = (lane & 3) * 2;

    const int rlast = min(q0 + 63, T_ - 1);
    const int kmax = P_ + (tok_ts(rlast) + 1) * TPS;
    const int ntiles = (kmax + 63) / 64;

    for (int idx = tid; idx < 64 * 8; idx += 128) {
        int r = idx >> 3, c = idx & 7;
        int gr = min(q0 + r, T_ - 1);
        size_t src = ((size_t)(b * T_ + gr)) * (3 * D_) + h * HD_ + c * 8;
        *(uint4*)&sb[AT_QH + r * ARS + c * 8] = *(const uint4*)(qh_ + src);
        *(uint4*)&sb[AT_QL + r * ARS + c * 8] = *(const uint4*)(ql_ + src);
    }

    auto issue_kv = [&](int it) {
        const int s = it & 1;
        const unsigned base = sbase + (unsigned)((2 + s * 2) * AT_TSZB);
        const int k0 = it * 64;
        #pragma unroll
        for (int i = 0; i < 4; i++) {
            int idx = tid + i * 128;
            int r = idx >> 3, c = idx & 7;
            int kr = min(k0 + r, T_ - 1);
            size_t src = ((size_t)(b * T_ + kr)) * (3 * D_) + D_ + h * HD_ + c * 8;
            unsigned o = (unsigned)(r * ARS * 2 + c * 16);
            cp16(base + o,           qh_ + src);        // K
            cp16(base + AT_TSZB + o, qh_ + src + D_);   // V
        }
        cp_commit();
        if (tid < 64) {
            int kg = k0 + tid;
            kcode[s * 64 + tid] = (kg < kmax)
                                ? ((tok_ts(kg) << 2) | tok_group(kg))
                                : ((0x3FFF << 2) | 3);
        }
    };

    issue_kv(0);
    __syncthreads();

    unsigned qfh[4][4], qfl[4][4];
    {
        unsigned rowoff = (unsigned)((warp * 16 + (lane & 15)) * (ARS * 2)) + (lane >> 4) * 16;
        #pragma unroll
        for (int ks = 0; ks < 4; ks++) {
            ldsm_x4(qfh[ks], sbase + AT_QH * 2 + rowoff + ks * 32);
            ldsm_x4(qfl[ks], sbase + AT_QL * 2 + rowoff + ks * 32);
        }
    }

    const int r0 = q0 + warp * 16 + (lane >> 2);
    const int r1 = r0 + 8;
    const int rc0 = min(r0, T_ - 1), rc1 = min(r1, T_ - 1);
    const int gq0 = tok_group(rc0), tq0 = tok_ts(rc0);
    const int gq1 = tok_group(rc1), tq1 = tok_ts(rc1);

    float m0 = -1e30f, m1 = -1e30f, l0 = 0.0f, l1 = 0.0f;
    float o[8][4];
    #pragma unroll
    for (int nt = 0; nt < 8; nt++)
        #pragma unroll
        for (int r = 0; r < 4; r++) o[nt][r] = 0.0f;

    const unsigned kb = (unsigned)(((lane & 7) + ((lane >> 4) << 3)) * (ARS * 2)) +
                        ((lane >> 3) & 1) * 16;

    for (int it = 0; it < ntiles; it++) {
        cp_wait<0>();
        __syncthreads();
        if (it + 1 < ntiles) issue_kv(it + 1);

        const int s = it & 1;
        const unsigned tK = sbase + (unsigned)((2 + s * 2) * AT_TSZB);
        const unsigned tV = tK + AT_TSZB;
        const int* kc = kcode + s * 64;

        float sc[8][4];
        #pragma unroll
        for (int nt = 0; nt < 8; nt++)
            #pragma unroll
            for (int r = 0; r < 4; r++) sc[nt][r] = 0.0f;

        #pragma unroll
        for (int kg = 0; kg < 4; kg++) {
            #pragma unroll
            for (int ks = 0; ks < 4; ks++) {
                unsigned kh[4];
                unsigned addr = kb + (unsigned)(kg * 16 * (ARS * 2)) + ks * 32;
                ldsm_x4(kh, tK + addr);
                #pragma unroll
                for (int half = 0; half < 2; half++) {
                    int nt = kg * 2 + half;
                    mma_f16f32(sc[nt], qfh[ks], &kh[half * 2]);
                    mma_f16f32(sc[nt], qfl[ks], &kh[half * 2]);
                }
            }
        }

        #pragma unroll
        for (int nt = 0; nt < 8; nt++) {
            int kc0 = kc[nt * 8 + tg2];
            int kc1 = kc[nt * 8 + tg2 + 1];
            sc[nt][0] = allow_code(gq0, tq0, kc0) ? sc[nt][0] * ATT_SCALE : -1e30f;
            sc[nt][1] = allow_code(gq0, tq0, kc1) ? sc[nt][1] * ATT_SCALE : -1e30f;
            sc[nt][2] = allow_code(gq1, tq1, kc0) ? sc[nt][2] * ATT_SCALE : -1e30f;
            sc[nt][3] = allow_code(gq1, tq1, kc1) ? sc[nt][3] * ATT_SCALE : -1e30f;
        }

        float mx0 = -1e30f, mx1 = -1e30f;
        #pragma unroll
        for (int nt = 0; nt < 8; nt++) {
            mx0 = fmaxf(mx0, fmaxf(sc[nt][0], sc[nt][1]));
            mx1 = fmaxf(mx1, fmaxf(sc[nt][2], sc[nt][3]));
        }
        mx0 = fmaxf(mx0, __shfl_xor_sync(0xffffffffu, mx0, 1));
        mx0 = fmaxf(mx0, __shfl_xor_sync(0xffffffffu, mx0, 2));
        mx1 = fmaxf(mx1, __shfl_xor_sync(0xffffffffu, mx1, 1));
        mx1 = fmaxf(mx1, __shfl_xor_sync(0xffffffffu, mx1, 2));
        float mn0 = fmaxf(m0, mx0), mn1 = fmaxf(m1, mx1);
        float corr0 = __expf(m0 - mn0), corr1 = __expf(m1 - mn1);
        m0 = mn0; m1 = mn1;
        l0 *= corr0; l1 *= corr1;
        #pragma unroll
        for (int nt = 0; nt < 8; nt++) {
            o[nt][0] *= corr0; o[nt][1] *= corr0;
            o[nt][2] *= corr1; o[nt][3] *= corr1;
        }

        // ---- P (single fp16), O += P*V (1 MMA per half) ----
        #pragma unroll
        for (int kv = 0; kv < 4; kv++) {
            unsigned ph[4];
            #pragma unroll
            for (int half = 0; half < 2; half++) {
                int nt = kv * 2 + half;
                float p0 = __expf(sc[nt][0] - m0);
                float p1 = __expf(sc[nt][1] - m0);
                float p2 = __expf(sc[nt][2] - m1);
                float p3 = __expf(sc[nt][3] - m1);
                l0 += p0 + p1;
                l1 += p2 + p3;
                ph[half * 2 + 0] = pack_h2(__float2half(p0), __float2half(p1));
                ph[half * 2 + 1] = pack_h2(__float2half(p2), __float2half(p3));
            }
            #pragma unroll
            for (int dg = 0; dg < 4; dg++) {
                unsigned vh[4];
                unsigned addr = kb + (unsigned)(kv * 16 * (ARS * 2)) + dg * 32;
                ldsm_x4t(vh, tV + addr);
                #pragma unroll
                for (int half = 0; half < 2; half++) {
                    int nt = dg * 2 + half;
                    unsigned bp[2] = {vh[half], vh[2 + half]};
                    mma_f16f32(o[nt], ph, bp);
                }
            }
        }
    }

    l0 += __shfl_xor_sync(0xffffffffu, l0, 1);
    l0 += __shfl_xor_sync(0xffffffffu, l0, 2);
    l1 += __shfl_xor_sync(0xffffffffu, l1, 1);
    l1 += __shfl_xor_sync(0xffffffffu, l1, 2);
    float li0 = 1.0f / l0, li1 = 1.0f / l1;

    #pragma unroll
    for (int nt = 0; nt < 8; nt++) {
        int d = h * HD_ + nt * 8 + tg2;
        if (r0 < T_) {
            size_t off = ((size_t)(b * T_ + r0)) * D_ + d;
            *(unsigned*)(o_ + off) = pack_h2(__float2half(o[nt][0] * li0),
                                             __float2half(o[nt][1] * li0));
        }
        if (r1 < T_) {
            size_t off = ((size_t)(b * T_ + r1)) * D_ + d;
            *(unsigned*)(o_ + off) = pack_h2(__float2half(o[nt][2] * li1),
                                             __float2half(o[nt][3] * li1));
        }
    }
}

// ---------------- host orchestration ----------------
extern "C" void kernel_launch(void* const* d_in, const int* in_sizes, int n_in,
                              void* d_out, int out_size) {
    (void)in_sizes; (void)n_in; (void)out_size;

    const float* prefix = (const float*)d_in[0];
    const float* obs    = (const float*)d_in[2];
    const float* rdo    = (const float*)d_in[4];
    const float* ln1_s  = (const float*)d_in[6];
    const float* ln1_b  = (const float*)d_in[7];
    const float* wqkv   = (const float*)d_in[8];
    const float* bqkv   = (const float*)d_in[9];
    const float* wo     = (const float*)d_in[10];
    const float* bo     = (const float*)d_in[11];
    const float* ln2_s  = (const float*)d_in[12];
    const float* ln2_b  = (const float*)d_in[13];
    const float* w1     = (const float*)d_in[14];
    const float* b1     = (const float*)d_in[15];
    const float* w2     = (const float*)d_in[16];
    const float* b2     = (const float*)d_in[17];
    const float* lnf_s  = (const float*)d_in[18];
    const float* lnf_b  = (const float*)d_in[19];
    float* out = (float*)d_out;

    float* x;
    __half *y, *att, *ffn, *qkvhi, *qkvlo;
    __half *wqkvT, *woT, *w1T, *w2T;
    cudaGetSymbolAddress((void**)&x,     g_x);
    cudaGetSymbolAddress((void**)&y,     g_y);
    cudaGetSymbolAddress((void**)&att,   g_att);
    cudaGetSymbolAddress((void**)&ffn,   g_ffn);
    cudaGetSymbolAddress((void**)&qkvhi, g_qkv_hi);
    cudaGetSymbolAddress((void**)&qkvlo, g_qkv_lo);
    cudaGetSymbolAddress((void**)&wqkvT, g_wqkvT);
    cudaGetSymbolAddress((void**)&woT,   g_woT);
    cudaGetSymbolAddress((void**)&w1T,   g_w1T);
    cudaGetSymbolAddress((void**)&w2T,   g_w2T);

    cudaFuncSetAttribute(wmma_gemm<0>, cudaFuncAttributeMaxDynamicSharedMemorySize, SMEM_GEMM);
    cudaFuncSetAttribute(wmma_gemm<1>, cudaFuncAttributeMaxDynamicSharedMemorySize, SMEM_GEMM);
    cudaFuncSetAttribute(wmma_gemm<2>, cudaFuncAttributeMaxDynamicSharedMemorySize, SMEM_GEMM);
    cudaFuncSetAttribute(attn_mma, cudaFuncAttributeMaxDynamicSharedMemorySize, ATTN_SMEM);

    assemble_kernel<<<2048, 256>>>(prefix, obs, rdo);

    wconv_all_kernel<<<dim3(6912, L_), dim3(32, 8)>>>(
        wqkv, wo, w1, w2, wqkvT, woT, w1T, w2T);

    const dim3 g_qkv_grid(3 * D_ / BN, M_ / BM);   // (18, 86)
    const dim3 g_wo_grid (D_ / BN,     M_ / BM);   // (6, 86)
    const dim3 g_w1_grid (F_ / BN,     M_ / BM);   // (24, 86)
    const dim3 g_attn((T_ + 63) / 64, NH_, B_);    // (22, 12, 8)

    for (int l = 0; l < L_; l++) {
        ln_h_kernel<<<M_, 256>>>(x, ln1_s + (size_t)l * D_, ln1_b + (size_t)l * D_, y);
        wmma_gemm<0><<<g_qkv_grid, 256, SMEM_GEMM>>>(
            y, wqkvT + (size_t)l * 3 * D_ * D_,
            bqkv + (size_t)l * 3 * D_, nullptr, nullptr,
            qkvhi, qkvlo, 3 * D_, D_);
        attn_mma<<<g_attn, 128, ATTN_SMEM>>>(qkvhi, qkvlo, att);
        wmma_gemm<2><<<g_wo_grid, 256, SMEM_GEMM>>>(
            att, woT + (size_t)l * D_ * D_,
            bo + (size_t)l * D_, x, x,
            nullptr, nullptr, D_, D_);
        ln_h_kernel<<<M_, 256>>>(x, ln2_s + (size_t)l * D_, ln2_b + (size_t)l * D_, y);
        wmma_gemm<1><<<g_w1_grid, 256, SMEM_GEMM>>>(
            y, w1T + (size_t)l * F_ * D_,
            b1 + (size_t)l * F_, nullptr, nullptr,
            ffn, nullptr, F_, D_);
        wmma_gemm<2><<<g_wo_grid, 256, SMEM_GEMM>>>(
            ffn, w2T + (size_t)l * D_ * F_,
            b2 + (size_t)l * D_, x, x,
            nullptr, nullptr, D_, F_);
    }

    ln_kernel<<<M_, 256>>>(x, lnf_s, lnf_b, out);
}

// round 17
// speedup vs baseline: 5.6390x; 1.0576x over previous
#include <cuda_runtime.h>
#include <cuda_fp16.h>
#include <math.h>
#include <stdint.h>

// ---------------- problem constants ----------------
namespace {
constexpr int B_  = 8;
constexpr int P_  = 16;
constexpr int HOR = 10;
constexpr int NO_ = 128;
constexpr int NR_ = 8;
constexpr int D_  = 768;
constexpr int NH_ = 12;
constexpr int HD_ = 64;
constexpr int F_  = 3072;
constexpr int L_  = 12;
constexpr int TPS = NO_ + NR_;          // 136
constexpr int T_  = P_ + HOR * TPS;     // 1376
constexpr int M_  = B_ * T_;            // 11008
constexpr float LN_EPS = 1e-6f;
constexpr float ATT_SCALE = 0.125f;     // 1/sqrt(64)

// GEMM tiling: 256 threads, 2x4 warp grid, BK=64, 3-stage cp.async, 2 CTAs/SM
constexpr int BM = 128;
constexpr int BN = 128;
constexpr int BK = 64;
constexpr int GRS = 72;                  // SMEM row stride in fp16 (144B), conflict-free ldmatrix
constexpr int TILE_B = 128 * GRS * 2;    // 18432 bytes per operand tile
constexpr int STAGE_B = 2 * TILE_B;      // A, W = 36864
constexpr int NSTAGE = 3;
constexpr int SMEM_GEMM = NSTAGE * STAGE_B;  // 110592

// attention smem: Q (single fp16) + 2-stage (K,V single fp16) + key codes
constexpr int ARS   = 72;                // 144B row stride, conflict-free
constexpr int ATSZ  = 64 * ARS;          // fp16 units per tile quarter (4608)
constexpr int AT_TSZB = ATSZ * 2;        // 9216 bytes per tile quarter
constexpr int AT_CODE_B = 5 * AT_TSZB;   // 46080
constexpr int ATTN_SMEM = AT_CODE_B + 2 * 64 * 4;   // 46592 bytes
}

// ---------------- scratch (device globals: no cudaMalloc allowed) ----------------
__device__ float g_x[(size_t)M_ * D_];
__device__ __half g_y  [(size_t)M_ * D_];
__device__ __half g_att[(size_t)M_ * D_];
__device__ __half g_ffn[(size_t)M_ * F_];
__device__ __half g_qkv[(size_t)M_ * 3 * D_];
__device__ __half g_wqkvT[(size_t)L_ * 3 * D_ * D_];
__device__ __half g_woT  [(size_t)L_ * D_ * D_];
__device__ __half g_w1T  [(size_t)L_ * F_ * D_];
__device__ __half g_w2T  [(size_t)L_ * D_ * F_];

// ---------------- mma / async helpers ----------------
__device__ __forceinline__ unsigned smem_u32(const void* p) {
    return (unsigned)__cvta_generic_to_shared(p);
}
__device__ __forceinline__ void ldsm_x4(unsigned* r, unsigned addr) {
    asm volatile("ldmatrix.sync.aligned.m8n8.x4.shared.b16 {%0,%1,%2,%3}, [%4];"
                 : "=r"(r[0]), "=r"(r[1]), "=r"(r[2]), "=r"(r[3]) : "r"(addr));
}
__device__ __forceinline__ void ldsm_x4t(unsigned* r, unsigned addr) {
    asm volatile("ldmatrix.sync.aligned.m8n8.x4.trans.shared.b16 {%0,%1,%2,%3}, [%4];"
                 : "=r"(r[0]), "=r"(r[1]), "=r"(r[2]), "=r"(r[3]) : "r"(addr));
}
__device__ __forceinline__ void mma_f16f32(float* c, const unsigned* a, const unsigned* b) {
    asm volatile(
        "mma.sync.aligned.m16n8k16.row.col.f32.f16.f16.f32 "
        "{%0,%1,%2,%3}, {%4,%5,%6,%7}, {%8,%9}, {%0,%1,%2,%3};"
        : "+f"(c[0]), "+f"(c[1]), "+f"(c[2]), "+f"(c[3])
        : "r"(a[0]), "r"(a[1]), "r"(a[2]), "r"(a[3]), "r"(b[0]), "r"(b[1]));
}
__device__ __forceinline__ void cp16(unsigned saddr, const void* g) {
    asm volatile("cp.async.cg.shared.global [%0], [%1], 16;" :: "r"(saddr), "l"(g));
}
__device__ __forceinline__ void cp_commit() {
    asm volatile("cp.async.commit_group;" ::: "memory");
}
template <int N>
__device__ __forceinline__ void cp_wait() {
    asm volatile("cp.async.wait_group %0;" :: "n"(N) : "memory");
}
__device__ __forceinline__ unsigned pack_h2(__half a, __half b) {
    __half2 t(a, b);
    return *(unsigned*)&t;
}

// ---------------- misc helpers ----------------
__device__ __forceinline__ float gelu_tanh(float x) {
    float x3 = x * x * x;
    return 0.5f * x * (1.0f + tanhf(0.7978845608028654f * (x + 0.044715f * x3)));
}
__device__ __forceinline__ int tok_group(int i) {
    if (i < P_) return 0;
    return (((i - P_) % TPS) < NO_) ? 1 : 2;
}
__device__ __forceinline__ int tok_ts(int i) {
    return (i < P_) ? -1 : (i - P_) / TPS;
}
__device__ __forceinline__ bool allow_code(int gq, int tq, int kc) {
    int gk = kc & 3;
    int tk = kc >> 2;
    if (gk == 0) return true;
    if (gq == 0) return false;
    if (tk > tq) return false;
    return (gk == 1) || (gq == 2);
}

// ---------------- assemble ----------------
__global__ void assemble_kernel(const float* __restrict__ prefix,
                                const float* __restrict__ obs,
                                const float* __restrict__ rdo) {
    for (int idx = blockIdx.x * blockDim.x + threadIdx.x;
         idx < M_ * D_; idx += gridDim.x * blockDim.x) {
        int d = idx % D_;
        int bt = idx / D_;
        int t = bt % T_;
        int b = bt / T_;
        float v;
        if (t < P_) {
            v = prefix[((size_t)b * P_ + t) * D_ + d];
        } else {
            int tt = t - P_;
            int ho = tt / TPS;
            int r  = tt % TPS;
            if (r < NO_)
                v = obs[(((size_t)b * HOR + ho) * NO_ + r) * D_ + d];
            else
                v = rdo[(((size_t)b * HOR + ho) * NR_ + (r - NO_)) * D_ + d];
        }
        g_x[idx] = v;
    }
}

// ---------------- fused weight transpose + fp16 convert ----------------
__global__ void wconv_all_kernel(const float* __restrict__ wqkv, const float* __restrict__ wo,
                                 const float* __restrict__ w1, const float* __restrict__ w2,
                                 __half* __restrict__ q16, __half* __restrict__ o16,
                                 __half* __restrict__ f16a, __half* __restrict__ f16b) {
    __shared__ float t[32][33];
    const int l = blockIdx.y;
    int bx = blockIdx.x;
    const float* src;
    __half* dstT;
    int R, C;
    if (bx < 1728) {
        src = wqkv + (size_t)l * D_ * 3 * D_;
        dstT = q16 + (size_t)l * 3 * D_ * D_;
        R = D_; C = 3 * D_;
    } else if (bx < 2304) {
        bx -= 1728;
        src = wo + (size_t)l * D_ * D_;
        dstT = o16 + (size_t)l * D_ * D_;
        R = D_; C = D_;
    } else if (bx < 4608) {
        bx -= 2304;
        src = w1 + (size_t)l * D_ * F_;
        dstT = f16a + (size_t)l * F_ * D_;
        R = D_; C = F_;
    } else {
        bx -= 4608;
        src = w2 + (size_t)l * F_ * D_;
        dstT = f16b + (size_t)l * D_ * F_;
        R = F_; C = D_;
    }
    const int cols = C / 32;
    const int cb = (bx % cols) * 32, rb = (bx / cols) * 32;
    const int tx = threadIdx.x, ty = threadIdx.y;
    #pragma unroll
    for (int i = 0; i < 32; i += 8)
        t[ty + i][tx] = src[(size_t)(rb + ty + i) * C + cb + tx];
    __syncthreads();
    #pragma unroll
    for (int i = 0; i < 32; i += 8)
        dstT[(size_t)(cb + ty + i) * R + rb + tx] = __float2half(t[tx][ty + i]);
}

// ---------------- layernorm ----------------
__device__ __forceinline__ float block_reduce_sum(float v, float* red) {
    int lane = threadIdx.x & 31;
    int wid  = threadIdx.x >> 5;
    #pragma unroll
    for (int o = 16; o; o >>= 1) v += __shfl_down_sync(0xffffffffu, v, o);
    if (lane == 0) red[wid] = v;
    __syncthreads();
    if (threadIdx.x < 32) {
        float t = (threadIdx.x < 8) ? red[threadIdx.x] : 0.0f;
        #pragma unroll
        for (int o = 4; o; o >>= 1) t += __shfl_down_sync(0xffffffffu, t, o);
        if (threadIdx.x == 0) red[32] = t;
    }
    __syncthreads();
    return red[32];
}

__global__ void ln_kernel(const float* __restrict__ x,
                          const float* __restrict__ s,
                          const float* __restrict__ b,
                          float* __restrict__ y) {
    __shared__ float red[33];
    int row = blockIdx.x;
    const float* xp = x + (size_t)row * D_;
    float v0 = xp[threadIdx.x];
    float v1 = xp[threadIdx.x + 256];
    float v2 = xp[threadIdx.x + 512];
    float mu = block_reduce_sum(v0 + v1 + v2, red) * (1.0f / D_);
    float d0 = v0 - mu, d1 = v1 - mu, d2 = v2 - mu;
    float var = block_reduce_sum(d0 * d0 + d1 * d1 + d2 * d2, red) * (1.0f / D_);
    float inv = rsqrtf(var + LN_EPS);
    float* yp = y + (size_t)row * D_;
    yp[threadIdx.x      ] = d0 * inv * s[threadIdx.x      ] + b[threadIdx.x      ];
    yp[threadIdx.x + 256] = d1 * inv * s[threadIdx.x + 256] + b[threadIdx.x + 256];
    yp[threadIdx.x + 512] = d2 * inv * s[threadIdx.x + 512] + b[threadIdx.x + 512];
}

__global__ void ln_h_kernel(const float* __restrict__ x,
                            const float* __restrict__ s,
                            const float* __restrict__ b,
                            __half* __restrict__ y) {
    __shared__ float red[33];
    int row = blockIdx.x;
    const float* xp = x + (size_t)row * D_;
    float v0 = xp[threadIdx.x];
    float v1 = xp[threadIdx.x + 256];
    float v2 = xp[threadIdx.x + 512];
    float mu = block_reduce_sum(v0 + v1 + v2, red) * (1.0f / D_);
    float d0 = v0 - mu, d1 = v1 - mu, d2 = v2 - mu;
    float var = block_reduce_sum(d0 * d0 + d1 * d1 + d2 * d2, red) * (1.0f / D_);
    float inv = rsqrtf(var + LN_EPS);
    size_t base = (size_t)row * D_;
    y[base + threadIdx.x      ] = __float2half(d0 * inv * s[threadIdx.x      ] + b[threadIdx.x      ]);
    y[base + threadIdx.x + 256] = __float2half(d1 * inv * s[threadIdx.x + 256] + b[threadIdx.x + 256]);
    y[base + threadIdx.x + 512] = __float2half(d2 * inv * s[threadIdx.x + 512] + b[threadIdx.x + 512]);
}

// ---------------- pure fp16 warp-mma GEMM, BK=64, 3-stage cp.async ----------------
// C[M,N] = A16[M,K] @ W16[N,K]^T + bias
// EPI 0: plain fp16 out ; EPI 1: gelu -> fp16 ; EPI 2: +R -> fp32
template <int EPI>
__global__ __launch_bounds__(256, 2) void wmma_gemm(
    const __half* __restrict__ A,
    const __half* __restrict__ W,
    const float* __restrict__ bias, const float* __restrict__ R,
    float* __restrict__ C,
    __half* __restrict__ Ch,
    int Ndim, int Kdim) {
    extern __shared__ char smem[];
    const unsigned sbase = smem_u32(smem);
    const int tid = threadIdx.x;
    const int lane = tid & 31;
    const int wid = tid >> 5;
    const int warp_m = wid & 1;
    const int warp_n = wid >> 1;
    const int bm = blockIdx.y * BM;
    const int bn = blockIdx.x * BN;
    const int NK = Kdim / BK;

    auto issue_stage = [&](int st) {
        const unsigned sb = sbase + (unsigned)((st % NSTAGE) * STAGE_B);
        const int k0 = st * BK;
        #pragma unroll
        for (int i = 0; i < 4; i++) {
            int f = tid + i * 256;          // 0..1023
            int r = f >> 3, cc = f & 7;
            unsigned so = (unsigned)(r * (GRS * 2) + cc * 16);
            size_t ao = (size_t)(bm + r) * Kdim + k0 + 8 * cc;
            size_t bo = (size_t)(bn + r) * Kdim + k0 + 8 * cc;
            cp16(sb + so,          A + ao);
            cp16(sb + TILE_B + so, W + bo);
        }
        cp_commit();
    };

    const unsigned a_base = (unsigned)((warp_m * 64 + (lane & 15)) * (GRS * 2) + (lane >> 4) * 16);
    const unsigned b_row = (unsigned)(warp_n * 32 + (lane & 7) + ((lane >> 4) << 3));
    const unsigned b_base = (unsigned)(b_row * (GRS * 2) + (((lane >> 3) & 1) * 16));

    float acc[4][4][4];
    #pragma unroll
    for (int mt = 0; mt < 4; mt++)
        #pragma unroll
        for (int nt = 0; nt < 4; nt++)
            #pragma unroll
            for (int r = 0; r < 4; r++) acc[mt][nt][r] = 0.0f;

    issue_stage(0);
    if (NK > 1) issue_stage(1);

    for (int i = 0; i < NK; i++) {
        if (i + 1 < NK) cp_wait<1>(); else cp_wait<0>();
        __syncthreads();
        if (i + 2 < NK) issue_stage(i + 2);

        const unsigned tA = sbase + (unsigned)((i % NSTAGE) * STAGE_B);
        const unsigned tW = tA + TILE_B;

        #pragma unroll
        for (int ks = 0; ks < 4; ks++) {
            unsigned fbw[2][4];
            #pragma unroll
            for (int pr = 0; pr < 2; pr++) {
                unsigned bo = b_base + (unsigned)(pr * 16 * (GRS * 2) + ks * 32);
                ldsm_x4(fbw[pr], tW + bo);
            }
            #pragma unroll
            for (int mt = 0; mt < 4; mt++) {
                unsigned fa[4];
                unsigned ao = a_base + (unsigned)(mt * 16 * (GRS * 2) + ks * 32);
                ldsm_x4(fa, tA + ao);
                #pragma unroll
                for (int nt = 0; nt < 4; nt++)
                    mma_f16f32(acc[mt][nt], fa, &fbw[nt >> 1][(nt & 1) * 2]);
            }
        }
    }

    // ---- epilogue ----
    const int g = lane >> 2, tg = lane & 3;
    #pragma unroll
    for (int mt = 0; mt < 4; mt++) {
        #pragma unroll
        for (int nt = 0; nt < 4; nt++) {
            int row0 = bm + warp_m * 64 + mt * 16 + g;
            int col  = bn + warp_n * 32 + nt * 8 + tg * 2;
            float2 bv = *(const float2*)(bias + col);
            float c0 = acc[mt][nt][0] + bv.x;
            float c1 = acc[mt][nt][1] + bv.y;
            float c2 = acc[mt][nt][2] + bv.x;
            float c3 = acc[mt][nt][3] + bv.y;
            size_t o0 = (size_t)row0 * Ndim + col;
            size_t o1 = o0 + (size_t)8 * Ndim;
            if (EPI == 2) {
                float2 r0 = *(const float2*)(R + o0);
                float2 r1 = *(const float2*)(R + o1);
                c0 += r0.x; c1 += r0.y; c2 += r1.x; c3 += r1.y;
                *(float2*)(C + o0) = make_float2(c0, c1);
                *(float2*)(C + o1) = make_float2(c2, c3);
            } else {
                if (EPI == 1) {
                    c0 = gelu_tanh(c0); c1 = gelu_tanh(c1);
                    c2 = gelu_tanh(c2); c3 = gelu_tanh(c3);
                }
                *(unsigned*)(Ch + o0) = pack_h2(__float2half(c0), __float2half(c1));
                *(unsigned*)(Ch + o1) = pack_h2(__float2half(c2), __float2half(c3));
            }
        }
    }
}

// ---------------- fp16 flash attention (single fp16 throughout) ----------------
__global__ __launch_bounds__(128) void attn_mma(
    const __half* __restrict__ qkv_,
    __half* __restrict__ o_) {
    extern __shared__ char smem[];
    __half* sb = (__half*)smem;
    int* kcode = (int*)(smem + AT_CODE_B);
    const unsigned sbase = smem_u32(smem);
    const int h = blockIdx.y, b = blockIdx.z;
    const int q0 = blockIdx.x * 64;
    const int tid = threadIdx.x;
    const int lane = tid & 31;
    const int warp = tid >> 5;
    const int tg2 = (lane & 3) * 2;

    const int rlast = min(q0 + 63, T_ - 1);
    const int kmax = P_ + (tok_ts(rlast) + 1) * TPS;
    const int ntiles = (kmax + 63) / 64;

    // ---- load Q tile (single fp16) ----
    for (int idx = tid; idx < 64 * 8; idx += 128) {
        int r = idx >> 3, c = idx & 7;
        int gr = min(q0 + r, T_ - 1);
        size_t src = ((size_t)(b * T_ + gr)) * (3 * D_) + h * HD_ + c * 8;
        *(uint4*)&sb[r * ARS + c * 8] = *(const uint4*)(qkv_ + src);
    }

    auto issue_kv = [&](int it) {
        const int s = it & 1;
        const unsigned base = sbase + (unsigned)((1 + s * 2) * AT_TSZB);
        const int k0 = it * 64;
        #pragma unroll
        for (int i = 0; i < 4; i++) {
            int idx = tid + i * 128;
            int r = idx >> 3, c = idx & 7;
            int kr = min(k0 + r, T_ - 1);
            size_t src = ((size_t)(b * T_ + kr)) * (3 * D_) + D_ + h * HD_ + c * 8;
            unsigned o = (unsigned)(r * ARS * 2 + c * 16);
            cp16(base + o,           qkv_ + src);        // K
            cp16(base + AT_TSZB + o, qkv_ + src + D_);   // V
        }
        cp_commit();
        if (tid < 64) {
            int kg = k0 + tid;
            kcode[s * 64 + tid] = (kg < kmax)
                                ? ((tok_ts(kg) << 2) | tok_group(kg))
                                : ((0x3FFF << 2) | 3);
        }
    };

    issue_kv(0);
    __syncthreads();

    unsigned qf[4][4];
    {
        unsigned rowoff = (unsigned)((warp * 16 + (lane & 15)) * (ARS * 2)) + (lane >> 4) * 16;
        #pragma unroll
        for (int ks = 0; ks < 4; ks++)
            ldsm_x4(qf[ks], sbase + rowoff + ks * 32);
    }

    const int r0 = q0 + warp * 16 + (lane >> 2);
    const int r1 = r0 + 8;
    const int rc0 = min(r0, T_ - 1), rc1 = min(r1, T_ - 1);
    const int gq0 = tok_group(rc0), tq0 = tok_ts(rc0);
    const int gq1 = tok_group(rc1), tq1 = tok_ts(rc1);

    float m0 = -1e30f, m1 = -1e30f, l0 = 0.0f, l1 = 0.0f;
    float o[8][4];
    #pragma unroll
    for (int nt = 0; nt < 8; nt++)
        #pragma unroll
        for (int r = 0; r < 4; r++) o[nt][r] = 0.0f;

    const unsigned kb = (unsigned)(((lane & 7) + ((lane >> 4) << 3)) * (ARS * 2)) +
                        ((lane >> 3) & 1) * 16;

    for (int it = 0; it < ntiles; it++) {
        cp_wait<0>();
        __syncthreads();
        if (it + 1 < ntiles) issue_kv(it + 1);

        const int s = it & 1;
        const unsigned tK = sbase + (unsigned)((1 + s * 2) * AT_TSZB);
        const unsigned tV = tK + AT_TSZB;
        const int* kc = kcode + s * 64;

        float sc[8][4];
        #pragma unroll
        for (int nt = 0; nt < 8; nt++)
            #pragma unroll
            for (int r = 0; r < 4; r++) sc[nt][r] = 0.0f;

        #pragma unroll
        for (int kg = 0; kg < 4; kg++) {
            #pragma unroll
            for (int ks = 0; ks < 4; ks++) {
                unsigned kh[4];
                unsigned addr = kb + (unsigned)(kg * 16 * (ARS * 2)) + ks * 32;
                ldsm_x4(kh, tK + addr);
                #pragma unroll
                for (int half = 0; half < 2; half++)
                    mma_f16f32(sc[kg * 2 + half], qf[ks], &kh[half * 2]);
            }
        }

        #pragma unroll
        for (int nt = 0; nt < 8; nt++) {
            int kc0 = kc[nt * 8 + tg2];
            int kc1 = kc[nt * 8 + tg2 + 1];
            sc[nt][0] = allow_code(gq0, tq0, kc0) ? sc[nt][0] * ATT_SCALE : -1e30f;
            sc[nt][1] = allow_code(gq0, tq0, kc1) ? sc[nt][1] * ATT_SCALE : -1e30f;
            sc[nt][2] = allow_code(gq1, tq1, kc0) ? sc[nt][2] * ATT_SCALE : -1e30f;
            sc[nt][3] = allow_code(gq1, tq1, kc1) ? sc[nt][3] * ATT_SCALE : -1e30f;
        }

        float mx0 = -1e30f, mx1 = -1e30f;
        #pragma unroll
        for (int nt = 0; nt < 8; nt++) {
            mx0 = fmaxf(mx0, fmaxf(sc[nt][0], sc[nt][1]));
            mx1 = fmaxf(mx1, fmaxf(sc[nt][2], sc[nt][3]));
        }
        mx0 = fmaxf(mx0, __shfl_xor_sync(0xffffffffu, mx0, 1));
        mx0 = fmaxf(mx0, __shfl_xor_sync(0xffffffffu, mx0, 2));
        mx1 = fmaxf(mx1, __shfl_xor_sync(0xffffffffu, mx1, 1));
        mx1 = fmaxf(mx1, __shfl_xor_sync(0xffffffffu, mx1, 2));
        float mn0 = fmaxf(m0, mx0), mn1 = fmaxf(m1, mx1);
        float corr0 = __expf(m0 - mn0), corr1 = __expf(m1 - mn1);
        m0 = mn0; m1 = mn1;
        l0 *= corr0; l1 *= corr1;
        #pragma unroll
        for (int nt = 0; nt < 8; nt++) {
            o[nt][0] *= corr0; o[nt][1] *= corr0;
            o[nt][2] *= corr1; o[nt][3] *= corr1;
        }

        #pragma unroll
        for (int kv = 0; kv < 4; kv++) {
            unsigned ph[4];
            #pragma unroll
            for (int half = 0; half < 2; half++) {
                int nt = kv * 2 + half;
                float p0 = __expf(sc[nt][0] - m0);
                float p1 = __expf(sc[nt][1] - m0);
                float p2 = __expf(sc[nt][2] - m1);
                float p3 = __expf(sc[nt][3] - m1);
                l0 += p0 + p1;
                l1 += p2 + p3;
                ph[half * 2 + 0] = pack_h2(__float2half(p0), __float2half(p1));
                ph[half * 2 + 1] = pack_h2(__float2half(p2), __float2half(p3));
            }
            #pragma unroll
            for (int dg = 0; dg < 4; dg++) {
                unsigned vh[4];
                unsigned addr = kb + (unsigned)(kv * 16 * (ARS * 2)) + dg * 32;
                ldsm_x4t(vh, tV + addr);
                #pragma unroll
                for (int half = 0; half < 2; half++) {
                    int nt = dg * 2 + half;
                    unsigned bp[2] = {vh[half], vh[2 + half]};
                    mma_f16f32(o[nt], ph, bp);
                }
            }
        }
    }

    l0 += __shfl_xor_sync(0xffffffffu, l0, 1);
    l0 += __shfl_xor_sync(0xffffffffu, l0, 2);
    l1 += __shfl_xor_sync(0xffffffffu, l1, 1);
    l1 += __shfl_xor_sync(0xffffffffu, l1, 2);
    float li0 = 1.0f / l0, li1 = 1.0f / l1;

    #pragma unroll
    for (int nt = 0; nt < 8; nt++) {
        int d = h * HD_ + nt * 8 + tg2;
        if (r0 < T_) {
            size_t off = ((size_t)(b * T_ + r0)) * D_ + d;
            *(unsigned*)(o_ + off) = pack_h2(__float2half(o[nt][0] * li0),
                                             __float2half(o[nt][1] * li0));
        }
        if (r1 < T_) {
            size_t off = ((size_t)(b * T_ + r1)) * D_ + d;
            *(unsigned*)(o_ + off) = pack_h2(__float2half(o[nt][2] * li1),
                                             __float2half(o[nt][3] * li1));
        }
    }
}

// ---------------- host orchestration ----------------
extern "C" void kernel_launch(void* const* d_in, const int* in_sizes, int n_in,
                              void* d_out, int out_size) {
    (void)in_sizes; (void)n_in; (void)out_size;

    const float* prefix = (const float*)d_in[0];
    const float* obs    = (const float*)d_in[2];
    const float* rdo    = (const float*)d_in[4];
    const float* ln1_s  = (const float*)d_in[6];
    const float* ln1_b  = (const float*)d_in[7];
    const float* wqkv   = (const float*)d_in[8];
    const float* bqkv   = (const float*)d_in[9];
    const float* wo     = (const float*)d_in[10];
    const float* bo     = (const float*)d_in[11];
    const float* ln2_s  = (const float*)d_in[12];
    const float* ln2_b  = (const float*)d_in[13];
    const float* w1     = (const float*)d_in[14];
    const float* b1     = (const float*)d_in[15];
    const float* w2     = (const float*)d_in[16];
    const float* b2     = (const float*)d_in[17];
    const float* lnf_s  = (const float*)d_in[18];
    const float* lnf_b  = (const float*)d_in[19];
    float* out = (float*)d_out;

    float* x;
    __half *y, *att, *ffn, *qkv;
    __half *wqkvT, *woT, *w1T, *w2T;
    cudaGetSymbolAddress((void**)&x,    g_x);
    cudaGetSymbolAddress((void**)&y,    g_y);
    cudaGetSymbolAddress((void**)&att,  g_att);
    cudaGetSymbolAddress((void**)&ffn,  g_ffn);
    cudaGetSymbolAddress((void**)&qkv,  g_qkv);
    cudaGetSymbolAddress((void**)&wqkvT, g_wqkvT);
    cudaGetSymbolAddress((void**)&woT,   g_woT);
    cudaGetSymbolAddress((void**)&w1T,   g_w1T);
    cudaGetSymbolAddress((void**)&w2T,   g_w2T);

    cudaFuncSetAttribute(wmma_gemm<0>, cudaFuncAttributeMaxDynamicSharedMemorySize, SMEM_GEMM);
    cudaFuncSetAttribute(wmma_gemm<1>, cudaFuncAttributeMaxDynamicSharedMemorySize, SMEM_GEMM);
    cudaFuncSetAttribute(wmma_gemm<2>, cudaFuncAttributeMaxDynamicSharedMemorySize, SMEM_GEMM);
    cudaFuncSetAttribute(attn_mma, cudaFuncAttributeMaxDynamicSharedMemorySize, ATTN_SMEM);

    assemble_kernel<<<2048, 256>>>(prefix, obs, rdo);

    wconv_all_kernel<<<dim3(6912, L_), dim3(32, 8)>>>(
        wqkv, wo, w1, w2, wqkvT, woT, w1T, w2T);

    const dim3 g_qkv_grid(3 * D_ / BN, M_ / BM);   // (18, 86)
    const dim3 g_wo_grid (D_ / BN,     M_ / BM);   // (6, 86)
    const dim3 g_w1_grid (F_ / BN,     M_ / BM);   // (24, 86)
    const dim3 g_attn((T_ + 63) / 64, NH_, B_);    // (22, 12, 8)

    for (int l = 0; l < L_; l++) {
        ln_h_kernel<<<M_, 256>>>(x, ln1_s + (size_t)l * D_, ln1_b + (size_t)l * D_, y);
        wmma_gemm<0><<<g_qkv_grid, 256, SMEM_GEMM>>>(
            y, wqkvT + (size_t)l * 3 * D_ * D_,
            bqkv + (size_t)l * 3 * D_, nullptr, nullptr,
            qkv, 3 * D_, D_);
        attn_mma<<<g_attn, 128, ATTN_SMEM>>>(qkv, att);
        wmma_gemm<2><<<g_wo_grid, 256, SMEM_GEMM>>>(
            att, woT + (size_t)l * D_ * D_,
            bo + (size_t)l * D_, x, x,
            nullptr, D_, D_);
        ln_h_kernel<<<M_, 256>>>(x, ln2_s + (size_t)l * D_, ln2_b + (size_t)l * D_, y);
        wmma_gemm<1><<<g_w1_grid, 256, SMEM_GEMM>>>(
            y, w1T + (size_t)l * F_ * D_,
            b1 + (size_t)l * F_, nullptr, nullptr,
            ffn, F_, D_);
        wmma_gemm<2><<<g_wo_grid, 256, SMEM_GEMM>>>(
            ffn, w2T + (size_t)l * D_ * F_,
            b2 + (size_t)l * D_, x, x,
            nullptr, D_, F_);
    }

    ln_kernel<<<M_, 256>>>(x, lnf_s, lnf_b, out);
}